// round 8
// baseline (speedup 1.0000x reference)
#include <cuda_runtime.h>
#include <cstdint>

// ----------------------------------------------------------------------------
// Problem constants (fixed shapes)
// ----------------------------------------------------------------------------
constexpr int BB   = 8;
constexpr int LL   = 1024;
constexpr int DM   = 768;
constexpr int DI   = 1536;
constexpr int NS   = 64;
constexpr int DTR  = 48;
constexpr int MTOT = BB * LL;        // 8192
constexpr int XZC  = 2 * DI;         // 3072
constexpr int PROJC = DTR + 2 * NS;  // 176

// ----------------------------------------------------------------------------
// Scratch (device globals; no allocation allowed)
// ----------------------------------------------------------------------------
__device__ float g_xzT [MTOT * XZC];   // (3072, m) in-proj output, d-major
__device__ float g_uT  [MTOT * DI];    // (d, m) conv+silu, full precision
__device__ float g_uTr [MTOT * DI];    // (d, m) conv+silu, tf32-rounded
__device__ float g_proj[MTOT * PROJC]; // (m, 176) [dt_r(tf32) | B | C]
__device__ float g_dtT [MTOT * DI];    // (d, m) softplus dt, full
__device__ float g_yT  [MTOT * DI];    // (d, m) scan out, tf32-rounded
__device__ float g_mid [MTOT * DM];    // inter-layer act (tf32-rounded)
__device__ float g_xr  [MTOT * DM];    // layer-0 input, tf32-rounded

constexpr int WIN_SZ  = 2 * XZC * DM;
constexpr int WX_SZ   = 2 * PROJC * DI;
constexpr int WDT_SZ  = 2 * DI * DTR;
constexpr int WOUT_SZ = 2 * DM * DI;
__device__ float g_win [WIN_SZ];
__device__ float g_wx  [WX_SZ];
__device__ float g_wdt [WDT_SZ];
__device__ float g_wout[WOUT_SZ];

// ----------------------------------------------------------------------------
// Helpers
// ----------------------------------------------------------------------------
__device__ __forceinline__ float siluf(float x) {
    return x * (1.0f / (1.0f + __expf(-x)));
}
__device__ __forceinline__ float softplusf(float x) {
    return fmaxf(x, 0.0f) + log1pf(__expf(-fabsf(x)));
}
__device__ __forceinline__ float tf32r(float x) {
    uint32_t r;
    asm("cvt.rna.tf32.f32 %0, %1;" : "=r"(r) : "f"(x));
    return __uint_as_float(r);
}
__device__ __forceinline__ float ex2f(float x) {   // MUFU EX2
    float r;
    asm("ex2.approx.f32 %0, %1;" : "=f"(r) : "f"(x));
    return r;
}
__device__ __forceinline__ void mma_tf32(float* d, const uint32_t* a,
                                         const uint32_t* b) {
    asm volatile(
        "mma.sync.aligned.m16n8k8.row.col.f32.tf32.tf32.f32 "
        "{%0,%1,%2,%3}, {%4,%5,%6,%7}, {%8,%9}, {%0,%1,%2,%3};\n"
        : "+f"(d[0]), "+f"(d[1]), "+f"(d[2]), "+f"(d[3])
        : "r"(a[0]), "r"(a[1]), "r"(a[2]), "r"(a[3]), "r"(b[0]), "r"(b[1]));
}
__device__ __forceinline__ void cpa16(float* smem, const float* g) {
    uint32_t dst = (uint32_t)__cvta_generic_to_shared(smem);
    asm volatile("cp.async.ca.shared.global [%0], [%1], 16;\n"
                 :: "r"(dst), "l"(g));
}
__device__ __forceinline__ void cpa16z(float* smem, const float* g, int sz) {
    uint32_t dst = (uint32_t)__cvta_generic_to_shared(smem);
    asm volatile("cp.async.ca.shared.global [%0], [%1], 16, %2;\n"
                 :: "r"(dst), "l"(g), "r"(sz));
}

// ----------------------------------------------------------------------------
// tf32 rounding prep kernel (float4; n % 4 == 0)
// ----------------------------------------------------------------------------
__global__ void round_tf32_kernel(const float* __restrict__ in,
                                  float* __restrict__ out, int n)
{
    int i = (blockIdx.x * blockDim.x + threadIdx.x) * 4;
    if (i < n) {
        float4 v = *reinterpret_cast<const float4*>(in + i);
        v.x = tf32r(v.x); v.y = tf32r(v.y);
        v.z = tf32r(v.z); v.w = tf32r(v.w);
        *reinterpret_cast<float4*>(out + i) = v;
    }
}

// ============================================================================
// Tensor-core tf32 GEMM, cp.async 2-stage pipeline. Inputs PRE-ROUNDED tf32.
//   C[m,n] = sum_k A[m,k] * W[n,k]  (W row-major N x K)
//   ATRANS: A stored K x MTOT (d-major);  else A m-major with lda.
//   CTRANS: C stored N x MTOT (n-major) via smem-staged transpose (aliases As)
//   MODE: 0 none | 1 softplus(+bias) | 2 round-all | 3 round cols < DTR
// Block 128x128x16, 256 thr, warp grid 2x4 (warp tile 64x32), mma m16n8k8.
// ============================================================================
constexpr int TBM = 128, TBN = 128, TBK = 16;
constexpr int SKM = 136;      // [k][m] stride
constexpr int SMK = 20;       // [m][k]/[n][k] stride
constexpr int ASTG = 2560;    // max(16*136, 128*20)
constexpr int BSTG = 2560;
constexpr int TSP  = 136;     // transpose staging stride (16B aligned)

template<bool ATRANS, bool CTRANS, int MODE>
__global__ void __launch_bounds__(256, 2) tgemm_kernel(
    const float* __restrict__ A, int lda,
    const float* __restrict__ W,
    const float* __restrict__ bias,
    float* __restrict__ C, int ldc,
    int N, int K)
{
    __shared__ float As[2][ASTG];
    __shared__ float Bs[2][BSTG];

    const int tid  = threadIdx.x;
    const int bm   = blockIdx.y * TBM;
    const int bn   = blockIdx.x * TBN;
    const int wid  = tid >> 5;
    const int lane = tid & 31;
    const int wm   = (wid & 1) * 64;
    const int wn   = (wid >> 1) * 32;
    const int gid  = lane >> 2;
    const int tig  = lane & 3;

    float acc[4][4][4];
    #pragma unroll
    for (int i = 0; i < 4; i++)
        #pragma unroll
        for (int j = 0; j < 4; j++)
            #pragma unroll
            for (int c = 0; c < 4; c++) acc[i][j][c] = 0.0f;

    auto issue_load = [&](int k0, int st) {
        #pragma unroll
        for (int itr = 0; itr < 2; itr++) {
            int s = tid + itr * 256;
            if (ATRANS) {
                int kk = s >> 5, mc = (s & 31) * 4;
                cpa16(&As[st][kk * SKM + mc],
                      A + (size_t)(k0 + kk) * MTOT + bm + mc);
            } else {
                int row = s >> 2, kc = (s & 3) * 4;
                cpa16(&As[st][row * SMK + kc],
                      A + (size_t)(bm + row) * lda + k0 + kc);
            }
            int n = s >> 2, kc = (s & 3) * 4;
            cpa16z(&Bs[st][n * SMK + kc],
                   W + (size_t)(bn + n) * K + k0 + kc,
                   (bn + n < N) ? 16 : 0);
        }
        asm volatile("cp.async.commit_group;\n");
    };

    issue_load(0, 0);

    const int kt = K / TBK;
    int st = 0;
    for (int it = 0; it < kt; it++) {
        asm volatile("cp.async.wait_group 0;\n");
        __syncthreads();
        if (it + 1 < kt) issue_load((it + 1) * TBK, st ^ 1);

        #pragma unroll
        for (int ks = 0; ks < 2; ks++) {
            const int kb = ks * 8;
            uint32_t afr[4][4], bfr[4][2];
            #pragma unroll
            for (int mi = 0; mi < 4; mi++) {
                int r = wm + mi * 16 + gid;
                if (ATRANS) {
                    afr[mi][0] = __float_as_uint(As[st][(kb + tig) * SKM + r]);
                    afr[mi][1] = __float_as_uint(As[st][(kb + tig) * SKM + r + 8]);
                    afr[mi][2] = __float_as_uint(As[st][(kb + tig + 4) * SKM + r]);
                    afr[mi][3] = __float_as_uint(As[st][(kb + tig + 4) * SKM + r + 8]);
                } else {
                    afr[mi][0] = __float_as_uint(As[st][r * SMK + kb + tig]);
                    afr[mi][1] = __float_as_uint(As[st][(r + 8) * SMK + kb + tig]);
                    afr[mi][2] = __float_as_uint(As[st][r * SMK + kb + tig + 4]);
                    afr[mi][3] = __float_as_uint(As[st][(r + 8) * SMK + kb + tig + 4]);
                }
            }
            #pragma unroll
            for (int ni = 0; ni < 4; ni++) {
                int c = wn + ni * 8 + gid;
                bfr[ni][0] = __float_as_uint(Bs[st][c * SMK + kb + tig]);
                bfr[ni][1] = __float_as_uint(Bs[st][c * SMK + kb + tig + 4]);
            }
            #pragma unroll
            for (int mi = 0; mi < 4; mi++)
                #pragma unroll
                for (int ni = 0; ni < 4; ni++)
                    mma_tf32(acc[mi][ni], afr[mi], bfr[ni]);
        }
        st ^= 1;
    }

    if constexpr (CTRANS) {
        // n-major output: stage 32 n-cols per phase in smem (aliases As:
        // need 32*136 = 4352 floats <= 5120).
        float (*Ts)[TSP] = reinterpret_cast<float (*)[TSP]>(&As[0][0]);
        #pragma unroll
        for (int p = 0; p < 4; p++) {
            __syncthreads();
            if ((wid >> 1) == p) {
                #pragma unroll
                for (int mi = 0; mi < 4; mi++)
                    #pragma unroll
                    for (int ni = 0; ni < 4; ni++)
                        #pragma unroll
                        for (int c = 0; c < 4; c++) {
                            int rr = wm + mi * 16 + gid + ((c >= 2) ? 8 : 0);
                            int cc = ni * 8 + tig * 2 + (c & 1);
                            float v = acc[mi][ni][c];
                            if (MODE == 1)
                                v = softplusf(v + bias[bn + p * 32 + cc]);
                            Ts[cc][rr] = v;
                        }
            }
            __syncthreads();
            int nn = tid >> 3;
            int mm = (tid & 7) * 16;
            int grow = bn + p * 32 + nn;
            if (grow < N) {
                size_t base = (size_t)grow * MTOT + bm + mm;
                #pragma unroll
                for (int q = 0; q < 4; q++)
                    *reinterpret_cast<float4*>(&C[base + q * 4]) =
                        *reinterpret_cast<const float4*>(&Ts[nn][mm + q * 4]);
            }
        }
    } else {
        // m-major epilogue (N even, c even => c+1 < N)
        #pragma unroll
        for (int mi = 0; mi < 4; mi++) {
            int r = bm + wm + mi * 16 + gid;
            #pragma unroll
            for (int ni = 0; ni < 4; ni++) {
                int c = bn + wn + ni * 8 + tig * 2;
                if (c < N) {
                    float d0 = acc[mi][ni][0], d1 = acc[mi][ni][1];
                    float d2 = acc[mi][ni][2], d3 = acc[mi][ni][3];
                    if (MODE == 1) {
                        float b0 = bias[c], b1 = bias[c + 1];
                        d0 = softplusf(d0 + b0); d1 = softplusf(d1 + b1);
                        d2 = softplusf(d2 + b0); d3 = softplusf(d3 + b1);
                    }
                    if (MODE == 2) {
                        d0 = tf32r(d0); d1 = tf32r(d1);
                        d2 = tf32r(d2); d3 = tf32r(d3);
                    }
                    if (MODE == 3 && c < DTR) {
                        d0 = tf32r(d0); d1 = tf32r(d1);
                        d2 = tf32r(d2); d3 = tf32r(d3);
                    }
                    C[(size_t)r * ldc + c]           = d0;
                    C[(size_t)r * ldc + c + 1]       = d1;
                    C[(size_t)(r + 8) * ldc + c]     = d2;
                    C[(size_t)(r + 8) * ldc + c + 1] = d3;
                }
            }
        }
    }
}

// ----------------------------------------------------------------------------
// Causal depthwise conv (k=4) + SiLU. Writes full (uT) + tf32-rounded (uTr).
// ----------------------------------------------------------------------------
__global__ void conv_silu_kernel(const float* __restrict__ xzT,
                                 const float* __restrict__ cw,
                                 const float* __restrict__ cb,
                                 float* __restrict__ uT,
                                 float* __restrict__ uTr)
{
    int i = blockIdx.x * blockDim.x + threadIdx.x;
    int d = i >> 13;
    int m = i & 8191;
    int t = m & 1023;
    const float* src = xzT + (size_t)d * MTOT + m;
    float w0 = cw[d * 4 + 0], w1 = cw[d * 4 + 1];
    float w2 = cw[d * 4 + 2], w3 = cw[d * 4 + 3];
    float acc = cb[d];
    if (t >= 3) acc = fmaf(src[-3], w0, acc);
    if (t >= 2) acc = fmaf(src[-2], w1, acc);
    if (t >= 1) acc = fmaf(src[-1], w2, acc);
    acc = fmaf(src[0], w3, acc);
    float s = siluf(acc);
    uT [(size_t)d * MTOT + m] = s;
    uTr[(size_t)d * MTOT + m] = tf32r(s);
}

// ----------------------------------------------------------------------------
// Selective scan. Block = 256 thr (8 warps) = 16 channels of ONE batch.
// B/C staged in smem per 32-t chunk (shared by all 8 warps -> 8x less L2).
// Warp: 2 channels, lane owns states (l, l+32). Fused skip + gate.
// ----------------------------------------------------------------------------
__global__ void __launch_bounds__(256) ssm_scan_kernel(
    const float* __restrict__ proj,
    const float* __restrict__ dtT,
    const float* __restrict__ uT,
    const float* __restrict__ xzT,
    const float* __restrict__ A_log,
    const float* __restrict__ Dparam,
    float* __restrict__ yT)
{
    __shared__ float sBC[32][128];     // [j][0:64)=B, [64:128)=C ; 16 KB
    const unsigned FULL = 0xFFFFFFFFu;
    const float L2E = 1.4426950408889634f;
    const int tid  = threadIdx.x;
    const int wid  = tid >> 5;
    const int lane = tid & 31;
    const int b  = blockIdx.y;
    const int d0 = blockIdx.x * 16 + wid * 2;
    const int d1 = d0 + 1;

    float A00 = -__expf(A_log[(size_t)d0 * NS + lane])      * L2E;
    float A01 = -__expf(A_log[(size_t)d0 * NS + lane + 32]) * L2E;
    float A10 = -__expf(A_log[(size_t)d1 * NS + lane])      * L2E;
    float A11 = -__expf(A_log[(size_t)d1 * NS + lane + 32]) * L2E;
    float D0 = Dparam[d0], D1 = Dparam[d1];

    float h00 = 0.f, h01 = 0.f, h10 = 0.f, h11 = 0.f;

    for (int tc = 0; tc < LL; tc += 32) {
        const size_t mb = (size_t)b * LL + tc;

        __syncthreads();   // previous chunk's sBC fully consumed
        #pragma unroll
        for (int it = 0; it < 4; it++) {
            int s   = tid + it * 256;
            int row = s >> 5;
            int c4  = (s & 31) * 4;
            cpa16(&sBC[row][c4], proj + (mb + row) * PROJC + 48 + c4);
        }
        asm volatile("cp.async.commit_group;\n");

        float dtv0 = dtT[(size_t)d0 * MTOT + mb + lane];
        float dtv1 = dtT[(size_t)d1 * MTOT + mb + lane];
        float uv0  = uT [(size_t)d0 * MTOT + mb + lane];
        float uv1  = uT [(size_t)d1 * MTOT + mb + lane];
        float zv0  = xzT[(size_t)(DI + d0) * MTOT + mb + lane];
        float zv1  = xzT[(size_t)(DI + d1) * MTOT + mb + lane];
        float duv0 = dtv0 * uv0;
        float duv1 = dtv1 * uv1;

        asm volatile("cp.async.wait_group 0;\n");
        __syncthreads();

        float y0keep = 0.f, y1keep = 0.f;
        #pragma unroll 8
        for (int j = 0; j < 32; j++) {
            float Bn0 = sBC[j][lane];
            float Bn1 = sBC[j][lane + 32];
            float Cn0 = sBC[j][64 + lane];
            float Cn1 = sBC[j][96 + lane];
            float dt0 = __shfl_sync(FULL, dtv0, j);
            float dt1 = __shfl_sync(FULL, dtv1, j);
            float du0 = __shfl_sync(FULL, duv0, j);
            float du1 = __shfl_sync(FULL, duv1, j);
            h00 = fmaf(ex2f(dt0 * A00), h00, du0 * Bn0);
            h01 = fmaf(ex2f(dt0 * A01), h01, du0 * Bn1);
            h10 = fmaf(ex2f(dt1 * A10), h10, du1 * Bn0);
            h11 = fmaf(ex2f(dt1 * A11), h11, du1 * Bn1);
            float y0 = fmaf(h00, Cn0, h01 * Cn1);
            float y1 = fmaf(h10, Cn0, h11 * Cn1);
            #pragma unroll
            for (int off = 16; off; off >>= 1) {
                y0 += __shfl_xor_sync(FULL, y0, off);
                y1 += __shfl_xor_sync(FULL, y1, off);
            }
            if (lane == j) { y0keep = y0; y1keep = y1; }
        }
        float out0 = (y0keep + uv0 * D0) * siluf(zv0);
        float out1 = (y1keep + uv1 * D1) * siluf(zv1);
        yT[(size_t)d0 * MTOT + mb + lane] = tf32r(out0);
        yT[(size_t)d1 * MTOT + mb + lane] = tf32r(out1);
    }
}

// ----------------------------------------------------------------------------
// kernel_launch
// ----------------------------------------------------------------------------
extern "C" void kernel_launch(void* const* d_in, const int* in_sizes, int n_in,
                              void* d_out, int out_size)
{
    const float* x     = (const float*)d_in[0];
    const float* W_in  = (const float*)d_in[1];
    const float* cw    = (const float*)d_in[2];
    const float* cb    = (const float*)d_in[3];
    const float* W_x   = (const float*)d_in[4];
    const float* W_dt  = (const float*)d_in[5];
    const float* b_dt  = (const float*)d_in[6];
    const float* A_log = (const float*)d_in[7];
    const float* Dp    = (const float*)d_in[8];
    const float* W_out = (const float*)d_in[9];

    float *xzT, *uT, *uTr, *proj, *dtT, *yT, *mid, *xr;
    float *win, *wx, *wdt, *wout;
    cudaGetSymbolAddress((void**)&xzT,  g_xzT);
    cudaGetSymbolAddress((void**)&uT,   g_uT);
    cudaGetSymbolAddress((void**)&uTr,  g_uTr);
    cudaGetSymbolAddress((void**)&proj, g_proj);
    cudaGetSymbolAddress((void**)&dtT,  g_dtT);
    cudaGetSymbolAddress((void**)&yT,   g_yT);
    cudaGetSymbolAddress((void**)&mid,  g_mid);
    cudaGetSymbolAddress((void**)&xr,   g_xr);
    cudaGetSymbolAddress((void**)&win,  g_win);
    cudaGetSymbolAddress((void**)&wx,   g_wx);
    cudaGetSymbolAddress((void**)&wdt,  g_wdt);
    cudaGetSymbolAddress((void**)&wout, g_wout);

    const dim3 tb256(256);
    const int MB = MTOT / TBM;   // 64

    // ---- tf32 pre-rounding (weights + layer-0 input) ----
    auto rgrid = [](int n) { return (n / 4 + 255) / 256; };
    round_tf32_kernel<<<rgrid(MTOT * DM), tb256>>>(x,     xr,   MTOT * DM);
    round_tf32_kernel<<<rgrid(WIN_SZ),    tb256>>>(W_in,  win,  WIN_SZ);
    round_tf32_kernel<<<rgrid(WX_SZ),     tb256>>>(W_x,   wx,   WX_SZ);
    round_tf32_kernel<<<rgrid(WDT_SZ),    tb256>>>(W_dt,  wdt,  WDT_SZ);
    round_tf32_kernel<<<rgrid(WOUT_SZ),   tb256>>>(W_out, wout, WOUT_SZ);

    for (int l = 0; l < 2; l++) {
        const float* xin = (l == 0) ? xr : mid;   // both tf32-rounded
        float* xout = (l == 1) ? (float*)d_out : mid;

        // 1. in-proj, n-major output straight into xzT (no transpose kernel)
        tgemm_kernel<false, true, 0>
            <<<dim3(XZC / TBN, MB), tb256>>>(
                xin, DM, win + (size_t)l * XZC * DM, nullptr,
                xzT, 0, XZC, DM);

        // 2. conv + silu -> uT (full) + uTr (rounded)
        conv_silu_kernel<<<(DI * MTOT) / 256, tb256>>>(
            xzT, cw + (size_t)l * DI * 4, cb + (size_t)l * DI, uT, uTr);

        // 3. x-proj: proj[m,176] = u @ W_x^T ; rounds dt_r cols (<48) only
        tgemm_kernel<true, false, 3>
            <<<dim3((PROJC + TBN - 1) / TBN, MB), tb256>>>(
                uTr, 0, wx + (size_t)l * PROJC * DI, nullptr,
                proj, PROJC, PROJC, DI);

        // 4. dt: n-major + fused softplus straight into dtT (no transpose)
        tgemm_kernel<false, true, 1>
            <<<dim3(DI / TBN, MB), tb256>>>(
                proj, PROJC, wdt + (size_t)l * DI * DTR,
                b_dt + (size_t)l * DI, dtT, 0, DI, DTR);

        // 5. selective scan + skip + gate -> yT (rounded for out-proj)
        ssm_scan_kernel<<<dim3(DI / 16, BB), tb256>>>(
            proj, dtT, uT, xzT,
            A_log + (size_t)l * DI * NS, Dp + (size_t)l * DI, yT);

        // 6. out-proj: xout = y @ W_out^T ; l=0 rounds (feeds next in-proj)
        if (l == 0)
            tgemm_kernel<true, false, 2>
                <<<dim3(DM / TBN, MB), tb256>>>(
                    yT, 0, wout + (size_t)l * DM * DI, nullptr,
                    xout, DM, DM, DI);
        else
            tgemm_kernel<true, false, 0>
                <<<dim3(DM / TBN, MB), tb256>>>(
                    yT, 0, wout + (size_t)l * DM * DI, nullptr,
                    xout, DM, DM, DI);
    }
}

// round 9
// speedup vs baseline: 1.0564x; 1.0564x over previous
#include <cuda_runtime.h>
#include <cstdint>

// ----------------------------------------------------------------------------
// Problem constants (fixed shapes)
// ----------------------------------------------------------------------------
constexpr int BB   = 8;
constexpr int LL   = 1024;
constexpr int DM   = 768;
constexpr int DI   = 1536;
constexpr int NS   = 64;
constexpr int DTR  = 48;
constexpr int MTOT = BB * LL;        // 8192
constexpr int XZC  = 2 * DI;         // 3072
constexpr int PROJC = DTR + 2 * NS;  // 176

// ----------------------------------------------------------------------------
// Scratch (device globals; no allocation allowed)
// ----------------------------------------------------------------------------
__device__ float g_xzT [MTOT * XZC];   // (3072, m) in-proj output, d-major
__device__ float g_uT  [MTOT * DI];    // (d, m) conv+silu, full precision
__device__ float g_uTr [MTOT * DI];    // (d, m) conv+silu, tf32-rounded
__device__ float g_proj[MTOT * PROJC]; // (m, 176) [dt_r(tf32) | B | C]
__device__ float g_dtm [MTOT * DI];    // (m, d) softplus dt (m-major)
__device__ float g_dtT [MTOT * DI];    // (d, m) softplus dt
__device__ float g_yT  [MTOT * DI];    // (d, m) scan out, tf32-rounded
__device__ float g_mid [MTOT * DM];    // inter-layer act (tf32-rounded)
__device__ float g_xr  [MTOT * DM];    // layer-0 input, tf32-rounded

constexpr int WIN_SZ  = 2 * XZC * DM;
constexpr int WX_SZ   = 2 * PROJC * DI;
constexpr int WDT_SZ  = 2 * DI * DTR;
constexpr int WOUT_SZ = 2 * DM * DI;
__device__ float g_win [WIN_SZ];
__device__ float g_wx  [WX_SZ];
__device__ float g_wdt [WDT_SZ];
__device__ float g_wout[WOUT_SZ];

// ----------------------------------------------------------------------------
// Helpers
// ----------------------------------------------------------------------------
__device__ __forceinline__ float siluf(float x) {
    return x * (1.0f / (1.0f + __expf(-x)));
}
__device__ __forceinline__ float softplusf(float x) {
    return fmaxf(x, 0.0f) + log1pf(__expf(-fabsf(x)));
}
__device__ __forceinline__ float tf32r(float x) {
    uint32_t r;
    asm("cvt.rna.tf32.f32 %0, %1;" : "=r"(r) : "f"(x));
    return __uint_as_float(r);
}
__device__ __forceinline__ float ex2f(float x) {   // MUFU EX2
    float r;
    asm("ex2.approx.f32 %0, %1;" : "=f"(r) : "f"(x));
    return r;
}
__device__ __forceinline__ void mma_tf32(float* d, const uint32_t* a,
                                         const uint32_t* b) {
    asm volatile(
        "mma.sync.aligned.m16n8k8.row.col.f32.tf32.tf32.f32 "
        "{%0,%1,%2,%3}, {%4,%5,%6,%7}, {%8,%9}, {%0,%1,%2,%3};\n"
        : "+f"(d[0]), "+f"(d[1]), "+f"(d[2]), "+f"(d[3])
        : "r"(a[0]), "r"(a[1]), "r"(a[2]), "r"(a[3]), "r"(b[0]), "r"(b[1]));
}
__device__ __forceinline__ void cpa16(float* smem, const float* g) {
    uint32_t dst = (uint32_t)__cvta_generic_to_shared(smem);
    asm volatile("cp.async.ca.shared.global [%0], [%1], 16;\n"
                 :: "r"(dst), "l"(g));
}
__device__ __forceinline__ void cpa16z(float* smem, const float* g, int sz) {
    uint32_t dst = (uint32_t)__cvta_generic_to_shared(smem);
    asm volatile("cp.async.ca.shared.global [%0], [%1], 16, %2;\n"
                 :: "r"(dst), "l"(g), "r"(sz));
}

// ----------------------------------------------------------------------------
// tf32 rounding prep kernel (float4; n % 4 == 0)
// ----------------------------------------------------------------------------
__global__ void round_tf32_kernel(const float* __restrict__ in,
                                  float* __restrict__ out, int n)
{
    int i = (blockIdx.x * blockDim.x + threadIdx.x) * 4;
    if (i < n) {
        float4 v = *reinterpret_cast<const float4*>(in + i);
        v.x = tf32r(v.x); v.y = tf32r(v.y);
        v.z = tf32r(v.z); v.w = tf32r(v.w);
        *reinterpret_cast<float4*>(out + i) = v;
    }
}

// ============================================================================
// Tensor-core tf32 GEMM, cp.async 2-stage pipeline. Inputs PRE-ROUNDED tf32.
//   C[m,n] = sum_k A[m,k] * W[n,k]  (W row-major N x K)
//   ATRANS: A stored K x MTOT (d-major);  else A m-major with lda.
//   CTRANS: C stored N x MTOT (n-major) via smem-staged transpose (aliases As)
//   MODE: 0 none | 1 softplus(+bias) | 2 round-all | 3 round cols < DTR
// Block 128x128x16, 256 thr, warp grid 2x4 (warp tile 64x32), mma m16n8k8.
// ============================================================================
constexpr int TBM = 128, TBN = 128, TBK = 16;
constexpr int SKM = 136;      // [k][m] stride
constexpr int SMK = 20;       // [m][k]/[n][k] stride
constexpr int ASTG = 2560;    // max(16*136, 128*20)
constexpr int BSTG = 2560;
constexpr int TSP  = 136;     // transpose staging stride

template<bool ATRANS, bool CTRANS, int MODE>
__global__ void __launch_bounds__(256, 2) tgemm_kernel(
    const float* __restrict__ A, int lda,
    const float* __restrict__ W,
    const float* __restrict__ bias,
    float* __restrict__ C, int ldc,
    int N, int K)
{
    __shared__ float As[2][ASTG];
    __shared__ float Bs[2][BSTG];

    const int tid  = threadIdx.x;
    const int bm   = blockIdx.y * TBM;
    const int bn   = blockIdx.x * TBN;
    const int wid  = tid >> 5;
    const int lane = tid & 31;
    const int wm   = (wid & 1) * 64;
    const int wn   = (wid >> 1) * 32;
    const int gid  = lane >> 2;
    const int tig  = lane & 3;

    float acc[4][4][4];
    #pragma unroll
    for (int i = 0; i < 4; i++)
        #pragma unroll
        for (int j = 0; j < 4; j++)
            #pragma unroll
            for (int c = 0; c < 4; c++) acc[i][j][c] = 0.0f;

    auto issue_load = [&](int k0, int st) {
        #pragma unroll
        for (int itr = 0; itr < 2; itr++) {
            int s = tid + itr * 256;
            if (ATRANS) {
                int kk = s >> 5, mc = (s & 31) * 4;
                cpa16(&As[st][kk * SKM + mc],
                      A + (size_t)(k0 + kk) * MTOT + bm + mc);
            } else {
                int row = s >> 2, kc = (s & 3) * 4;
                cpa16(&As[st][row * SMK + kc],
                      A + (size_t)(bm + row) * lda + k0 + kc);
            }
            int n = s >> 2, kc = (s & 3) * 4;
            cpa16z(&Bs[st][n * SMK + kc],
                   W + (size_t)(bn + n) * K + k0 + kc,
                   (bn + n < N) ? 16 : 0);
        }
        asm volatile("cp.async.commit_group;\n");
    };

    issue_load(0, 0);

    const int kt = K / TBK;
    int st = 0;
    for (int it = 0; it < kt; it++) {
        asm volatile("cp.async.wait_group 0;\n");
        __syncthreads();
        if (it + 1 < kt) issue_load((it + 1) * TBK, st ^ 1);

        #pragma unroll
        for (int ks = 0; ks < 2; ks++) {
            const int kb = ks * 8;
            uint32_t afr[4][4], bfr[4][2];
            #pragma unroll
            for (int mi = 0; mi < 4; mi++) {
                int r = wm + mi * 16 + gid;
                if (ATRANS) {
                    afr[mi][0] = __float_as_uint(As[st][(kb + tig) * SKM + r]);
                    afr[mi][1] = __float_as_uint(As[st][(kb + tig) * SKM + r + 8]);
                    afr[mi][2] = __float_as_uint(As[st][(kb + tig + 4) * SKM + r]);
                    afr[mi][3] = __float_as_uint(As[st][(kb + tig + 4) * SKM + r + 8]);
                } else {
                    afr[mi][0] = __float_as_uint(As[st][r * SMK + kb + tig]);
                    afr[mi][1] = __float_as_uint(As[st][(r + 8) * SMK + kb + tig]);
                    afr[mi][2] = __float_as_uint(As[st][r * SMK + kb + tig + 4]);
                    afr[mi][3] = __float_as_uint(As[st][(r + 8) * SMK + kb + tig + 4]);
                }
            }
            #pragma unroll
            for (int ni = 0; ni < 4; ni++) {
                int c = wn + ni * 8 + gid;
                bfr[ni][0] = __float_as_uint(Bs[st][c * SMK + kb + tig]);
                bfr[ni][1] = __float_as_uint(Bs[st][c * SMK + kb + tig + 4]);
            }
            #pragma unroll
            for (int mi = 0; mi < 4; mi++)
                #pragma unroll
                for (int ni = 0; ni < 4; ni++)
                    mma_tf32(acc[mi][ni], afr[mi], bfr[ni]);
        }
        st ^= 1;
    }

    if constexpr (CTRANS) {
        // n-major output: 4 phases of 32 n-cols staged in smem (aliases As).
        float (*Ts)[TSP] = reinterpret_cast<float (*)[TSP]>(&As[0][0]);
        #pragma unroll
        for (int p = 0; p < 4; p++) {
            __syncthreads();
            if ((wid >> 1) == p) {
                #pragma unroll
                for (int mi = 0; mi < 4; mi++)
                    #pragma unroll
                    for (int ni = 0; ni < 4; ni++)
                        #pragma unroll
                        for (int c = 0; c < 4; c++) {
                            int rr = wm + mi * 16 + gid + ((c >= 2) ? 8 : 0);
                            int cc = ni * 8 + tig * 2 + (c & 1);
                            Ts[cc][rr] = acc[mi][ni][c];
                        }
            }
            __syncthreads();
            int nn = tid >> 3;
            int mm = (tid & 7) * 16;
            int grow = bn + p * 32 + nn;
            if (grow < N) {
                size_t base = (size_t)grow * MTOT + bm + mm;
                #pragma unroll
                for (int q = 0; q < 4; q++)
                    *reinterpret_cast<float4*>(&C[base + q * 4]) =
                        *reinterpret_cast<const float4*>(&Ts[nn][mm + q * 4]);
            }
        }
    } else {
        // m-major epilogue (N even, c even => c+1 < N)
        #pragma unroll
        for (int mi = 0; mi < 4; mi++) {
            int r = bm + wm + mi * 16 + gid;
            #pragma unroll
            for (int ni = 0; ni < 4; ni++) {
                int c = bn + wn + ni * 8 + tig * 2;
                if (c < N) {
                    float d0 = acc[mi][ni][0], d1 = acc[mi][ni][1];
                    float d2 = acc[mi][ni][2], d3 = acc[mi][ni][3];
                    if (MODE == 1) {
                        float b0 = bias[c], b1 = bias[c + 1];
                        d0 = softplusf(d0 + b0); d1 = softplusf(d1 + b1);
                        d2 = softplusf(d2 + b0); d3 = softplusf(d3 + b1);
                    }
                    if (MODE == 2) {
                        d0 = tf32r(d0); d1 = tf32r(d1);
                        d2 = tf32r(d2); d3 = tf32r(d3);
                    }
                    if (MODE == 3 && c < DTR) {
                        d0 = tf32r(d0); d1 = tf32r(d1);
                        d2 = tf32r(d2); d3 = tf32r(d3);
                    }
                    C[(size_t)r * ldc + c]           = d0;
                    C[(size_t)r * ldc + c + 1]       = d1;
                    C[(size_t)(r + 8) * ldc + c]     = d2;
                    C[(size_t)(r + 8) * ldc + c + 1] = d3;
                }
            }
        }
    }
}

// ----------------------------------------------------------------------------
// 32x32 tiled transpose: in (R x Ccols) -> out (Ccols x R). R,C % 32 == 0.
// ----------------------------------------------------------------------------
__global__ void transpose_kernel(const float* __restrict__ in,
                                 float* __restrict__ out, int R, int Ccols)
{
    __shared__ float tile[32][33];
    int c0 = blockIdx.x * 32, r0 = blockIdx.y * 32;
    int x = threadIdx.x, y = threadIdx.y;
    #pragma unroll
    for (int i = 0; i < 32; i += 8)
        tile[y + i][x] = in[(size_t)(r0 + y + i) * Ccols + c0 + x];
    __syncthreads();
    #pragma unroll
    for (int i = 0; i < 32; i += 8)
        out[(size_t)(c0 + y + i) * R + r0 + x] = tile[x][y + i];
}

// ----------------------------------------------------------------------------
// Causal depthwise conv (k=4) + SiLU. Writes full (uT) + tf32-rounded (uTr).
// ----------------------------------------------------------------------------
__global__ void conv_silu_kernel(const float* __restrict__ xzT,
                                 const float* __restrict__ cw,
                                 const float* __restrict__ cb,
                                 float* __restrict__ uT,
                                 float* __restrict__ uTr)
{
    int i = blockIdx.x * blockDim.x + threadIdx.x;
    int d = i >> 13;
    int m = i & 8191;
    int t = m & 1023;
    const float* src = xzT + (size_t)d * MTOT + m;
    float w0 = cw[d * 4 + 0], w1 = cw[d * 4 + 1];
    float w2 = cw[d * 4 + 2], w3 = cw[d * 4 + 3];
    float acc = cb[d];
    if (t >= 3) acc = fmaf(src[-3], w0, acc);
    if (t >= 2) acc = fmaf(src[-2], w1, acc);
    if (t >= 1) acc = fmaf(src[-1], w2, acc);
    acc = fmaf(src[0], w3, acc);
    float s = siluf(acc);
    uT [(size_t)d * MTOT + m] = s;
    uTr[(size_t)d * MTOT + m] = tf32r(s);
}

// ----------------------------------------------------------------------------
// Selective scan. Block = 256 thr (8 warps) = 16 channels of ONE batch.
// B/C double-buffered in smem per 32-t chunk; next chunk's cp.async overlaps
// the current chunk's recurrence. Warp: 2 channels, lane owns states
// (l, l+32). Fused skip + gate.
// ----------------------------------------------------------------------------
__global__ void __launch_bounds__(256) ssm_scan_kernel(
    const float* __restrict__ proj,
    const float* __restrict__ dtT,
    const float* __restrict__ uT,
    const float* __restrict__ xzT,
    const float* __restrict__ A_log,
    const float* __restrict__ Dparam,
    float* __restrict__ yT)
{
    __shared__ float sBC[2][32][128];   // 32 KB: [j][0:64)=B, [64:128)=C
    const unsigned FULL = 0xFFFFFFFFu;
    const float L2E = 1.4426950408889634f;
    const int tid  = threadIdx.x;
    const int wid  = tid >> 5;
    const int lane = tid & 31;
    const int b  = blockIdx.y;
    const int d0 = blockIdx.x * 16 + wid * 2;
    const int d1 = d0 + 1;

    float A00 = -__expf(A_log[(size_t)d0 * NS + lane])      * L2E;
    float A01 = -__expf(A_log[(size_t)d0 * NS + lane + 32]) * L2E;
    float A10 = -__expf(A_log[(size_t)d1 * NS + lane])      * L2E;
    float A11 = -__expf(A_log[(size_t)d1 * NS + lane + 32]) * L2E;
    float D0 = Dparam[d0], D1 = Dparam[d1];

    float h00 = 0.f, h01 = 0.f, h10 = 0.f, h11 = 0.f;

    auto issueBC = [&](int tc, int st) {
        size_t mb = (size_t)b * LL + tc;
        #pragma unroll
        for (int it = 0; it < 4; it++) {
            int s   = tid + it * 256;
            int row = s >> 5;
            int c4  = (s & 31) * 4;
            cpa16(&sBC[st][row][c4], proj + (mb + row) * PROJC + 48 + c4);
        }
        asm volatile("cp.async.commit_group;\n");
    };

    issueBC(0, 0);

    int st = 0;
    for (int tc = 0; tc < LL; tc += 32, st ^= 1) {
        const size_t mb = (size_t)b * LL + tc;

        float dtv0 = dtT[(size_t)d0 * MTOT + mb + lane];
        float dtv1 = dtT[(size_t)d1 * MTOT + mb + lane];
        float uv0  = uT [(size_t)d0 * MTOT + mb + lane];
        float uv1  = uT [(size_t)d1 * MTOT + mb + lane];
        float zv0  = xzT[(size_t)(DI + d0) * MTOT + mb + lane];
        float zv1  = xzT[(size_t)(DI + d1) * MTOT + mb + lane];
        float duv0 = dtv0 * uv0;
        float duv1 = dtv1 * uv1;

        if (tc + 32 < LL) {
            issueBC(tc + 32, st ^ 1);       // overlaps this chunk's compute
            asm volatile("cp.async.wait_group 1;\n");
        } else {
            asm volatile("cp.async.wait_group 0;\n");
        }
        __syncthreads();

        float y0keep = 0.f, y1keep = 0.f;
        #pragma unroll 8
        for (int j = 0; j < 32; j++) {
            float Bn0 = sBC[st][j][lane];
            float Bn1 = sBC[st][j][lane + 32];
            float Cn0 = sBC[st][j][64 + lane];
            float Cn1 = sBC[st][j][96 + lane];
            float dt0 = __shfl_sync(FULL, dtv0, j);
            float dt1 = __shfl_sync(FULL, dtv1, j);
            float du0 = __shfl_sync(FULL, duv0, j);
            float du1 = __shfl_sync(FULL, duv1, j);
            h00 = fmaf(ex2f(dt0 * A00), h00, du0 * Bn0);
            h01 = fmaf(ex2f(dt0 * A01), h01, du0 * Bn1);
            h10 = fmaf(ex2f(dt1 * A10), h10, du1 * Bn0);
            h11 = fmaf(ex2f(dt1 * A11), h11, du1 * Bn1);
            float y0 = fmaf(h00, Cn0, h01 * Cn1);
            float y1 = fmaf(h10, Cn0, h11 * Cn1);
            #pragma unroll
            for (int off = 16; off; off >>= 1) {
                y0 += __shfl_xor_sync(FULL, y0, off);
                y1 += __shfl_xor_sync(FULL, y1, off);
            }
            if (lane == j) { y0keep = y0; y1keep = y1; }
        }
        __syncthreads();   // all warps done with sBC[st] before reissue

        float out0 = (y0keep + uv0 * D0) * siluf(zv0);
        float out1 = (y1keep + uv1 * D1) * siluf(zv1);
        yT[(size_t)d0 * MTOT + mb + lane] = tf32r(out0);
        yT[(size_t)d1 * MTOT + mb + lane] = tf32r(out1);
    }
}

// ----------------------------------------------------------------------------
// kernel_launch
// ----------------------------------------------------------------------------
extern "C" void kernel_launch(void* const* d_in, const int* in_sizes, int n_in,
                              void* d_out, int out_size)
{
    const float* x     = (const float*)d_in[0];
    const float* W_in  = (const float*)d_in[1];
    const float* cw    = (const float*)d_in[2];
    const float* cb    = (const float*)d_in[3];
    const float* W_x   = (const float*)d_in[4];
    const float* W_dt  = (const float*)d_in[5];
    const float* b_dt  = (const float*)d_in[6];
    const float* A_log = (const float*)d_in[7];
    const float* Dp    = (const float*)d_in[8];
    const float* W_out = (const float*)d_in[9];

    float *xzT, *uT, *uTr, *proj, *dtm, *dtT, *yT, *mid, *xr;
    float *win, *wx, *wdt, *wout;
    cudaGetSymbolAddress((void**)&xzT,  g_xzT);
    cudaGetSymbolAddress((void**)&uT,   g_uT);
    cudaGetSymbolAddress((void**)&uTr,  g_uTr);
    cudaGetSymbolAddress((void**)&proj, g_proj);
    cudaGetSymbolAddress((void**)&dtm,  g_dtm);
    cudaGetSymbolAddress((void**)&dtT,  g_dtT);
    cudaGetSymbolAddress((void**)&yT,   g_yT);
    cudaGetSymbolAddress((void**)&mid,  g_mid);
    cudaGetSymbolAddress((void**)&xr,   g_xr);
    cudaGetSymbolAddress((void**)&win,  g_win);
    cudaGetSymbolAddress((void**)&wx,   g_wx);
    cudaGetSymbolAddress((void**)&wdt,  g_wdt);
    cudaGetSymbolAddress((void**)&wout, g_wout);

    const dim3 tb256(256);
    const int MB = MTOT / TBM;   // 64

    // ---- tf32 pre-rounding (weights + layer-0 input) ----
    auto rgrid = [](int n) { return (n / 4 + 255) / 256; };
    round_tf32_kernel<<<rgrid(MTOT * DM), tb256>>>(x,     xr,   MTOT * DM);
    round_tf32_kernel<<<rgrid(WIN_SZ),    tb256>>>(W_in,  win,  WIN_SZ);
    round_tf32_kernel<<<rgrid(WX_SZ),     tb256>>>(W_x,   wx,   WX_SZ);
    round_tf32_kernel<<<rgrid(WDT_SZ),    tb256>>>(W_dt,  wdt,  WDT_SZ);
    round_tf32_kernel<<<rgrid(WOUT_SZ),   tb256>>>(W_out, wout, WOUT_SZ);

    for (int l = 0; l < 2; l++) {
        const float* xin = (l == 0) ? xr : mid;   // both tf32-rounded
        float* xout = (l == 1) ? (float*)d_out : mid;

        // 1. in-proj, n-major output straight into xzT (CTRANS, no softplus)
        tgemm_kernel<false, true, 0>
            <<<dim3(XZC / TBN, MB), tb256>>>(
                xin, DM, win + (size_t)l * XZC * DM, nullptr,
                xzT, 0, XZC, DM);

        // 2. conv + silu -> uT (full) + uTr (rounded)
        conv_silu_kernel<<<(DI * MTOT) / 256, tb256>>>(
            xzT, cw + (size_t)l * DI * 4, cb + (size_t)l * DI, uT, uTr);

        // 3. x-proj: proj[m,176] = u @ W_x^T ; rounds dt_r cols (<48) only
        tgemm_kernel<true, false, 3>
            <<<dim3((PROJC + TBN - 1) / TBN, MB), tb256>>>(
                uTr, 0, wx + (size_t)l * PROJC * DI, nullptr,
                proj, PROJC, PROJC, DI);

        // 4. dt: m-major + fused softplus (parallel across warps) -> dtm
        tgemm_kernel<false, false, 1>
            <<<dim3(DI / TBN, MB), tb256>>>(
                proj, PROJC, wdt + (size_t)l * DI * DTR,
                b_dt + (size_t)l * DI, dtm, DI, DI, DTR);

        // 5. transpose dt_m -> dtT (d-major)
        transpose_kernel<<<dim3(DI / 32, MTOT / 32), dim3(32, 8)>>>(
            dtm, dtT, MTOT, DI);

        // 6. selective scan + skip + gate -> yT (rounded for out-proj)
        ssm_scan_kernel<<<dim3(DI / 16, BB), tb256>>>(
            proj, dtT, uT, xzT,
            A_log + (size_t)l * DI * NS, Dp + (size_t)l * DI, yT);

        // 7. out-proj: xout = y @ W_out^T ; l=0 rounds (feeds next in-proj)
        if (l == 0)
            tgemm_kernel<true, false, 2>
                <<<dim3(DM / TBN, MB), tb256>>>(
                    yT, 0, wout + (size_t)l * DM * DI, nullptr,
                    xout, DM, DM, DI);
        else
            tgemm_kernel<true, false, 0>
                <<<dim3(DM / TBN, MB), tb256>>>(
                    yT, 0, wout + (size_t)l * DM * DI, nullptr,
                    xout, DM, DM, DI);
    }
}

// round 10
// speedup vs baseline: 1.0956x; 1.0371x over previous
#include <cuda_runtime.h>
#include <cstdint>

// ----------------------------------------------------------------------------
// Problem constants (fixed shapes)
// ----------------------------------------------------------------------------
constexpr int BB   = 8;
constexpr int LL   = 1024;
constexpr int DM   = 768;
constexpr int DI   = 1536;
constexpr int NS   = 64;
constexpr int DTR  = 48;
constexpr int MTOT = BB * LL;        // 8192
constexpr int XZC  = 2 * DI;         // 3072
constexpr int PROJC = DTR + 2 * NS;  // 176

// ----------------------------------------------------------------------------
// Scratch (device globals; no allocation allowed)
// ----------------------------------------------------------------------------
__device__ float g_xzT [MTOT * XZC];   // (3072, m) in-proj output, d-major
__device__ float g_uT  [MTOT * DI];    // (d, m) conv+silu, full precision
__device__ float g_uTr [MTOT * DI];    // (d, m) conv+silu, tf32-rounded
__device__ float g_proj[MTOT * PROJC]; // (m, 176) [dt_r(tf32) | B | C]
__device__ float g_dtm [MTOT * DI];    // (m, d) softplus dt (m-major)
__device__ float g_dtT [MTOT * DI];    // (d, m) softplus dt
__device__ float g_yT  [MTOT * DI];    // (d, m) scan out, tf32-rounded
__device__ float g_mid [MTOT * DM];    // inter-layer act (tf32-rounded)
__device__ float g_xr  [MTOT * DM];    // layer-0 input, tf32-rounded

constexpr int WIN_SZ  = 2 * XZC * DM;
constexpr int WX_SZ   = 2 * PROJC * DI;
constexpr int WDT_SZ  = 2 * DI * DTR;
constexpr int WOUT_SZ = 2 * DM * DI;
__device__ float g_win [WIN_SZ];
__device__ float g_wx  [WX_SZ];
__device__ float g_wdt [WDT_SZ];
__device__ float g_wout[WOUT_SZ];

// ----------------------------------------------------------------------------
// Helpers
// ----------------------------------------------------------------------------
__device__ __forceinline__ float siluf(float x) {
    return x * (1.0f / (1.0f + __expf(-x)));
}
__device__ __forceinline__ float softplusf(float x) {
    return fmaxf(x, 0.0f) + log1pf(__expf(-fabsf(x)));
}
__device__ __forceinline__ float tf32r(float x) {
    uint32_t r;
    asm("cvt.rna.tf32.f32 %0, %1;" : "=r"(r) : "f"(x));
    return __uint_as_float(r);
}
__device__ __forceinline__ float ex2f(float x) {   // MUFU EX2
    float r;
    asm("ex2.approx.f32 %0, %1;" : "=f"(r) : "f"(x));
    return r;
}
__device__ __forceinline__ void mma_tf32(float* d, const uint32_t* a,
                                         const uint32_t* b) {
    asm volatile(
        "mma.sync.aligned.m16n8k8.row.col.f32.tf32.tf32.f32 "
        "{%0,%1,%2,%3}, {%4,%5,%6,%7}, {%8,%9}, {%0,%1,%2,%3};\n"
        : "+f"(d[0]), "+f"(d[1]), "+f"(d[2]), "+f"(d[3])
        : "r"(a[0]), "r"(a[1]), "r"(a[2]), "r"(a[3]), "r"(b[0]), "r"(b[1]));
}
__device__ __forceinline__ void cpa16(float* smem, const float* g) {
    uint32_t dst = (uint32_t)__cvta_generic_to_shared(smem);
    asm volatile("cp.async.ca.shared.global [%0], [%1], 16;\n"
                 :: "r"(dst), "l"(g));
}
__device__ __forceinline__ void cpa16z(float* smem, const float* g, int sz) {
    uint32_t dst = (uint32_t)__cvta_generic_to_shared(smem);
    asm volatile("cp.async.ca.shared.global [%0], [%1], 16, %2;\n"
                 :: "r"(dst), "l"(g), "r"(sz));
}

// ----------------------------------------------------------------------------
// tf32 rounding prep kernel (float4; n % 4 == 0)
// ----------------------------------------------------------------------------
__global__ void round_tf32_kernel(const float* __restrict__ in,
                                  float* __restrict__ out, int n)
{
    int i = (blockIdx.x * blockDim.x + threadIdx.x) * 4;
    if (i < n) {
        float4 v = *reinterpret_cast<const float4*>(in + i);
        v.x = tf32r(v.x); v.y = tf32r(v.y);
        v.z = tf32r(v.z); v.w = tf32r(v.w);
        *reinterpret_cast<float4*>(out + i) = v;
    }
}

// ============================================================================
// Tensor-core tf32 GEMM, cp.async 2-stage pipeline. Inputs PRE-ROUNDED tf32.
//   C[m,n] = sum_k A[m,k] * W[n,k]  (W row-major N x K)
//   ATRANS: A stored K x MTOT (d-major);  else A m-major with lda.
//   CTRANS: C stored N x MTOT (n-major) via smem-staged transpose (aliases As)
//   MODE: 0 none | 1 softplus(+bias) | 2 round-all | 3 round cols < DTR
// Block 128x128x16, 256 thr, warp grid 2x4 (warp tile 64x32), mma m16n8k8.
// ============================================================================
constexpr int TBM = 128, TBN = 128, TBK = 16;
constexpr int SKM = 136;      // [k][m] stride
constexpr int SMK = 20;       // [m][k]/[n][k] stride
constexpr int ASTG = 2560;    // max(16*136, 128*20)
constexpr int BSTG = 2560;
constexpr int TSP  = 136;     // transpose staging stride

template<bool ATRANS, bool CTRANS, int MODE>
__global__ void __launch_bounds__(256, 2) tgemm_kernel(
    const float* __restrict__ A, int lda,
    const float* __restrict__ W,
    const float* __restrict__ bias,
    float* __restrict__ C, int ldc,
    int N, int K)
{
    __shared__ float As[2][ASTG];
    __shared__ float Bs[2][BSTG];

    const int tid  = threadIdx.x;
    const int bm   = blockIdx.y * TBM;
    const int bn   = blockIdx.x * TBN;
    const int wid  = tid >> 5;
    const int lane = tid & 31;
    const int wm   = (wid & 1) * 64;
    const int wn   = (wid >> 1) * 32;
    const int gid  = lane >> 2;
    const int tig  = lane & 3;

    float acc[4][4][4];
    #pragma unroll
    for (int i = 0; i < 4; i++)
        #pragma unroll
        for (int j = 0; j < 4; j++)
            #pragma unroll
            for (int c = 0; c < 4; c++) acc[i][j][c] = 0.0f;

    auto issue_load = [&](int k0, int st) {
        #pragma unroll
        for (int itr = 0; itr < 2; itr++) {
            int s = tid + itr * 256;
            if (ATRANS) {
                int kk = s >> 5, mc = (s & 31) * 4;
                cpa16(&As[st][kk * SKM + mc],
                      A + (size_t)(k0 + kk) * MTOT + bm + mc);
            } else {
                int row = s >> 2, kc = (s & 3) * 4;
                cpa16(&As[st][row * SMK + kc],
                      A + (size_t)(bm + row) * lda + k0 + kc);
            }
            int n = s >> 2, kc = (s & 3) * 4;
            cpa16z(&Bs[st][n * SMK + kc],
                   W + (size_t)(bn + n) * K + k0 + kc,
                   (bn + n < N) ? 16 : 0);
        }
        asm volatile("cp.async.commit_group;\n");
    };

    issue_load(0, 0);

    const int kt = K / TBK;
    int st = 0;
    for (int it = 0; it < kt; it++) {
        asm volatile("cp.async.wait_group 0;\n");
        __syncthreads();
        if (it + 1 < kt) issue_load((it + 1) * TBK, st ^ 1);

        #pragma unroll
        for (int ks = 0; ks < 2; ks++) {
            const int kb = ks * 8;
            uint32_t afr[4][4], bfr[4][2];
            #pragma unroll
            for (int mi = 0; mi < 4; mi++) {
                int r = wm + mi * 16 + gid;
                if (ATRANS) {
                    afr[mi][0] = __float_as_uint(As[st][(kb + tig) * SKM + r]);
                    afr[mi][1] = __float_as_uint(As[st][(kb + tig) * SKM + r + 8]);
                    afr[mi][2] = __float_as_uint(As[st][(kb + tig + 4) * SKM + r]);
                    afr[mi][3] = __float_as_uint(As[st][(kb + tig + 4) * SKM + r + 8]);
                } else {
                    afr[mi][0] = __float_as_uint(As[st][r * SMK + kb + tig]);
                    afr[mi][1] = __float_as_uint(As[st][(r + 8) * SMK + kb + tig]);
                    afr[mi][2] = __float_as_uint(As[st][r * SMK + kb + tig + 4]);
                    afr[mi][3] = __float_as_uint(As[st][(r + 8) * SMK + kb + tig + 4]);
                }
            }
            #pragma unroll
            for (int ni = 0; ni < 4; ni++) {
                int c = wn + ni * 8 + gid;
                bfr[ni][0] = __float_as_uint(Bs[st][c * SMK + kb + tig]);
                bfr[ni][1] = __float_as_uint(Bs[st][c * SMK + kb + tig + 4]);
            }
            #pragma unroll
            for (int mi = 0; mi < 4; mi++)
                #pragma unroll
                for (int ni = 0; ni < 4; ni++)
                    mma_tf32(acc[mi][ni], afr[mi], bfr[ni]);
        }
        st ^= 1;
    }

    if constexpr (CTRANS) {
        // n-major output: 4 phases of 32 n-cols staged in smem (aliases As).
        float (*Ts)[TSP] = reinterpret_cast<float (*)[TSP]>(&As[0][0]);
        #pragma unroll
        for (int p = 0; p < 4; p++) {
            __syncthreads();
            if ((wid >> 1) == p) {
                #pragma unroll
                for (int mi = 0; mi < 4; mi++)
                    #pragma unroll
                    for (int ni = 0; ni < 4; ni++)
                        #pragma unroll
                        for (int c = 0; c < 4; c++) {
                            int rr = wm + mi * 16 + gid + ((c >= 2) ? 8 : 0);
                            int cc = ni * 8 + tig * 2 + (c & 1);
                            Ts[cc][rr] = acc[mi][ni][c];
                        }
            }
            __syncthreads();
            int nn = tid >> 3;
            int mm = (tid & 7) * 16;
            int grow = bn + p * 32 + nn;
            if (grow < N) {
                size_t base = (size_t)grow * MTOT + bm + mm;
                #pragma unroll
                for (int q = 0; q < 4; q++)
                    *reinterpret_cast<float4*>(&C[base + q * 4]) =
                        *reinterpret_cast<const float4*>(&Ts[nn][mm + q * 4]);
            }
        }
    } else {
        // m-major epilogue (N even, c even => c+1 < N)
        #pragma unroll
        for (int mi = 0; mi < 4; mi++) {
            int r = bm + wm + mi * 16 + gid;
            #pragma unroll
            for (int ni = 0; ni < 4; ni++) {
                int c = bn + wn + ni * 8 + tig * 2;
                if (c < N) {
                    float d0 = acc[mi][ni][0], d1 = acc[mi][ni][1];
                    float d2 = acc[mi][ni][2], d3 = acc[mi][ni][3];
                    if (MODE == 1) {
                        float b0 = bias[c], b1 = bias[c + 1];
                        d0 = softplusf(d0 + b0); d1 = softplusf(d1 + b1);
                        d2 = softplusf(d2 + b0); d3 = softplusf(d3 + b1);
                    }
                    if (MODE == 2) {
                        d0 = tf32r(d0); d1 = tf32r(d1);
                        d2 = tf32r(d2); d3 = tf32r(d3);
                    }
                    if (MODE == 3 && c < DTR) {
                        d0 = tf32r(d0); d1 = tf32r(d1);
                        d2 = tf32r(d2); d3 = tf32r(d3);
                    }
                    C[(size_t)r * ldc + c]           = d0;
                    C[(size_t)r * ldc + c + 1]       = d1;
                    C[(size_t)(r + 8) * ldc + c]     = d2;
                    C[(size_t)(r + 8) * ldc + c + 1] = d3;
                }
            }
        }
    }
}

// ----------------------------------------------------------------------------
// 32x32 tiled transpose: in (R x Ccols) -> out (Ccols x R). R,C % 32 == 0.
// ----------------------------------------------------------------------------
__global__ void transpose_kernel(const float* __restrict__ in,
                                 float* __restrict__ out, int R, int Ccols)
{
    __shared__ float tile[32][33];
    int c0 = blockIdx.x * 32, r0 = blockIdx.y * 32;
    int x = threadIdx.x, y = threadIdx.y;
    #pragma unroll
    for (int i = 0; i < 32; i += 8)
        tile[y + i][x] = in[(size_t)(r0 + y + i) * Ccols + c0 + x];
    __syncthreads();
    #pragma unroll
    for (int i = 0; i < 32; i += 8)
        out[(size_t)(c0 + y + i) * R + r0 + x] = tile[x][y + i];
}

// ----------------------------------------------------------------------------
// Causal depthwise conv (k=4) + SiLU. Writes full (uT) + tf32-rounded (uTr).
// ----------------------------------------------------------------------------
__global__ void conv_silu_kernel(const float* __restrict__ xzT,
                                 const float* __restrict__ cw,
                                 const float* __restrict__ cb,
                                 float* __restrict__ uT,
                                 float* __restrict__ uTr)
{
    int i = blockIdx.x * blockDim.x + threadIdx.x;
    int d = i >> 13;
    int m = i & 8191;
    int t = m & 1023;
    const float* src = xzT + (size_t)d * MTOT + m;
    float w0 = cw[d * 4 + 0], w1 = cw[d * 4 + 1];
    float w2 = cw[d * 4 + 2], w3 = cw[d * 4 + 3];
    float acc = cb[d];
    if (t >= 3) acc = fmaf(src[-3], w0, acc);
    if (t >= 2) acc = fmaf(src[-2], w1, acc);
    if (t >= 1) acc = fmaf(src[-1], w2, acc);
    acc = fmaf(src[0], w3, acc);
    float s = siluf(acc);
    uT [(size_t)d * MTOT + m] = s;
    uTr[(size_t)d * MTOT + m] = tf32r(s);
}

// ----------------------------------------------------------------------------
// Selective scan v3. Block = 128 thr (4 warps) = 8 channels of ONE batch.
// - B/C double-buffered in smem (cp.async overlapped with compute)
// - dt/du broadcasts via smem (LDS) instead of SHFL
// - y reduction: 2-level shfl butterfly -> 8 smem partials -> per-chunk sum
//   (12 of 14 SHFL per step eliminated; scan was shuffle-throughput-bound)
// ----------------------------------------------------------------------------
__global__ void __launch_bounds__(128) ssm_scan_kernel(
    const float* __restrict__ proj,
    const float* __restrict__ dtT,
    const float* __restrict__ uT,
    const float* __restrict__ xzT,
    const float* __restrict__ A_log,
    const float* __restrict__ Dparam,
    float* __restrict__ yT)
{
    __shared__ float sBC [2][32][128];    // 32 KB
    __shared__ float sdt [4][4][32];      // [warp][dt0,dt1,du0,du1][j] 2 KB
    __shared__ float pbuf[4][2][32][9];   // [warp][ch][j][8 group sums] 9.2 KB

    const unsigned FULL = 0xFFFFFFFFu;
    const float L2E = 1.4426950408889634f;
    const int tid  = threadIdx.x;
    const int wid  = tid >> 5;
    const int lane = tid & 31;
    const int b  = blockIdx.y;
    const int d0 = blockIdx.x * 8 + wid * 2;
    const int d1 = d0 + 1;

    float A00 = -__expf(A_log[(size_t)d0 * NS + lane])      * L2E;
    float A01 = -__expf(A_log[(size_t)d0 * NS + lane + 32]) * L2E;
    float A10 = -__expf(A_log[(size_t)d1 * NS + lane])      * L2E;
    float A11 = -__expf(A_log[(size_t)d1 * NS + lane + 32]) * L2E;
    float D0 = Dparam[d0], D1 = Dparam[d1];

    float h00 = 0.f, h01 = 0.f, h10 = 0.f, h11 = 0.f;

    auto issueBC = [&](int tc, int st) {
        size_t mb = (size_t)b * LL + tc;
        #pragma unroll
        for (int it = 0; it < 8; it++) {
            int s   = tid + it * 128;
            int row = s >> 5;
            int c4  = (s & 31) * 4;
            cpa16(&sBC[st][row][c4], proj + (mb + row) * PROJC + 48 + c4);
        }
        asm volatile("cp.async.commit_group;\n");
    };

    issueBC(0, 0);

    int st = 0;
    for (int tc = 0; tc < LL; tc += 32, st ^= 1) {
        const size_t mb = (size_t)b * LL + tc;

        float dtv0 = dtT[(size_t)d0 * MTOT + mb + lane];
        float dtv1 = dtT[(size_t)d1 * MTOT + mb + lane];
        float uv0  = uT [(size_t)d0 * MTOT + mb + lane];
        float uv1  = uT [(size_t)d1 * MTOT + mb + lane];
        float zv0  = xzT[(size_t)(DI + d0) * MTOT + mb + lane];
        float zv1  = xzT[(size_t)(DI + d1) * MTOT + mb + lane];
        sdt[wid][0][lane] = dtv0;
        sdt[wid][1][lane] = dtv1;
        sdt[wid][2][lane] = dtv0 * uv0;
        sdt[wid][3][lane] = dtv1 * uv1;

        if (tc + 32 < LL) {
            issueBC(tc + 32, st ^ 1);       // overlaps this chunk's compute
            asm volatile("cp.async.wait_group 1;\n");
        } else {
            asm volatile("cp.async.wait_group 0;\n");
        }
        __syncthreads();   // sBC[st] ready; sdt visible to whole warp

        #pragma unroll 8
        for (int j = 0; j < 32; j++) {
            float Bn0 = sBC[st][j][lane];
            float Bn1 = sBC[st][j][lane + 32];
            float Cn0 = sBC[st][j][64 + lane];
            float Cn1 = sBC[st][j][96 + lane];
            float dt0 = sdt[wid][0][j];
            float dt1 = sdt[wid][1][j];
            float du0 = sdt[wid][2][j];
            float du1 = sdt[wid][3][j];
            h00 = fmaf(ex2f(dt0 * A00), h00, du0 * Bn0);
            h01 = fmaf(ex2f(dt0 * A01), h01, du0 * Bn1);
            h10 = fmaf(ex2f(dt1 * A10), h10, du1 * Bn0);
            h11 = fmaf(ex2f(dt1 * A11), h11, du1 * Bn1);
            float y0 = fmaf(h00, Cn0, h01 * Cn1);
            float y1 = fmaf(h10, Cn0, h11 * Cn1);
            // 2-level butterfly: lanes 0..7 end with the 8 disjoint group sums
            y0 += __shfl_xor_sync(FULL, y0, 16);
            y0 += __shfl_xor_sync(FULL, y0, 8);
            y1 += __shfl_xor_sync(FULL, y1, 16);
            y1 += __shfl_xor_sync(FULL, y1, 8);
            if (lane < 8) {
                pbuf[wid][0][j][lane] = y0;
                pbuf[wid][1][j][lane] = y1;
            }
        }
        __syncwarp();

        // per-chunk: lane j sums its 8 partials (stride 9 -> conflict-free)
        float y0f = 0.f, y1f = 0.f;
        #pragma unroll
        for (int i = 0; i < 8; i++) {
            y0f += pbuf[wid][0][lane][i];
            y1f += pbuf[wid][1][lane][i];
        }

        __syncthreads();   // all warps done with sBC[st] before reissue

        float out0 = (y0f + uv0 * D0) * siluf(zv0);
        float out1 = (y1f + uv1 * D1) * siluf(zv1);
        yT[(size_t)d0 * MTOT + mb + lane] = tf32r(out0);
        yT[(size_t)d1 * MTOT + mb + lane] = tf32r(out1);
    }
}

// ----------------------------------------------------------------------------
// kernel_launch
// ----------------------------------------------------------------------------
extern "C" void kernel_launch(void* const* d_in, const int* in_sizes, int n_in,
                              void* d_out, int out_size)
{
    const float* x     = (const float*)d_in[0];
    const float* W_in  = (const float*)d_in[1];
    const float* cw    = (const float*)d_in[2];
    const float* cb    = (const float*)d_in[3];
    const float* W_x   = (const float*)d_in[4];
    const float* W_dt  = (const float*)d_in[5];
    const float* b_dt  = (const float*)d_in[6];
    const float* A_log = (const float*)d_in[7];
    const float* Dp    = (const float*)d_in[8];
    const float* W_out = (const float*)d_in[9];

    float *xzT, *uT, *uTr, *proj, *dtm, *dtT, *yT, *mid, *xr;
    float *win, *wx, *wdt, *wout;
    cudaGetSymbolAddress((void**)&xzT,  g_xzT);
    cudaGetSymbolAddress((void**)&uT,   g_uT);
    cudaGetSymbolAddress((void**)&uTr,  g_uTr);
    cudaGetSymbolAddress((void**)&proj, g_proj);
    cudaGetSymbolAddress((void**)&dtm,  g_dtm);
    cudaGetSymbolAddress((void**)&dtT,  g_dtT);
    cudaGetSymbolAddress((void**)&yT,   g_yT);
    cudaGetSymbolAddress((void**)&mid,  g_mid);
    cudaGetSymbolAddress((void**)&xr,   g_xr);
    cudaGetSymbolAddress((void**)&win,  g_win);
    cudaGetSymbolAddress((void**)&wx,   g_wx);
    cudaGetSymbolAddress((void**)&wdt,  g_wdt);
    cudaGetSymbolAddress((void**)&wout, g_wout);

    const dim3 tb256(256);
    const int MB = MTOT / TBM;   // 64

    // ---- tf32 pre-rounding (weights + layer-0 input) ----
    auto rgrid = [](int n) { return (n / 4 + 255) / 256; };
    round_tf32_kernel<<<rgrid(MTOT * DM), tb256>>>(x,     xr,   MTOT * DM);
    round_tf32_kernel<<<rgrid(WIN_SZ),    tb256>>>(W_in,  win,  WIN_SZ);
    round_tf32_kernel<<<rgrid(WX_SZ),     tb256>>>(W_x,   wx,   WX_SZ);
    round_tf32_kernel<<<rgrid(WDT_SZ),    tb256>>>(W_dt,  wdt,  WDT_SZ);
    round_tf32_kernel<<<rgrid(WOUT_SZ),   tb256>>>(W_out, wout, WOUT_SZ);

    for (int l = 0; l < 2; l++) {
        const float* xin = (l == 0) ? xr : mid;   // both tf32-rounded
        float* xout = (l == 1) ? (float*)d_out : mid;

        // 1. in-proj, n-major output straight into xzT (CTRANS, no softplus)
        tgemm_kernel<false, true, 0>
            <<<dim3(XZC / TBN, MB), tb256>>>(
                xin, DM, win + (size_t)l * XZC * DM, nullptr,
                xzT, 0, XZC, DM);

        // 2. conv + silu -> uT (full) + uTr (rounded)
        conv_silu_kernel<<<(DI * MTOT) / 256, tb256>>>(
            xzT, cw + (size_t)l * DI * 4, cb + (size_t)l * DI, uT, uTr);

        // 3. x-proj: proj[m,176] = u @ W_x^T ; rounds dt_r cols (<48) only
        tgemm_kernel<true, false, 3>
            <<<dim3((PROJC + TBN - 1) / TBN, MB), tb256>>>(
                uTr, 0, wx + (size_t)l * PROJC * DI, nullptr,
                proj, PROJC, PROJC, DI);

        // 4. dt: m-major + fused softplus (parallel across warps) -> dtm
        tgemm_kernel<false, false, 1>
            <<<dim3(DI / TBN, MB), tb256>>>(
                proj, PROJC, wdt + (size_t)l * DI * DTR,
                b_dt + (size_t)l * DI, dtm, DI, DI, DTR);

        // 5. transpose dt_m -> dtT (d-major)
        transpose_kernel<<<dim3(DI / 32, MTOT / 32), dim3(32, 8)>>>(
            dtm, dtT, MTOT, DI);

        // 6. selective scan + skip + gate -> yT (rounded for out-proj)
        ssm_scan_kernel<<<dim3(DI / 8, BB), dim3(128)>>>(
            proj, dtT, uT, xzT,
            A_log + (size_t)l * DI * NS, Dp + (size_t)l * DI, yT);

        // 7. out-proj: xout = y @ W_out^T ; l=0 rounds (feeds next in-proj)
        if (l == 0)
            tgemm_kernel<true, false, 2>
                <<<dim3(DM / TBN, MB), tb256>>>(
                    yT, 0, wout + (size_t)l * DM * DI, nullptr,
                    xout, DM, DM, DI);
        else
            tgemm_kernel<true, false, 0>
                <<<dim3(DM / TBN, MB), tb256>>>(
                    yT, 0, wout + (size_t)l * DM * DI, nullptr,
                    xout, DM, DM, DI);
    }
}

// round 11
// speedup vs baseline: 1.1288x; 1.0303x over previous
#include <cuda_runtime.h>
#include <cstdint>

// ----------------------------------------------------------------------------
// Problem constants (fixed shapes)
// ----------------------------------------------------------------------------
constexpr int BB   = 8;
constexpr int LL   = 1024;
constexpr int DM   = 768;
constexpr int DI   = 1536;
constexpr int NS   = 64;
constexpr int DTR  = 48;
constexpr int MTOT = BB * LL;        // 8192
constexpr int XZC  = 2 * DI;         // 3072
constexpr int PROJC = DTR + 2 * NS;  // 176

// ----------------------------------------------------------------------------
// Scratch (device globals; no allocation allowed)
// ----------------------------------------------------------------------------
__device__ float g_xzT [MTOT * XZC];   // (3072, m) in-proj output, d-major
__device__ float g_uT  [MTOT * DI];    // (d, m) conv+silu, full precision
__device__ float g_uTr [MTOT * DI];    // (d, m) conv+silu, tf32-rounded
__device__ float g_proj[MTOT * PROJC]; // (m, 176) [dt_r(tf32) | B | C]
__device__ float g_dtm [MTOT * DI];    // (m, d) softplus dt (m-major)
__device__ float g_dtT [MTOT * DI];    // (d, m) softplus dt
__device__ float g_yT  [MTOT * DI];    // (d, m) scan out, tf32-rounded
__device__ float g_mid [MTOT * DM];    // inter-layer act (tf32-rounded)
__device__ float g_xr  [MTOT * DM];    // layer-0 input, tf32-rounded

constexpr int WIN_SZ  = 2 * XZC * DM;
constexpr int WX_SZ   = 2 * PROJC * DI;
constexpr int WDT_SZ  = 2 * DI * DTR;
constexpr int WOUT_SZ = 2 * DM * DI;
__device__ float g_win [WIN_SZ];
__device__ float g_wx  [WX_SZ];
__device__ float g_wdt [WDT_SZ];
__device__ float g_wout[WOUT_SZ];

// ----------------------------------------------------------------------------
// Helpers
// ----------------------------------------------------------------------------
__device__ __forceinline__ float siluf(float x) {
    return x * (1.0f / (1.0f + __expf(-x)));
}
__device__ __forceinline__ float softplusf(float x) {
    return fmaxf(x, 0.0f) + log1pf(__expf(-fabsf(x)));
}
__device__ __forceinline__ float tf32r(float x) {
    uint32_t r;
    asm("cvt.rna.tf32.f32 %0, %1;" : "=r"(r) : "f"(x));
    return __uint_as_float(r);
}
__device__ __forceinline__ float ex2f(float x) {   // MUFU EX2
    float r;
    asm("ex2.approx.f32 %0, %1;" : "=f"(r) : "f"(x));
    return r;
}
__device__ __forceinline__ void mma_tf32(float* d, const uint32_t* a,
                                         const uint32_t* b) {
    asm volatile(
        "mma.sync.aligned.m16n8k8.row.col.f32.tf32.tf32.f32 "
        "{%0,%1,%2,%3}, {%4,%5,%6,%7}, {%8,%9}, {%0,%1,%2,%3};\n"
        : "+f"(d[0]), "+f"(d[1]), "+f"(d[2]), "+f"(d[3])
        : "r"(a[0]), "r"(a[1]), "r"(a[2]), "r"(a[3]), "r"(b[0]), "r"(b[1]));
}
__device__ __forceinline__ void cpa16(float* smem, const float* g) {
    uint32_t dst = (uint32_t)__cvta_generic_to_shared(smem);
    asm volatile("cp.async.ca.shared.global [%0], [%1], 16;\n"
                 :: "r"(dst), "l"(g));
}
__device__ __forceinline__ void cpa16z(float* smem, const float* g, int sz) {
    uint32_t dst = (uint32_t)__cvta_generic_to_shared(smem);
    asm volatile("cp.async.ca.shared.global [%0], [%1], 16, %2;\n"
                 :: "r"(dst), "l"(g), "r"(sz));
}

// ----------------------------------------------------------------------------
// Merged tf32 rounding kernel: 5 arrays in one launch (segment walk).
// ----------------------------------------------------------------------------
constexpr int RQ0 = (MTOT * DM) / 4;
constexpr int RQ1 = RQ0 + WIN_SZ / 4;
constexpr int RQ2 = RQ1 + WX_SZ / 4;
constexpr int RQ3 = RQ2 + WDT_SZ / 4;
constexpr int RQ4 = RQ3 + WOUT_SZ / 4;

__global__ void round_all_kernel(
    const float* __restrict__ x,    float* __restrict__ xr,
    const float* __restrict__ Wi,   float* __restrict__ wi,
    const float* __restrict__ Wx,   float* __restrict__ wx,
    const float* __restrict__ Wdt,  float* __restrict__ wdt,
    const float* __restrict__ Wo,   float* __restrict__ wo)
{
    int q = blockIdx.x * blockDim.x + threadIdx.x;
    if (q >= RQ4) return;
    const float* in; float* out; int base;
    if      (q < RQ0) { in = x;   out = xr;  base = 0;   }
    else if (q < RQ1) { in = Wi;  out = wi;  base = RQ0; }
    else if (q < RQ2) { in = Wx;  out = wx;  base = RQ1; }
    else if (q < RQ3) { in = Wdt; out = wdt; base = RQ2; }
    else              { in = Wo;  out = wo;  base = RQ3; }
    int i = (q - base) * 4;
    float4 v = *reinterpret_cast<const float4*>(in + i);
    v.x = tf32r(v.x); v.y = tf32r(v.y);
    v.z = tf32r(v.z); v.w = tf32r(v.w);
    *reinterpret_cast<float4*>(out + i) = v;
}

// ============================================================================
// Tensor-core tf32 GEMM, cp.async 2-stage pipeline. Inputs PRE-ROUNDED tf32.
//   C[m,n] = sum_k A[m,k] * W[n,k]  (W row-major N x K)
//   ATRANS: A stored K x MTOT (d-major);  else A m-major with lda.
//   CTRANS: C stored N x MTOT (n-major) via smem-staged transpose (aliases As)
//   MODE: 0 none | 1 softplus(+bias) | 2 round-all | 3 round cols < DTR
// ============================================================================
constexpr int TBM = 128, TBN = 128, TBK = 16;
constexpr int SKM = 136;
constexpr int SMK = 20;
constexpr int ASTG = 2560;
constexpr int BSTG = 2560;
constexpr int TSP  = 136;

template<bool ATRANS, bool CTRANS, int MODE>
__global__ void __launch_bounds__(256, 2) tgemm_kernel(
    const float* __restrict__ A, int lda,
    const float* __restrict__ W,
    const float* __restrict__ bias,
    float* __restrict__ C, int ldc,
    int N, int K)
{
    __shared__ float As[2][ASTG];
    __shared__ float Bs[2][BSTG];

    const int tid  = threadIdx.x;
    const int bm   = blockIdx.y * TBM;
    const int bn   = blockIdx.x * TBN;
    const int wid  = tid >> 5;
    const int lane = tid & 31;
    const int wm   = (wid & 1) * 64;
    const int wn   = (wid >> 1) * 32;
    const int gid  = lane >> 2;
    const int tig  = lane & 3;

    float acc[4][4][4];
    #pragma unroll
    for (int i = 0; i < 4; i++)
        #pragma unroll
        for (int j = 0; j < 4; j++)
            #pragma unroll
            for (int c = 0; c < 4; c++) acc[i][j][c] = 0.0f;

    auto issue_load = [&](int k0, int st) {
        #pragma unroll
        for (int itr = 0; itr < 2; itr++) {
            int s = tid + itr * 256;
            if (ATRANS) {
                int kk = s >> 5, mc = (s & 31) * 4;
                cpa16(&As[st][kk * SKM + mc],
                      A + (size_t)(k0 + kk) * MTOT + bm + mc);
            } else {
                int row = s >> 2, kc = (s & 3) * 4;
                cpa16(&As[st][row * SMK + kc],
                      A + (size_t)(bm + row) * lda + k0 + kc);
            }
            int n = s >> 2, kc = (s & 3) * 4;
            cpa16z(&Bs[st][n * SMK + kc],
                   W + (size_t)(bn + n) * K + k0 + kc,
                   (bn + n < N) ? 16 : 0);
        }
        asm volatile("cp.async.commit_group;\n");
    };

    issue_load(0, 0);

    const int kt = K / TBK;
    int st = 0;
    for (int it = 0; it < kt; it++) {
        asm volatile("cp.async.wait_group 0;\n");
        __syncthreads();
        if (it + 1 < kt) issue_load((it + 1) * TBK, st ^ 1);

        #pragma unroll
        for (int ks = 0; ks < 2; ks++) {
            const int kb = ks * 8;
            uint32_t afr[4][4], bfr[4][2];
            #pragma unroll
            for (int mi = 0; mi < 4; mi++) {
                int r = wm + mi * 16 + gid;
                if (ATRANS) {
                    afr[mi][0] = __float_as_uint(As[st][(kb + tig) * SKM + r]);
                    afr[mi][1] = __float_as_uint(As[st][(kb + tig) * SKM + r + 8]);
                    afr[mi][2] = __float_as_uint(As[st][(kb + tig + 4) * SKM + r]);
                    afr[mi][3] = __float_as_uint(As[st][(kb + tig + 4) * SKM + r + 8]);
                } else {
                    afr[mi][0] = __float_as_uint(As[st][r * SMK + kb + tig]);
                    afr[mi][1] = __float_as_uint(As[st][(r + 8) * SMK + kb + tig]);
                    afr[mi][2] = __float_as_uint(As[st][r * SMK + kb + tig + 4]);
                    afr[mi][3] = __float_as_uint(As[st][(r + 8) * SMK + kb + tig + 4]);
                }
            }
            #pragma unroll
            for (int ni = 0; ni < 4; ni++) {
                int c = wn + ni * 8 + gid;
                bfr[ni][0] = __float_as_uint(Bs[st][c * SMK + kb + tig]);
                bfr[ni][1] = __float_as_uint(Bs[st][c * SMK + kb + tig + 4]);
            }
            #pragma unroll
            for (int mi = 0; mi < 4; mi++)
                #pragma unroll
                for (int ni = 0; ni < 4; ni++)
                    mma_tf32(acc[mi][ni], afr[mi], bfr[ni]);
        }
        st ^= 1;
    }

    if constexpr (CTRANS) {
        float (*Ts)[TSP] = reinterpret_cast<float (*)[TSP]>(&As[0][0]);
        #pragma unroll
        for (int p = 0; p < 4; p++) {
            __syncthreads();
            if ((wid >> 1) == p) {
                #pragma unroll
                for (int mi = 0; mi < 4; mi++)
                    #pragma unroll
                    for (int ni = 0; ni < 4; ni++)
                        #pragma unroll
                        for (int c = 0; c < 4; c++) {
                            int rr = wm + mi * 16 + gid + ((c >= 2) ? 8 : 0);
                            int cc = ni * 8 + tig * 2 + (c & 1);
                            Ts[cc][rr] = acc[mi][ni][c];
                        }
            }
            __syncthreads();
            int nn = tid >> 3;
            int mm = (tid & 7) * 16;
            int grow = bn + p * 32 + nn;
            if (grow < N) {
                size_t base = (size_t)grow * MTOT + bm + mm;
                #pragma unroll
                for (int q = 0; q < 4; q++)
                    *reinterpret_cast<float4*>(&C[base + q * 4]) =
                        *reinterpret_cast<const float4*>(&Ts[nn][mm + q * 4]);
            }
        }
    } else {
        #pragma unroll
        for (int mi = 0; mi < 4; mi++) {
            int r = bm + wm + mi * 16 + gid;
            #pragma unroll
            for (int ni = 0; ni < 4; ni++) {
                int c = bn + wn + ni * 8 + tig * 2;
                if (c < N) {
                    float d0 = acc[mi][ni][0], d1 = acc[mi][ni][1];
                    float d2 = acc[mi][ni][2], d3 = acc[mi][ni][3];
                    if (MODE == 1) {
                        float b0 = bias[c], b1 = bias[c + 1];
                        d0 = softplusf(d0 + b0); d1 = softplusf(d1 + b1);
                        d2 = softplusf(d2 + b0); d3 = softplusf(d3 + b1);
                    }
                    if (MODE == 2) {
                        d0 = tf32r(d0); d1 = tf32r(d1);
                        d2 = tf32r(d2); d3 = tf32r(d3);
                    }
                    if (MODE == 3 && c < DTR) {
                        d0 = tf32r(d0); d1 = tf32r(d1);
                        d2 = tf32r(d2); d3 = tf32r(d3);
                    }
                    C[(size_t)r * ldc + c]           = d0;
                    C[(size_t)r * ldc + c + 1]       = d1;
                    C[(size_t)(r + 8) * ldc + c]     = d2;
                    C[(size_t)(r + 8) * ldc + c + 1] = d3;
                }
            }
        }
    }
}

// ----------------------------------------------------------------------------
// 32x32 tiled transpose: in (R x Ccols) -> out (Ccols x R). R,C % 32 == 0.
// ----------------------------------------------------------------------------
__global__ void transpose_kernel(const float* __restrict__ in,
                                 float* __restrict__ out, int R, int Ccols)
{
    __shared__ float tile[32][33];
    int c0 = blockIdx.x * 32, r0 = blockIdx.y * 32;
    int x = threadIdx.x, y = threadIdx.y;
    #pragma unroll
    for (int i = 0; i < 32; i += 8)
        tile[y + i][x] = in[(size_t)(r0 + y + i) * Ccols + c0 + x];
    __syncthreads();
    #pragma unroll
    for (int i = 0; i < 32; i += 8)
        out[(size_t)(c0 + y + i) * R + r0 + x] = tile[x][y + i];
}

// ----------------------------------------------------------------------------
// Causal depthwise conv (k=4) + SiLU. Writes full (uT) + tf32-rounded (uTr).
// ----------------------------------------------------------------------------
__global__ void conv_silu_kernel(const float* __restrict__ xzT,
                                 const float* __restrict__ cw,
                                 const float* __restrict__ cb,
                                 float* __restrict__ uT,
                                 float* __restrict__ uTr)
{
    int i = blockIdx.x * blockDim.x + threadIdx.x;
    int d = i >> 13;
    int m = i & 8191;
    int t = m & 1023;
    const float* src = xzT + (size_t)d * MTOT + m;
    float w0 = cw[d * 4 + 0], w1 = cw[d * 4 + 1];
    float w2 = cw[d * 4 + 2], w3 = cw[d * 4 + 3];
    float acc = cb[d];
    if (t >= 3) acc = fmaf(src[-3], w0, acc);
    if (t >= 2) acc = fmaf(src[-2], w1, acc);
    if (t >= 1) acc = fmaf(src[-1], w2, acc);
    acc = fmaf(src[0], w3, acc);
    float s = siluf(acc);
    uT [(size_t)d * MTOT + m] = s;
    uTr[(size_t)d * MTOT + m] = tf32r(s);
}

// ----------------------------------------------------------------------------
// Selective scan v4. Block = 128 thr (4 warps) = 8 channels of ONE batch.
// - B/C AND dt/u/z double-buffered via cp.async (no exposed DRAM latency)
// - dt/du broadcasts via smem LDS; du overwrites u slots in-place
// - y reduction: xor16+xor8 butterfly, all-lane (lane&7) store (no divergence)
// ----------------------------------------------------------------------------
__global__ void __launch_bounds__(128) ssm_scan_kernel(
    const float* __restrict__ proj,
    const float* __restrict__ dtT,
    const float* __restrict__ uT,
    const float* __restrict__ xzT,
    const float* __restrict__ A_log,
    const float* __restrict__ Dparam,
    float* __restrict__ yT)
{
    __shared__ float sBC [2][32][128];    // 32 KB
    __shared__ float sDU [2][4][6][32];   // 6 KB [st][w][dt0,dt1,u0->du0,u1->du1,z0,z1][t]
    __shared__ float pbuf[4][2][32][9];   // 9 KB

    const unsigned FULL = 0xFFFFFFFFu;
    const float L2E = 1.4426950408889634f;
    const int tid  = threadIdx.x;
    const int wid  = tid >> 5;
    const int lane = tid & 31;
    const int b  = blockIdx.y;
    const int d0 = blockIdx.x * 8 + wid * 2;
    const int d1 = d0 + 1;

    float A00 = -__expf(A_log[(size_t)d0 * NS + lane])      * L2E;
    float A01 = -__expf(A_log[(size_t)d0 * NS + lane + 32]) * L2E;
    float A10 = -__expf(A_log[(size_t)d1 * NS + lane])      * L2E;
    float A11 = -__expf(A_log[(size_t)d1 * NS + lane + 32]) * L2E;
    float D0 = Dparam[d0], D1 = Dparam[d1];

    // Per-lane fixed source rows for the DU prefetch (r1: rows 0..3, r2: 4..5)
    const int seg = (lane & 7) * 4;
    const int r1  = lane >> 3;              // 0..3
    const int r2  = 4 + (lane >> 3);        // 4..7 (only lanes<16 used)
    const float* base_dt0 = dtT + (size_t)d0 * MTOT;
    const float* base_dt1 = dtT + (size_t)d1 * MTOT;
    const float* base_u0  = uT  + (size_t)d0 * MTOT;
    const float* base_u1  = uT  + (size_t)d1 * MTOT;
    const float* base_z0  = xzT + (size_t)(DI + d0) * MTOT;
    const float* base_z1  = xzT + (size_t)(DI + d1) * MTOT;
    const float* p1 = (r1 == 0) ? base_dt0 : (r1 == 1) ? base_dt1
                    : (r1 == 2) ? base_u0  : base_u1;
    const float* p2 = (r2 == 4) ? base_z0 : base_z1;

    float h00 = 0.f, h01 = 0.f, h10 = 0.f, h11 = 0.f;

    auto issueAll = [&](int tc, int st) {
        size_t mb = (size_t)b * LL + tc;
        #pragma unroll
        for (int it = 0; it < 8; it++) {
            int s   = tid + it * 128;
            int row = s >> 5;
            int c4  = (s & 31) * 4;
            cpa16(&sBC[st][row][c4], proj + (mb + row) * PROJC + 48 + c4);
        }
        cpa16(&sDU[st][wid][r1][seg], p1 + mb + seg);
        if (lane < 16)
            cpa16(&sDU[st][wid][r2][seg], p2 + mb + seg);
        asm volatile("cp.async.commit_group;\n");
    };

    issueAll(0, 0);

    int st = 0;
    for (int tc = 0; tc < LL; tc += 32, st ^= 1) {
        const size_t mb = (size_t)b * LL + tc;

        if (tc + 32 < LL) {
            issueAll(tc + 32, st ^ 1);      // overlaps this chunk's compute
            asm volatile("cp.async.wait_group 1;\n");
        } else {
            asm volatile("cp.async.wait_group 0;\n");
        }
        __syncthreads();

        float dtv0 = sDU[st][wid][0][lane];
        float dtv1 = sDU[st][wid][1][lane];
        float uv0  = sDU[st][wid][2][lane];
        float uv1  = sDU[st][wid][3][lane];
        float zv0  = sDU[st][wid][4][lane];
        float zv1  = sDU[st][wid][5][lane];
        sDU[st][wid][2][lane] = dtv0 * uv0;   // u slots -> du (warp-private)
        sDU[st][wid][3][lane] = dtv1 * uv1;
        __syncwarp();

        #pragma unroll 8
        for (int j = 0; j < 32; j++) {
            float Bn0 = sBC[st][j][lane];
            float Bn1 = sBC[st][j][lane + 32];
            float Cn0 = sBC[st][j][64 + lane];
            float Cn1 = sBC[st][j][96 + lane];
            float dt0 = sDU[st][wid][0][j];
            float dt1 = sDU[st][wid][1][j];
            float du0 = sDU[st][wid][2][j];
            float du1 = sDU[st][wid][3][j];
            h00 = fmaf(ex2f(dt0 * A00), h00, du0 * Bn0);
            h01 = fmaf(ex2f(dt0 * A01), h01, du0 * Bn1);
            h10 = fmaf(ex2f(dt1 * A10), h10, du1 * Bn0);
            h11 = fmaf(ex2f(dt1 * A11), h11, du1 * Bn1);
            float y0 = fmaf(h00, Cn0, h01 * Cn1);
            float y1 = fmaf(h10, Cn0, h11 * Cn1);
            y0 += __shfl_xor_sync(FULL, y0, 16);
            y0 += __shfl_xor_sync(FULL, y0, 8);
            y1 += __shfl_xor_sync(FULL, y1, 16);
            y1 += __shfl_xor_sync(FULL, y1, 8);
            // lanes l, l+8, l+16, l+24 hold identical sums -> same-address
            // stores collapse; no branch divergence
            pbuf[wid][0][j][lane & 7] = y0;
            pbuf[wid][1][j][lane & 7] = y1;
        }
        __syncwarp();

        float y0f = 0.f, y1f = 0.f;
        #pragma unroll
        for (int i = 0; i < 8; i++) {
            y0f += pbuf[wid][0][lane][i];
            y1f += pbuf[wid][1][lane][i];
        }

        __syncthreads();   // buffers free before next chunk's issue

        float out0 = (y0f + uv0 * D0) * siluf(zv0);
        float out1 = (y1f + uv1 * D1) * siluf(zv1);
        yT[(size_t)d0 * MTOT + mb + lane] = tf32r(out0);
        yT[(size_t)d1 * MTOT + mb + lane] = tf32r(out1);
    }
}

// ----------------------------------------------------------------------------
// kernel_launch
// ----------------------------------------------------------------------------
extern "C" void kernel_launch(void* const* d_in, const int* in_sizes, int n_in,
                              void* d_out, int out_size)
{
    const float* x     = (const float*)d_in[0];
    const float* W_in  = (const float*)d_in[1];
    const float* cw    = (const float*)d_in[2];
    const float* cb    = (const float*)d_in[3];
    const float* W_x   = (const float*)d_in[4];
    const float* W_dt  = (const float*)d_in[5];
    const float* b_dt  = (const float*)d_in[6];
    const float* A_log = (const float*)d_in[7];
    const float* Dp    = (const float*)d_in[8];
    const float* W_out = (const float*)d_in[9];

    float *xzT, *uT, *uTr, *proj, *dtm, *dtT, *yT, *mid, *xr;
    float *win, *wx, *wdt, *wout;
    cudaGetSymbolAddress((void**)&xzT,  g_xzT);
    cudaGetSymbolAddress((void**)&uT,   g_uT);
    cudaGetSymbolAddress((void**)&uTr,  g_uTr);
    cudaGetSymbolAddress((void**)&proj, g_proj);
    cudaGetSymbolAddress((void**)&dtm,  g_dtm);
    cudaGetSymbolAddress((void**)&dtT,  g_dtT);
    cudaGetSymbolAddress((void**)&yT,   g_yT);
    cudaGetSymbolAddress((void**)&mid,  g_mid);
    cudaGetSymbolAddress((void**)&xr,   g_xr);
    cudaGetSymbolAddress((void**)&win,  g_win);
    cudaGetSymbolAddress((void**)&wx,   g_wx);
    cudaGetSymbolAddress((void**)&wdt,  g_wdt);
    cudaGetSymbolAddress((void**)&wout, g_wout);

    const dim3 tb256(256);
    const int MB = MTOT / TBM;   // 64

    // ---- tf32 pre-rounding (weights + layer-0 input), single launch ----
    round_all_kernel<<<(RQ4 + 255) / 256, tb256>>>(
        x, xr, W_in, win, W_x, wx, W_dt, wdt, W_out, wout);

    for (int l = 0; l < 2; l++) {
        const float* xin = (l == 0) ? xr : mid;   // both tf32-rounded
        float* xout = (l == 1) ? (float*)d_out : mid;

        // 1. in-proj, n-major output straight into xzT (CTRANS)
        tgemm_kernel<false, true, 0>
            <<<dim3(XZC / TBN, MB), tb256>>>(
                xin, DM, win + (size_t)l * XZC * DM, nullptr,
                xzT, 0, XZC, DM);

        // 2. conv + silu -> uT (full) + uTr (rounded)
        conv_silu_kernel<<<(DI * MTOT) / 256, tb256>>>(
            xzT, cw + (size_t)l * DI * 4, cb + (size_t)l * DI, uT, uTr);

        // 3. x-proj: proj[m,176] = u @ W_x^T ; rounds dt_r cols (<48) only
        tgemm_kernel<true, false, 3>
            <<<dim3((PROJC + TBN - 1) / TBN, MB), tb256>>>(
                uTr, 0, wx + (size_t)l * PROJC * DI, nullptr,
                proj, PROJC, PROJC, DI);

        // 4. dt: m-major + fused softplus -> dtm
        tgemm_kernel<false, false, 1>
            <<<dim3(DI / TBN, MB), tb256>>>(
                proj, PROJC, wdt + (size_t)l * DI * DTR,
                b_dt + (size_t)l * DI, dtm, DI, DI, DTR);

        // 5. transpose dt_m -> dtT (d-major)
        transpose_kernel<<<dim3(DI / 32, MTOT / 32), dim3(32, 8)>>>(
            dtm, dtT, MTOT, DI);

        // 6. selective scan + skip + gate -> yT (rounded for out-proj)
        ssm_scan_kernel<<<dim3(DI / 8, BB), dim3(128)>>>(
            proj, dtT, uT, xzT,
            A_log + (size_t)l * DI * NS, Dp + (size_t)l * DI, yT);

        // 7. out-proj: xout = y @ W_out^T ; l=0 rounds (feeds next in-proj)
        if (l == 0)
            tgemm_kernel<true, false, 2>
                <<<dim3(DM / TBN, MB), tb256>>>(
                    yT, 0, wout + (size_t)l * DM * DI, nullptr,
                    xout, DM, DM, DI);
        else
            tgemm_kernel<true, false, 0>
                <<<dim3(DM / TBN, MB), tb256>>>(
                    yT, 0, wout + (size_t)l * DM * DI, nullptr,
                    xout, DM, DM, DI);
    }
}

// round 12
// speedup vs baseline: 1.1374x; 1.0076x over previous
#include <cuda_runtime.h>
#include <cstdint>

// ----------------------------------------------------------------------------
// Problem constants (fixed shapes)
// ----------------------------------------------------------------------------
constexpr int BB   = 8;
constexpr int LL   = 1024;
constexpr int DM   = 768;
constexpr int DI   = 1536;
constexpr int NS   = 64;
constexpr int DTR  = 48;
constexpr int MTOT = BB * LL;        // 8192
constexpr int XZC  = 2 * DI;         // 3072
constexpr int PROJC = DTR + 2 * NS;  // 176

// ----------------------------------------------------------------------------
// Scratch (device globals; no allocation allowed)
// ----------------------------------------------------------------------------
__device__ float g_xzT [MTOT * XZC];   // (3072, m) in-proj output, d-major
__device__ float g_uT  [MTOT * DI];    // (d, m) conv+silu, full precision
__device__ float g_uTr [MTOT * DI];    // (d, m) conv+silu, tf32-rounded
__device__ float g_proj[MTOT * PROJC]; // (m, 176) [dt_r(tf32) | B | C]
__device__ float g_dtT [MTOT * DI];    // (d, m) RAW dt (pre-softplus, +bias)
__device__ float g_yT  [MTOT * DI];    // (d, m) scan out, tf32-rounded
__device__ float g_mid [MTOT * DM];    // inter-layer act (tf32-rounded)
__device__ float g_xr  [MTOT * DM];    // layer-0 input, tf32-rounded

constexpr int WIN_SZ  = 2 * XZC * DM;
constexpr int WX_SZ   = 2 * PROJC * DI;
constexpr int WDT_SZ  = 2 * DI * DTR;
constexpr int WOUT_SZ = 2 * DM * DI;
__device__ float g_win [WIN_SZ];
__device__ float g_wx  [WX_SZ];
__device__ float g_wdt [WDT_SZ];
__device__ float g_wout[WOUT_SZ];

// ----------------------------------------------------------------------------
// Helpers
// ----------------------------------------------------------------------------
__device__ __forceinline__ float siluf(float x) {
    return x * (1.0f / (1.0f + __expf(-x)));
}
__device__ __forceinline__ float softplusf(float x) {
    return fmaxf(x, 0.0f) + log1pf(__expf(-fabsf(x)));
}
__device__ __forceinline__ float tf32r(float x) {
    uint32_t r;
    asm("cvt.rna.tf32.f32 %0, %1;" : "=r"(r) : "f"(x));
    return __uint_as_float(r);
}
__device__ __forceinline__ float ex2f(float x) {   // MUFU EX2
    float r;
    asm("ex2.approx.f32 %0, %1;" : "=f"(r) : "f"(x));
    return r;
}
__device__ __forceinline__ void mma_tf32(float* d, const uint32_t* a,
                                         const uint32_t* b) {
    asm volatile(
        "mma.sync.aligned.m16n8k8.row.col.f32.tf32.tf32.f32 "
        "{%0,%1,%2,%3}, {%4,%5,%6,%7}, {%8,%9}, {%0,%1,%2,%3};\n"
        : "+f"(d[0]), "+f"(d[1]), "+f"(d[2]), "+f"(d[3])
        : "r"(a[0]), "r"(a[1]), "r"(a[2]), "r"(a[3]), "r"(b[0]), "r"(b[1]));
}
__device__ __forceinline__ void cpa16(float* smem, const float* g) {
    uint32_t dst = (uint32_t)__cvta_generic_to_shared(smem);
    asm volatile("cp.async.ca.shared.global [%0], [%1], 16;\n"
                 :: "r"(dst), "l"(g));
}
__device__ __forceinline__ void cpa16z(float* smem, const float* g, int sz) {
    uint32_t dst = (uint32_t)__cvta_generic_to_shared(smem);
    asm volatile("cp.async.ca.shared.global [%0], [%1], 16, %2;\n"
                 :: "r"(dst), "l"(g), "r"(sz));
}

// ----------------------------------------------------------------------------
// Merged tf32 rounding kernel: 5 arrays in one launch (segment walk).
// ----------------------------------------------------------------------------
constexpr int RQ0 = (MTOT * DM) / 4;
constexpr int RQ1 = RQ0 + WIN_SZ / 4;
constexpr int RQ2 = RQ1 + WX_SZ / 4;
constexpr int RQ3 = RQ2 + WDT_SZ / 4;
constexpr int RQ4 = RQ3 + WOUT_SZ / 4;

__global__ void round_all_kernel(
    const float* __restrict__ x,    float* __restrict__ xr,
    const float* __restrict__ Wi,   float* __restrict__ wi,
    const float* __restrict__ Wx,   float* __restrict__ wx,
    const float* __restrict__ Wdt,  float* __restrict__ wdt,
    const float* __restrict__ Wo,   float* __restrict__ wo)
{
    int q = blockIdx.x * blockDim.x + threadIdx.x;
    if (q >= RQ4) return;
    const float* in; float* out; int base;
    if      (q < RQ0) { in = x;   out = xr;  base = 0;   }
    else if (q < RQ1) { in = Wi;  out = wi;  base = RQ0; }
    else if (q < RQ2) { in = Wx;  out = wx;  base = RQ1; }
    else if (q < RQ3) { in = Wdt; out = wdt; base = RQ2; }
    else              { in = Wo;  out = wo;  base = RQ3; }
    int i = (q - base) * 4;
    float4 v = *reinterpret_cast<const float4*>(in + i);
    v.x = tf32r(v.x); v.y = tf32r(v.y);
    v.z = tf32r(v.z); v.w = tf32r(v.w);
    *reinterpret_cast<float4*>(out + i) = v;
}

// ============================================================================
// Tensor-core tf32 GEMM, cp.async 2-stage pipeline. Inputs PRE-ROUNDED tf32.
//   C[m,n] = sum_k A[m,k] * W[n,k]  (W row-major N x K)
//   ATRANS: A stored K x MTOT (d-major);  else A m-major with lda.
//   CTRANS: C stored N x MTOT (n-major) via smem-staged transpose (aliases As)
//   MODE: 0 none | 1 softplus(+bias) | 2 round-all | 3 round cols < DTR
//         4 bias-add only (CTRANS path: raw dt for scan-side softplus)
// ============================================================================
constexpr int TBM = 128, TBN = 128, TBK = 16;
constexpr int SKM = 136;
constexpr int SMK = 20;
constexpr int ASTG = 2560;
constexpr int BSTG = 2560;
constexpr int TSP  = 136;

template<bool ATRANS, bool CTRANS, int MODE>
__global__ void __launch_bounds__(256, 2) tgemm_kernel(
    const float* __restrict__ A, int lda,
    const float* __restrict__ W,
    const float* __restrict__ bias,
    float* __restrict__ C, int ldc,
    int N, int K)
{
    __shared__ float As[2][ASTG];
    __shared__ float Bs[2][BSTG];

    const int tid  = threadIdx.x;
    const int bm   = blockIdx.y * TBM;
    const int bn   = blockIdx.x * TBN;
    const int wid  = tid >> 5;
    const int lane = tid & 31;
    const int wm   = (wid & 1) * 64;
    const int wn   = (wid >> 1) * 32;
    const int gid  = lane >> 2;
    const int tig  = lane & 3;

    float acc[4][4][4];
    #pragma unroll
    for (int i = 0; i < 4; i++)
        #pragma unroll
        for (int j = 0; j < 4; j++)
            #pragma unroll
            for (int c = 0; c < 4; c++) acc[i][j][c] = 0.0f;

    auto issue_load = [&](int k0, int st) {
        #pragma unroll
        for (int itr = 0; itr < 2; itr++) {
            int s = tid + itr * 256;
            if (ATRANS) {
                int kk = s >> 5, mc = (s & 31) * 4;
                cpa16(&As[st][kk * SKM + mc],
                      A + (size_t)(k0 + kk) * MTOT + bm + mc);
            } else {
                int row = s >> 2, kc = (s & 3) * 4;
                cpa16(&As[st][row * SMK + kc],
                      A + (size_t)(bm + row) * lda + k0 + kc);
            }
            int n = s >> 2, kc = (s & 3) * 4;
            cpa16z(&Bs[st][n * SMK + kc],
                   W + (size_t)(bn + n) * K + k0 + kc,
                   (bn + n < N) ? 16 : 0);
        }
        asm volatile("cp.async.commit_group;\n");
    };

    issue_load(0, 0);

    const int kt = K / TBK;
    int st = 0;
    for (int it = 0; it < kt; it++) {
        asm volatile("cp.async.wait_group 0;\n");
        __syncthreads();
        if (it + 1 < kt) issue_load((it + 1) * TBK, st ^ 1);

        #pragma unroll
        for (int ks = 0; ks < 2; ks++) {
            const int kb = ks * 8;
            uint32_t afr[4][4], bfr[4][2];
            #pragma unroll
            for (int mi = 0; mi < 4; mi++) {
                int r = wm + mi * 16 + gid;
                if (ATRANS) {
                    afr[mi][0] = __float_as_uint(As[st][(kb + tig) * SKM + r]);
                    afr[mi][1] = __float_as_uint(As[st][(kb + tig) * SKM + r + 8]);
                    afr[mi][2] = __float_as_uint(As[st][(kb + tig + 4) * SKM + r]);
                    afr[mi][3] = __float_as_uint(As[st][(kb + tig + 4) * SKM + r + 8]);
                } else {
                    afr[mi][0] = __float_as_uint(As[st][r * SMK + kb + tig]);
                    afr[mi][1] = __float_as_uint(As[st][(r + 8) * SMK + kb + tig]);
                    afr[mi][2] = __float_as_uint(As[st][r * SMK + kb + tig + 4]);
                    afr[mi][3] = __float_as_uint(As[st][(r + 8) * SMK + kb + tig + 4]);
                }
            }
            #pragma unroll
            for (int ni = 0; ni < 4; ni++) {
                int c = wn + ni * 8 + gid;
                bfr[ni][0] = __float_as_uint(Bs[st][c * SMK + kb + tig]);
                bfr[ni][1] = __float_as_uint(Bs[st][c * SMK + kb + tig + 4]);
            }
            #pragma unroll
            for (int mi = 0; mi < 4; mi++)
                #pragma unroll
                for (int ni = 0; ni < 4; ni++)
                    mma_tf32(acc[mi][ni], afr[mi], bfr[ni]);
        }
        st ^= 1;
    }

    if constexpr (CTRANS) {
        float (*Ts)[TSP] = reinterpret_cast<float (*)[TSP]>(&As[0][0]);
        #pragma unroll
        for (int p = 0; p < 4; p++) {
            __syncthreads();
            if ((wid >> 1) == p) {
                #pragma unroll
                for (int mi = 0; mi < 4; mi++)
                    #pragma unroll
                    for (int ni = 0; ni < 4; ni++)
                        #pragma unroll
                        for (int c = 0; c < 4; c++) {
                            int rr = wm + mi * 16 + gid + ((c >= 2) ? 8 : 0);
                            int cc = ni * 8 + tig * 2 + (c & 1);
                            float v = acc[mi][ni][c];
                            if (MODE == 4)
                                v += bias[bn + p * 32 + cc];
                            Ts[cc][rr] = v;
                        }
            }
            __syncthreads();
            int nn = tid >> 3;
            int mm = (tid & 7) * 16;
            int grow = bn + p * 32 + nn;
            if (grow < N) {
                size_t base = (size_t)grow * MTOT + bm + mm;
                #pragma unroll
                for (int q = 0; q < 4; q++)
                    *reinterpret_cast<float4*>(&C[base + q * 4]) =
                        *reinterpret_cast<const float4*>(&Ts[nn][mm + q * 4]);
            }
        }
    } else {
        #pragma unroll
        for (int mi = 0; mi < 4; mi++) {
            int r = bm + wm + mi * 16 + gid;
            #pragma unroll
            for (int ni = 0; ni < 4; ni++) {
                int c = bn + wn + ni * 8 + tig * 2;
                if (c < N) {
                    float d0 = acc[mi][ni][0], d1 = acc[mi][ni][1];
                    float d2 = acc[mi][ni][2], d3 = acc[mi][ni][3];
                    if (MODE == 1) {
                        float b0 = bias[c], b1 = bias[c + 1];
                        d0 = softplusf(d0 + b0); d1 = softplusf(d1 + b1);
                        d2 = softplusf(d2 + b0); d3 = softplusf(d3 + b1);
                    }
                    if (MODE == 2) {
                        d0 = tf32r(d0); d1 = tf32r(d1);
                        d2 = tf32r(d2); d3 = tf32r(d3);
                    }
                    if (MODE == 3 && c < DTR) {
                        d0 = tf32r(d0); d1 = tf32r(d1);
                        d2 = tf32r(d2); d3 = tf32r(d3);
                    }
                    C[(size_t)r * ldc + c]           = d0;
                    C[(size_t)r * ldc + c + 1]       = d1;
                    C[(size_t)(r + 8) * ldc + c]     = d2;
                    C[(size_t)(r + 8) * ldc + c + 1] = d3;
                }
            }
        }
    }
}

// ----------------------------------------------------------------------------
// Causal depthwise conv (k=4) + SiLU. Writes full (uT) + tf32-rounded (uTr).
// ----------------------------------------------------------------------------
__global__ void conv_silu_kernel(const float* __restrict__ xzT,
                                 const float* __restrict__ cw,
                                 const float* __restrict__ cb,
                                 float* __restrict__ uT,
                                 float* __restrict__ uTr)
{
    int i = blockIdx.x * blockDim.x + threadIdx.x;
    int d = i >> 13;
    int m = i & 8191;
    int t = m & 1023;
    const float* src = xzT + (size_t)d * MTOT + m;
    float w0 = cw[d * 4 + 0], w1 = cw[d * 4 + 1];
    float w2 = cw[d * 4 + 2], w3 = cw[d * 4 + 3];
    float acc = cb[d];
    if (t >= 3) acc = fmaf(src[-3], w0, acc);
    if (t >= 2) acc = fmaf(src[-2], w1, acc);
    if (t >= 1) acc = fmaf(src[-1], w2, acc);
    acc = fmaf(src[0], w3, acc);
    float s = siluf(acc);
    uT [(size_t)d * MTOT + m] = s;
    uTr[(size_t)d * MTOT + m] = tf32r(s);
}

// ----------------------------------------------------------------------------
// Selective scan v5. Block = 128 thr (4 warps) = 8 channels of ONE batch.
// - B/C AND rawdt/u/z double-buffered via cp.async
// - softplus applied IN-SCAN (2 per lane per chunk; GEMM supplies raw dt+bias)
// - dt/du broadcasts via smem LDS; butterfly+smem reduction
// ----------------------------------------------------------------------------
__global__ void __launch_bounds__(128) ssm_scan_kernel(
    const float* __restrict__ proj,
    const float* __restrict__ dtT,    // RAW dt (pre-softplus, bias added)
    const float* __restrict__ uT,
    const float* __restrict__ xzT,
    const float* __restrict__ A_log,
    const float* __restrict__ Dparam,
    float* __restrict__ yT)
{
    __shared__ float sBC [2][32][128];    // 32 KB
    __shared__ float sDU [2][4][6][32];   // 6 KB
    __shared__ float pbuf[4][2][32][9];   // 9 KB

    const unsigned FULL = 0xFFFFFFFFu;
    const float L2E = 1.4426950408889634f;
    const int tid  = threadIdx.x;
    const int wid  = tid >> 5;
    const int lane = tid & 31;
    const int b  = blockIdx.y;
    const int d0 = blockIdx.x * 8 + wid * 2;
    const int d1 = d0 + 1;

    float A00 = -__expf(A_log[(size_t)d0 * NS + lane])      * L2E;
    float A01 = -__expf(A_log[(size_t)d0 * NS + lane + 32]) * L2E;
    float A10 = -__expf(A_log[(size_t)d1 * NS + lane])      * L2E;
    float A11 = -__expf(A_log[(size_t)d1 * NS + lane + 32]) * L2E;
    float D0 = Dparam[d0], D1 = Dparam[d1];

    const int seg = (lane & 7) * 4;
    const int r1  = lane >> 3;
    const int r2  = 4 + (lane >> 3);
    const float* base_dt0 = dtT + (size_t)d0 * MTOT;
    const float* base_dt1 = dtT + (size_t)d1 * MTOT;
    const float* base_u0  = uT  + (size_t)d0 * MTOT;
    const float* base_u1  = uT  + (size_t)d1 * MTOT;
    const float* base_z0  = xzT + (size_t)(DI + d0) * MTOT;
    const float* base_z1  = xzT + (size_t)(DI + d1) * MTOT;
    const float* p1 = (r1 == 0) ? base_dt0 : (r1 == 1) ? base_dt1
                    : (r1 == 2) ? base_u0  : base_u1;
    const float* p2 = (r2 == 4) ? base_z0 : base_z1;

    float h00 = 0.f, h01 = 0.f, h10 = 0.f, h11 = 0.f;

    auto issueAll = [&](int tc, int st) {
        size_t mb = (size_t)b * LL + tc;
        #pragma unroll
        for (int it = 0; it < 8; it++) {
            int s   = tid + it * 128;
            int row = s >> 5;
            int c4  = (s & 31) * 4;
            cpa16(&sBC[st][row][c4], proj + (mb + row) * PROJC + 48 + c4);
        }
        cpa16(&sDU[st][wid][r1][seg], p1 + mb + seg);
        if (lane < 16)
            cpa16(&sDU[st][wid][r2][seg], p2 + mb + seg);
        asm volatile("cp.async.commit_group;\n");
    };

    issueAll(0, 0);

    int st = 0;
    for (int tc = 0; tc < LL; tc += 32, st ^= 1) {
        const size_t mb = (size_t)b * LL + tc;

        if (tc + 32 < LL) {
            issueAll(tc + 32, st ^ 1);
            asm volatile("cp.async.wait_group 1;\n");
        } else {
            asm volatile("cp.async.wait_group 0;\n");
        }
        __syncthreads();

        float raw0 = sDU[st][wid][0][lane];
        float raw1 = sDU[st][wid][1][lane];
        float uv0  = sDU[st][wid][2][lane];
        float uv1  = sDU[st][wid][3][lane];
        float zv0  = sDU[st][wid][4][lane];
        float zv1  = sDU[st][wid][5][lane];
        float sp0  = softplusf(raw0);        // softplus moved into scan
        float sp1  = softplusf(raw1);
        sDU[st][wid][0][lane] = sp0;
        sDU[st][wid][1][lane] = sp1;
        sDU[st][wid][2][lane] = sp0 * uv0;   // u slots -> du
        sDU[st][wid][3][lane] = sp1 * uv1;
        __syncwarp();

        #pragma unroll 8
        for (int j = 0; j < 32; j++) {
            float Bn0 = sBC[st][j][lane];
            float Bn1 = sBC[st][j][lane + 32];
            float Cn0 = sBC[st][j][64 + lane];
            float Cn1 = sBC[st][j][96 + lane];
            float dt0 = sDU[st][wid][0][j];
            float dt1 = sDU[st][wid][1][j];
            float du0 = sDU[st][wid][2][j];
            float du1 = sDU[st][wid][3][j];
            h00 = fmaf(ex2f(dt0 * A00), h00, du0 * Bn0);
            h01 = fmaf(ex2f(dt0 * A01), h01, du0 * Bn1);
            h10 = fmaf(ex2f(dt1 * A10), h10, du1 * Bn0);
            h11 = fmaf(ex2f(dt1 * A11), h11, du1 * Bn1);
            float y0 = fmaf(h00, Cn0, h01 * Cn1);
            float y1 = fmaf(h10, Cn0, h11 * Cn1);
            y0 += __shfl_xor_sync(FULL, y0, 16);
            y0 += __shfl_xor_sync(FULL, y0, 8);
            y1 += __shfl_xor_sync(FULL, y1, 16);
            y1 += __shfl_xor_sync(FULL, y1, 8);
            pbuf[wid][0][j][lane & 7] = y0;
            pbuf[wid][1][j][lane & 7] = y1;
        }
        __syncwarp();

        float y0f = 0.f, y1f = 0.f;
        #pragma unroll
        for (int i = 0; i < 8; i++) {
            y0f += pbuf[wid][0][lane][i];
            y1f += pbuf[wid][1][lane][i];
        }

        __syncthreads();

        float out0 = (y0f + uv0 * D0) * siluf(zv0);
        float out1 = (y1f + uv1 * D1) * siluf(zv1);
        yT[(size_t)d0 * MTOT + mb + lane] = tf32r(out0);
        yT[(size_t)d1 * MTOT + mb + lane] = tf32r(out1);
    }
}

// ----------------------------------------------------------------------------
// kernel_launch
// ----------------------------------------------------------------------------
extern "C" void kernel_launch(void* const* d_in, const int* in_sizes, int n_in,
                              void* d_out, int out_size)
{
    const float* x     = (const float*)d_in[0];
    const float* W_in  = (const float*)d_in[1];
    const float* cw    = (const float*)d_in[2];
    const float* cb    = (const float*)d_in[3];
    const float* W_x   = (const float*)d_in[4];
    const float* W_dt  = (const float*)d_in[5];
    const float* b_dt  = (const float*)d_in[6];
    const float* A_log = (const float*)d_in[7];
    const float* Dp    = (const float*)d_in[8];
    const float* W_out = (const float*)d_in[9];

    float *xzT, *uT, *uTr, *proj, *dtT, *yT, *mid, *xr;
    float *win, *wx, *wdt, *wout;
    cudaGetSymbolAddress((void**)&xzT,  g_xzT);
    cudaGetSymbolAddress((void**)&uT,   g_uT);
    cudaGetSymbolAddress((void**)&uTr,  g_uTr);
    cudaGetSymbolAddress((void**)&proj, g_proj);
    cudaGetSymbolAddress((void**)&dtT,  g_dtT);
    cudaGetSymbolAddress((void**)&yT,   g_yT);
    cudaGetSymbolAddress((void**)&mid,  g_mid);
    cudaGetSymbolAddress((void**)&xr,   g_xr);
    cudaGetSymbolAddress((void**)&win,  g_win);
    cudaGetSymbolAddress((void**)&wx,   g_wx);
    cudaGetSymbolAddress((void**)&wdt,  g_wdt);
    cudaGetSymbolAddress((void**)&wout, g_wout);

    const dim3 tb256(256);
    const int MB = MTOT / TBM;   // 64

    // ---- tf32 pre-rounding (weights + layer-0 input), single launch ----
    round_all_kernel<<<(RQ4 + 255) / 256, tb256>>>(
        x, xr, W_in, win, W_x, wx, W_dt, wdt, W_out, wout);

    for (int l = 0; l < 2; l++) {
        const float* xin = (l == 0) ? xr : mid;
        float* xout = (l == 1) ? (float*)d_out : mid;

        // 1. in-proj, n-major output straight into xzT (CTRANS)
        tgemm_kernel<false, true, 0>
            <<<dim3(XZC / TBN, MB), tb256>>>(
                xin, DM, win + (size_t)l * XZC * DM, nullptr,
                xzT, 0, XZC, DM);

        // 2. conv + silu -> uT (full) + uTr (rounded)
        conv_silu_kernel<<<(DI * MTOT) / 256, tb256>>>(
            xzT, cw + (size_t)l * DI * 4, cb + (size_t)l * DI, uT, uTr);

        // 3. x-proj: proj[m,176] = u @ W_x^T ; rounds dt_r cols (<48) only
        tgemm_kernel<true, false, 3>
            <<<dim3((PROJC + TBN - 1) / TBN, MB), tb256>>>(
                uTr, 0, wx + (size_t)l * PROJC * DI, nullptr,
                proj, PROJC, PROJC, DI);

        // 4. dt raw (+bias) n-major straight into dtT (CTRANS, MODE 4)
        tgemm_kernel<false, true, 4>
            <<<dim3(DI / TBN, MB), tb256>>>(
                proj, PROJC, wdt + (size_t)l * DI * DTR,
                b_dt + (size_t)l * DI, dtT, 0, DI, DTR);

        // 5. selective scan (softplus fused) + skip + gate -> yT
        ssm_scan_kernel<<<dim3(DI / 8, BB), dim3(128)>>>(
            proj, dtT, uT, xzT,
            A_log + (size_t)l * DI * NS, Dp + (size_t)l * DI, yT);

        // 6. out-proj: xout = y @ W_out^T ; l=0 rounds (feeds next in-proj)
        if (l == 0)
            tgemm_kernel<true, false, 2>
                <<<dim3(DM / TBN, MB), tb256>>>(
                    yT, 0, wout + (size_t)l * DM * DI, nullptr,
                    xout, DM, DM, DI);
        else
            tgemm_kernel<true, false, 0>
                <<<dim3(DM / TBN, MB), tb256>>>(
                    yT, 0, wout + (size_t)l * DM * DI, nullptr,
                    xout, DM, DM, DI);
    }
}

// round 13
// speedup vs baseline: 1.1504x; 1.0114x over previous
#include <cuda_runtime.h>
#include <cstdint>

// ----------------------------------------------------------------------------
// Problem constants (fixed shapes)
// ----------------------------------------------------------------------------
constexpr int BB   = 8;
constexpr int LL   = 1024;
constexpr int DM   = 768;
constexpr int DI   = 1536;
constexpr int NS   = 64;
constexpr int DTR  = 48;
constexpr int MTOT = BB * LL;        // 8192
constexpr int XZC  = 2 * DI;         // 3072
constexpr int PROJC = DTR + 2 * NS;  // 176

// ----------------------------------------------------------------------------
// Scratch (device globals; no allocation allowed)
// ----------------------------------------------------------------------------
__device__ float g_xzT [MTOT * XZC];   // (3072, m) in-proj output, d-major
__device__ float g_uT  [MTOT * DI];    // (d, m) conv+silu, full precision
__device__ float g_uTr [MTOT * DI];    // (d, m) conv+silu, tf32-rounded
__device__ float g_proj[MTOT * PROJC]; // (m, 176) [dt_r(tf32) | B | C]
__device__ float g_dtT [MTOT * DI];    // (d, m) RAW dt (pre-softplus, +bias)
__device__ float g_yT  [MTOT * DI];    // (d, m) scan out, tf32-rounded
__device__ float g_mid [MTOT * DM];    // inter-layer act (tf32-rounded)
__device__ float g_xr  [MTOT * DM];    // layer-0 input, tf32-rounded

constexpr int WIN_SZ  = 2 * XZC * DM;
constexpr int WX_SZ   = 2 * PROJC * DI;
constexpr int WDT_SZ  = 2 * DI * DTR;
constexpr int WOUT_SZ = 2 * DM * DI;
__device__ float g_win [WIN_SZ];
__device__ float g_wx  [WX_SZ];
__device__ float g_wdt [WDT_SZ];
__device__ float g_wout[WOUT_SZ];

// ----------------------------------------------------------------------------
// Helpers
// ----------------------------------------------------------------------------
__device__ __forceinline__ float siluf(float x) {
    return x * (1.0f / (1.0f + __expf(-x)));
}
__device__ __forceinline__ float softplusf(float x) {
    return fmaxf(x, 0.0f) + log1pf(__expf(-fabsf(x)));
}
__device__ __forceinline__ float tf32r(float x) {
    uint32_t r;
    asm("cvt.rna.tf32.f32 %0, %1;" : "=r"(r) : "f"(x));
    return __uint_as_float(r);
}
__device__ __forceinline__ float ex2f(float x) {   // MUFU EX2
    float r;
    asm("ex2.approx.f32 %0, %1;" : "=f"(r) : "f"(x));
    return r;
}
__device__ __forceinline__ void mma_tf32(float* d, const uint32_t* a,
                                         const uint32_t* b) {
    asm volatile(
        "mma.sync.aligned.m16n8k8.row.col.f32.tf32.tf32.f32 "
        "{%0,%1,%2,%3}, {%4,%5,%6,%7}, {%8,%9}, {%0,%1,%2,%3};\n"
        : "+f"(d[0]), "+f"(d[1]), "+f"(d[2]), "+f"(d[3])
        : "r"(a[0]), "r"(a[1]), "r"(a[2]), "r"(a[3]), "r"(b[0]), "r"(b[1]));
}
__device__ __forceinline__ void cpa16(float* smem, const float* g) {
    uint32_t dst = (uint32_t)__cvta_generic_to_shared(smem);
    asm volatile("cp.async.ca.shared.global [%0], [%1], 16;\n"
                 :: "r"(dst), "l"(g));
}
__device__ __forceinline__ void cpa16z(float* smem, const float* g, int sz) {
    uint32_t dst = (uint32_t)__cvta_generic_to_shared(smem);
    asm volatile("cp.async.ca.shared.global [%0], [%1], 16, %2;\n"
                 :: "r"(dst), "l"(g), "r"(sz));
}

// ----------------------------------------------------------------------------
// Merged tf32 rounding kernel: 5 arrays in one launch (segment walk).
// ----------------------------------------------------------------------------
constexpr int RQ0 = (MTOT * DM) / 4;
constexpr int RQ1 = RQ0 + WIN_SZ / 4;
constexpr int RQ2 = RQ1 + WX_SZ / 4;
constexpr int RQ3 = RQ2 + WDT_SZ / 4;
constexpr int RQ4 = RQ3 + WOUT_SZ / 4;

__global__ void round_all_kernel(
    const float* __restrict__ x,    float* __restrict__ xr,
    const float* __restrict__ Wi,   float* __restrict__ wi,
    const float* __restrict__ Wx,   float* __restrict__ wx,
    const float* __restrict__ Wdt,  float* __restrict__ wdt,
    const float* __restrict__ Wo,   float* __restrict__ wo)
{
    int q = blockIdx.x * blockDim.x + threadIdx.x;
    if (q >= RQ4) return;
    const float* in; float* out; int base;
    if      (q < RQ0) { in = x;   out = xr;  base = 0;   }
    else if (q < RQ1) { in = Wi;  out = wi;  base = RQ0; }
    else if (q < RQ2) { in = Wx;  out = wx;  base = RQ1; }
    else if (q < RQ3) { in = Wdt; out = wdt; base = RQ2; }
    else              { in = Wo;  out = wo;  base = RQ3; }
    int i = (q - base) * 4;
    float4 v = *reinterpret_cast<const float4*>(in + i);
    v.x = tf32r(v.x); v.y = tf32r(v.y);
    v.z = tf32r(v.z); v.w = tf32r(v.w);
    *reinterpret_cast<float4*>(out + i) = v;
}

// ============================================================================
// Tensor-core tf32 GEMM, cp.async 2-stage pipeline. Inputs PRE-ROUNDED tf32.
//   C[m,n] = sum_k A[m,k] * W[n,k]  (W row-major N x K)
//   ATRANS: A stored K x MTOT (d-major);  else A m-major with lda.
//   CTRANS: C stored N x MTOT (n-major) via smem-staged transpose (aliases As)
//   MODE: 0 none | 1 softplus(+bias) | 2 round-all | 3 round cols < DTR
//         4 bias-add only (CTRANS path: raw dt for scan-side softplus)
// ============================================================================
constexpr int TBM = 128, TBN = 128, TBK = 16;
constexpr int SKM = 136;
constexpr int SMK = 20;
constexpr int ASTG = 2560;
constexpr int BSTG = 2560;
constexpr int TSP  = 136;

template<bool ATRANS, bool CTRANS, int MODE>
__global__ void __launch_bounds__(256, 2) tgemm_kernel(
    const float* __restrict__ A, int lda,
    const float* __restrict__ W,
    const float* __restrict__ bias,
    float* __restrict__ C, int ldc,
    int N, int K)
{
    __shared__ float As[2][ASTG];
    __shared__ float Bs[2][BSTG];

    const int tid  = threadIdx.x;
    const int bm   = blockIdx.y * TBM;
    const int bn   = blockIdx.x * TBN;
    const int wid  = tid >> 5;
    const int lane = tid & 31;
    const int wm   = (wid & 1) * 64;
    const int wn   = (wid >> 1) * 32;
    const int gid  = lane >> 2;
    const int tig  = lane & 3;

    float acc[4][4][4];
    #pragma unroll
    for (int i = 0; i < 4; i++)
        #pragma unroll
        for (int j = 0; j < 4; j++)
            #pragma unroll
            for (int c = 0; c < 4; c++) acc[i][j][c] = 0.0f;

    auto issue_load = [&](int k0, int st) {
        #pragma unroll
        for (int itr = 0; itr < 2; itr++) {
            int s = tid + itr * 256;
            if (ATRANS) {
                int kk = s >> 5, mc = (s & 31) * 4;
                cpa16(&As[st][kk * SKM + mc],
                      A + (size_t)(k0 + kk) * MTOT + bm + mc);
            } else {
                int row = s >> 2, kc = (s & 3) * 4;
                cpa16(&As[st][row * SMK + kc],
                      A + (size_t)(bm + row) * lda + k0 + kc);
            }
            int n = s >> 2, kc = (s & 3) * 4;
            cpa16z(&Bs[st][n * SMK + kc],
                   W + (size_t)(bn + n) * K + k0 + kc,
                   (bn + n < N) ? 16 : 0);
        }
        asm volatile("cp.async.commit_group;\n");
    };

    issue_load(0, 0);

    const int kt = K / TBK;
    int st = 0;
    for (int it = 0; it < kt; it++) {
        asm volatile("cp.async.wait_group 0;\n");
        __syncthreads();
        if (it + 1 < kt) issue_load((it + 1) * TBK, st ^ 1);

        #pragma unroll
        for (int ks = 0; ks < 2; ks++) {
            const int kb = ks * 8;
            uint32_t afr[4][4], bfr[4][2];
            #pragma unroll
            for (int mi = 0; mi < 4; mi++) {
                int r = wm + mi * 16 + gid;
                if (ATRANS) {
                    afr[mi][0] = __float_as_uint(As[st][(kb + tig) * SKM + r]);
                    afr[mi][1] = __float_as_uint(As[st][(kb + tig) * SKM + r + 8]);
                    afr[mi][2] = __float_as_uint(As[st][(kb + tig + 4) * SKM + r]);
                    afr[mi][3] = __float_as_uint(As[st][(kb + tig + 4) * SKM + r + 8]);
                } else {
                    afr[mi][0] = __float_as_uint(As[st][r * SMK + kb + tig]);
                    afr[mi][1] = __float_as_uint(As[st][(r + 8) * SMK + kb + tig]);
                    afr[mi][2] = __float_as_uint(As[st][r * SMK + kb + tig + 4]);
                    afr[mi][3] = __float_as_uint(As[st][(r + 8) * SMK + kb + tig + 4]);
                }
            }
            #pragma unroll
            for (int ni = 0; ni < 4; ni++) {
                int c = wn + ni * 8 + gid;
                bfr[ni][0] = __float_as_uint(Bs[st][c * SMK + kb + tig]);
                bfr[ni][1] = __float_as_uint(Bs[st][c * SMK + kb + tig + 4]);
            }
            #pragma unroll
            for (int mi = 0; mi < 4; mi++)
                #pragma unroll
                for (int ni = 0; ni < 4; ni++)
                    mma_tf32(acc[mi][ni], afr[mi], bfr[ni]);
        }
        st ^= 1;
    }

    if constexpr (CTRANS) {
        float (*Ts)[TSP] = reinterpret_cast<float (*)[TSP]>(&As[0][0]);
        #pragma unroll
        for (int p = 0; p < 4; p++) {
            __syncthreads();
            if ((wid >> 1) == p) {
                #pragma unroll
                for (int mi = 0; mi < 4; mi++)
                    #pragma unroll
                    for (int ni = 0; ni < 4; ni++)
                        #pragma unroll
                        for (int c = 0; c < 4; c++) {
                            int rr = wm + mi * 16 + gid + ((c >= 2) ? 8 : 0);
                            int cc = ni * 8 + tig * 2 + (c & 1);
                            float v = acc[mi][ni][c];
                            if (MODE == 4)
                                v += bias[bn + p * 32 + cc];
                            Ts[cc][rr] = v;
                        }
            }
            __syncthreads();
            int nn = tid >> 3;
            int mm = (tid & 7) * 16;
            int grow = bn + p * 32 + nn;
            if (grow < N) {
                size_t base = (size_t)grow * MTOT + bm + mm;
                #pragma unroll
                for (int q = 0; q < 4; q++)
                    *reinterpret_cast<float4*>(&C[base + q * 4]) =
                        *reinterpret_cast<const float4*>(&Ts[nn][mm + q * 4]);
            }
        }
    } else {
        #pragma unroll
        for (int mi = 0; mi < 4; mi++) {
            int r = bm + wm + mi * 16 + gid;
            #pragma unroll
            for (int ni = 0; ni < 4; ni++) {
                int c = bn + wn + ni * 8 + tig * 2;
                if (c < N) {
                    float d0 = acc[mi][ni][0], d1 = acc[mi][ni][1];
                    float d2 = acc[mi][ni][2], d3 = acc[mi][ni][3];
                    if (MODE == 1) {
                        float b0 = bias[c], b1 = bias[c + 1];
                        d0 = softplusf(d0 + b0); d1 = softplusf(d1 + b1);
                        d2 = softplusf(d2 + b0); d3 = softplusf(d3 + b1);
                    }
                    if (MODE == 2) {
                        d0 = tf32r(d0); d1 = tf32r(d1);
                        d2 = tf32r(d2); d3 = tf32r(d3);
                    }
                    if (MODE == 3 && c < DTR) {
                        d0 = tf32r(d0); d1 = tf32r(d1);
                        d2 = tf32r(d2); d3 = tf32r(d3);
                    }
                    C[(size_t)r * ldc + c]           = d0;
                    C[(size_t)r * ldc + c + 1]       = d1;
                    C[(size_t)(r + 8) * ldc + c]     = d2;
                    C[(size_t)(r + 8) * ldc + c + 1] = d3;
                }
            }
        }
    }
}

// ----------------------------------------------------------------------------
// Causal depthwise conv (k=4) + SiLU. Writes full (uT) + tf32-rounded (uTr).
// ----------------------------------------------------------------------------
__global__ void conv_silu_kernel(const float* __restrict__ xzT,
                                 const float* __restrict__ cw,
                                 const float* __restrict__ cb,
                                 float* __restrict__ uT,
                                 float* __restrict__ uTr)
{
    int i = blockIdx.x * blockDim.x + threadIdx.x;
    int d = i >> 13;
    int m = i & 8191;
    int t = m & 1023;
    const float* src = xzT + (size_t)d * MTOT + m;
    float w0 = cw[d * 4 + 0], w1 = cw[d * 4 + 1];
    float w2 = cw[d * 4 + 2], w3 = cw[d * 4 + 3];
    float acc = cb[d];
    if (t >= 3) acc = fmaf(src[-3], w0, acc);
    if (t >= 2) acc = fmaf(src[-2], w1, acc);
    if (t >= 1) acc = fmaf(src[-1], w2, acc);
    acc = fmaf(src[0], w3, acc);
    float s = siluf(acc);
    uT [(size_t)d * MTOT + m] = s;
    uTr[(size_t)d * MTOT + m] = tf32r(s);
}

// ----------------------------------------------------------------------------
// Selective scan v6. Block = 128 thr (4 warps) = 8 channels of ONE batch.
// 16-step chunks -> 24.5 KB smem/block -> ~9 blocks/SM (was 4): the scan was
// occupancy-bound (25% -> 56%+). Double-buffered cp.async for B/C + dt/u/z.
// softplus fused in-scan. Same reduction (xor16+xor8 + smem partials).
// ----------------------------------------------------------------------------
constexpr int CH = 16;   // chunk length (timesteps)

__global__ void __launch_bounds__(128) ssm_scan_kernel(
    const float* __restrict__ proj,
    const float* __restrict__ dtT,    // RAW dt (pre-softplus, bias added)
    const float* __restrict__ uT,
    const float* __restrict__ xzT,
    const float* __restrict__ A_log,
    const float* __restrict__ Dparam,
    float* __restrict__ yT)
{
    __shared__ float sBC [2][CH][128];    // 16 KB
    __shared__ float sDU [2][4][8][CH];   // 4 KB: dt0,dt1,u0,u1,z0,z1,du0,du1
    __shared__ float pbuf[4][2][CH][9];   // 4.5 KB

    const unsigned FULL = 0xFFFFFFFFu;
    const float L2E = 1.4426950408889634f;
    const int tid  = threadIdx.x;
    const int wid  = tid >> 5;
    const int lane = tid & 31;
    const int b  = blockIdx.y;
    const int d0 = blockIdx.x * 8 + wid * 2;
    const int d1 = d0 + 1;

    float A00 = -__expf(A_log[(size_t)d0 * NS + lane])      * L2E;
    float A01 = -__expf(A_log[(size_t)d0 * NS + lane + 32]) * L2E;
    float A10 = -__expf(A_log[(size_t)d1 * NS + lane])      * L2E;
    float A11 = -__expf(A_log[(size_t)d1 * NS + lane + 32]) * L2E;
    float D0 = Dparam[d0], D1 = Dparam[d1];

    // DU prefetch mapping: rows 0..5 = dt0,dt1,u0,u1,z0,z1 (16 floats each)
    const int prow = lane >> 2;            // 0..7; only lanes<24 (rows 0..5)
    const int pseg = (lane & 3) * 4;       // 0,4,8,12
    const float* psrc =
        (prow == 0) ? dtT + (size_t)d0 * MTOT :
        (prow == 1) ? dtT + (size_t)d1 * MTOT :
        (prow == 2) ? uT  + (size_t)d0 * MTOT :
        (prow == 3) ? uT  + (size_t)d1 * MTOT :
        (prow == 4) ? xzT + (size_t)(DI + d0) * MTOT
                    : xzT + (size_t)(DI + d1) * MTOT;

    float h00 = 0.f, h01 = 0.f, h10 = 0.f, h11 = 0.f;

    auto issueAll = [&](int tc, int st) {
        size_t mb = (size_t)b * LL + tc;
        #pragma unroll
        for (int it = 0; it < 4; it++) {
            int s   = tid + it * 128;      // 512 float4 slots
            int row = s >> 5;              // 0..15
            int c4  = (s & 31) * 4;
            cpa16(&sBC[st][row][c4], proj + (mb + row) * PROJC + 48 + c4);
        }
        if (lane < 24)
            cpa16(&sDU[st][wid][prow][pseg], psrc + mb + pseg);
        asm volatile("cp.async.commit_group;\n");
    };

    issueAll(0, 0);

    const int jj = lane & 15;
    const int ch = lane >> 4;

    int st = 0;
    for (int tc = 0; tc < LL; tc += CH, st ^= 1) {
        const size_t mb = (size_t)b * LL + tc;

        if (tc + CH < LL) {
            issueAll(tc + CH, st ^ 1);
            asm volatile("cp.async.wait_group 1;\n");
        } else {
            asm volatile("cp.async.wait_group 0;\n");
        }
        __syncthreads();

        // softplus + du: lanes 0..15 -> ch0, 16..31 -> ch1
        {
            float raw = sDU[st][wid][ch][jj];
            float uu  = sDU[st][wid][2 + ch][jj];
            float sp  = softplusf(raw);
            sDU[st][wid][ch][jj]     = sp;        // raw dt -> softplus dt
            sDU[st][wid][6 + ch][jj] = sp * uu;   // du
        }
        __syncwarp();

        #pragma unroll
        for (int j = 0; j < CH; j++) {
            float Bn0 = sBC[st][j][lane];
            float Bn1 = sBC[st][j][lane + 32];
            float Cn0 = sBC[st][j][64 + lane];
            float Cn1 = sBC[st][j][96 + lane];
            float dt0 = sDU[st][wid][0][j];
            float dt1 = sDU[st][wid][1][j];
            float du0 = sDU[st][wid][6][j];
            float du1 = sDU[st][wid][7][j];
            h00 = fmaf(ex2f(dt0 * A00), h00, du0 * Bn0);
            h01 = fmaf(ex2f(dt0 * A01), h01, du0 * Bn1);
            h10 = fmaf(ex2f(dt1 * A10), h10, du1 * Bn0);
            h11 = fmaf(ex2f(dt1 * A11), h11, du1 * Bn1);
            float y0 = fmaf(h00, Cn0, h01 * Cn1);
            float y1 = fmaf(h10, Cn0, h11 * Cn1);
            y0 += __shfl_xor_sync(FULL, y0, 16);
            y0 += __shfl_xor_sync(FULL, y0, 8);
            y1 += __shfl_xor_sync(FULL, y1, 16);
            y1 += __shfl_xor_sync(FULL, y1, 8);
            pbuf[wid][0][j][lane & 7] = y0;
            pbuf[wid][1][j][lane & 7] = y1;
        }
        __syncwarp();

        // epilogue: lane 0..15 -> ch0 t=tc+jj ; lane 16..31 -> ch1 t=tc+jj
        {
            float yf = 0.f;
            #pragma unroll
            for (int i = 0; i < 8; i++)
                yf += pbuf[wid][ch][jj][i];
            float uu = sDU[st][wid][2 + ch][jj];
            float zz = sDU[st][wid][4 + ch][jj];
            float Dv = ch ? D1 : D0;
            float out = (yf + uu * Dv) * siluf(zz);
            yT[(size_t)(d0 + ch) * MTOT + mb + jj] = tf32r(out);
        }
        __syncthreads();   // buffers free before next chunk's issue
    }
}

// ----------------------------------------------------------------------------
// kernel_launch
// ----------------------------------------------------------------------------
extern "C" void kernel_launch(void* const* d_in, const int* in_sizes, int n_in,
                              void* d_out, int out_size)
{
    const float* x     = (const float*)d_in[0];
    const float* W_in  = (const float*)d_in[1];
    const float* cw    = (const float*)d_in[2];
    const float* cb    = (const float*)d_in[3];
    const float* W_x   = (const float*)d_in[4];
    const float* W_dt  = (const float*)d_in[5];
    const float* b_dt  = (const float*)d_in[6];
    const float* A_log = (const float*)d_in[7];
    const float* Dp    = (const float*)d_in[8];
    const float* W_out = (const float*)d_in[9];

    float *xzT, *uT, *uTr, *proj, *dtT, *yT, *mid, *xr;
    float *win, *wx, *wdt, *wout;
    cudaGetSymbolAddress((void**)&xzT,  g_xzT);
    cudaGetSymbolAddress((void**)&uT,   g_uT);
    cudaGetSymbolAddress((void**)&uTr,  g_uTr);
    cudaGetSymbolAddress((void**)&proj, g_proj);
    cudaGetSymbolAddress((void**)&dtT,  g_dtT);
    cudaGetSymbolAddress((void**)&yT,   g_yT);
    cudaGetSymbolAddress((void**)&mid,  g_mid);
    cudaGetSymbolAddress((void**)&xr,   g_xr);
    cudaGetSymbolAddress((void**)&win,  g_win);
    cudaGetSymbolAddress((void**)&wx,   g_wx);
    cudaGetSymbolAddress((void**)&wdt,  g_wdt);
    cudaGetSymbolAddress((void**)&wout, g_wout);

    const dim3 tb256(256);
    const int MB = MTOT / TBM;   // 64

    // ---- tf32 pre-rounding (weights + layer-0 input), single launch ----
    round_all_kernel<<<(RQ4 + 255) / 256, tb256>>>(
        x, xr, W_in, win, W_x, wx, W_dt, wdt, W_out, wout);

    for (int l = 0; l < 2; l++) {
        const float* xin = (l == 0) ? xr : mid;
        float* xout = (l == 1) ? (float*)d_out : mid;

        // 1. in-proj, n-major output straight into xzT (CTRANS)
        tgemm_kernel<false, true, 0>
            <<<dim3(XZC / TBN, MB), tb256>>>(
                xin, DM, win + (size_t)l * XZC * DM, nullptr,
                xzT, 0, XZC, DM);

        // 2. conv + silu -> uT (full) + uTr (rounded)
        conv_silu_kernel<<<(DI * MTOT) / 256, tb256>>>(
            xzT, cw + (size_t)l * DI * 4, cb + (size_t)l * DI, uT, uTr);

        // 3. x-proj: proj[m,176] = u @ W_x^T ; rounds dt_r cols (<48) only
        tgemm_kernel<true, false, 3>
            <<<dim3((PROJC + TBN - 1) / TBN, MB), tb256>>>(
                uTr, 0, wx + (size_t)l * PROJC * DI, nullptr,
                proj, PROJC, PROJC, DI);

        // 4. dt raw (+bias) n-major straight into dtT (CTRANS, MODE 4)
        tgemm_kernel<false, true, 4>
            <<<dim3(DI / TBN, MB), tb256>>>(
                proj, PROJC, wdt + (size_t)l * DI * DTR,
                b_dt + (size_t)l * DI, dtT, 0, DI, DTR);

        // 5. selective scan (softplus fused) + skip + gate -> yT
        ssm_scan_kernel<<<dim3(DI / 8, BB), dim3(128)>>>(
            proj, dtT, uT, xzT,
            A_log + (size_t)l * DI * NS, Dp + (size_t)l * DI, yT);

        // 6. out-proj: xout = y @ W_out^T ; l=0 rounds (feeds next in-proj)
        if (l == 0)
            tgemm_kernel<true, false, 2>
                <<<dim3(DM / TBN, MB), tb256>>>(
                    yT, 0, wout + (size_t)l * DM * DI, nullptr,
                    xout, DM, DM, DI);
        else
            tgemm_kernel<true, false, 0>
                <<<dim3(DM / TBN, MB), tb256>>>(
                    yT, 0, wout + (size_t)l * DM * DI, nullptr,
                    xout, DM, DM, DI);
    }
}

// round 14
// speedup vs baseline: 1.3306x; 1.1567x over previous
#include <cuda_runtime.h>
#include <cuda_fp16.h>
#include <cstdint>

// ----------------------------------------------------------------------------
// Problem constants (fixed shapes)
// ----------------------------------------------------------------------------
constexpr int BB   = 8;
constexpr int LL   = 1024;
constexpr int DM   = 768;
constexpr int DI   = 1536;
constexpr int NS   = 64;
constexpr int DTR  = 48;
constexpr int MTOT = BB * LL;        // 8192
constexpr int XZC  = 2 * DI;         // 3072
constexpr int PROJC = DTR + 2 * NS;  // 176

// ----------------------------------------------------------------------------
// Scratch (device globals; no allocation allowed)
// ----------------------------------------------------------------------------
__device__ float  g_xzT [MTOT * XZC];   // (3072, m) in-proj output, d-major
__device__ float  g_uT  [MTOT * DI];    // (d, m) conv+silu, full precision
__device__ float  g_uTr [MTOT * DI];    // (d, m) conv+silu, tf32-rounded
__device__ float  g_proj[MTOT * PROJC]; // (m, 176) [dt_r(tf32) | B | C]
__device__ float  g_dtT [MTOT * DI];    // (d, m) RAW dt (pre-softplus, +bias)
__device__ float  g_yT  [MTOT * DI];    // (d, m) scan out, tf32-rounded
__device__ __half g_midh[MTOT * DM];    // inter-layer act (fp16)
__device__ __half g_xrh [MTOT * DM];    // layer-0 input, fp16
__device__ __half g_winh[2 * XZC * DM]; // W_in fp16

constexpr int WIN_SZ  = 2 * XZC * DM;
constexpr int WX_SZ   = 2 * PROJC * DI;
constexpr int WDT_SZ  = 2 * DI * DTR;
constexpr int WOUT_SZ = 2 * DM * DI;
__device__ float g_wx  [WX_SZ];
__device__ float g_wdt [WDT_SZ];
__device__ float g_wout[WOUT_SZ];

// ----------------------------------------------------------------------------
// Helpers
// ----------------------------------------------------------------------------
__device__ __forceinline__ float siluf(float x) {
    return x * (1.0f / (1.0f + __expf(-x)));
}
__device__ __forceinline__ float softplusf(float x) {
    return fmaxf(x, 0.0f) + log1pf(__expf(-fabsf(x)));
}
__device__ __forceinline__ float tf32r(float x) {
    uint32_t r;
    asm("cvt.rna.tf32.f32 %0, %1;" : "=r"(r) : "f"(x));
    return __uint_as_float(r);
}
__device__ __forceinline__ float ex2f(float x) {   // MUFU EX2
    float r;
    asm("ex2.approx.f32 %0, %1;" : "=f"(r) : "f"(x));
    return r;
}
__device__ __forceinline__ void mma_tf32(float* d, const uint32_t* a,
                                         const uint32_t* b) {
    asm volatile(
        "mma.sync.aligned.m16n8k8.row.col.f32.tf32.tf32.f32 "
        "{%0,%1,%2,%3}, {%4,%5,%6,%7}, {%8,%9}, {%0,%1,%2,%3};\n"
        : "+f"(d[0]), "+f"(d[1]), "+f"(d[2]), "+f"(d[3])
        : "r"(a[0]), "r"(a[1]), "r"(a[2]), "r"(a[3]), "r"(b[0]), "r"(b[1]));
}
__device__ __forceinline__ void mma_f16(float* d, const uint32_t* a,
                                        const uint32_t* b) {
    asm volatile(
        "mma.sync.aligned.m16n8k16.row.col.f32.f16.f16.f32 "
        "{%0,%1,%2,%3}, {%4,%5,%6,%7}, {%8,%9}, {%0,%1,%2,%3};\n"
        : "+f"(d[0]), "+f"(d[1]), "+f"(d[2]), "+f"(d[3])
        : "r"(a[0]), "r"(a[1]), "r"(a[2]), "r"(a[3]), "r"(b[0]), "r"(b[1]));
}
__device__ __forceinline__ void cpa16(void* smem, const void* g) {
    uint32_t dst = (uint32_t)__cvta_generic_to_shared(smem);
    asm volatile("cp.async.ca.shared.global [%0], [%1], 16;\n"
                 :: "r"(dst), "l"(g));
}
__device__ __forceinline__ void cpa16z(void* smem, const void* g, int sz) {
    uint32_t dst = (uint32_t)__cvta_generic_to_shared(smem);
    asm volatile("cp.async.ca.shared.global [%0], [%1], 16, %2;\n"
                 :: "r"(dst), "l"(g), "r"(sz));
}

// ----------------------------------------------------------------------------
// Merged rounding kernel: x,W_in -> fp16 ; W_x,W_dt,W_out -> tf32.
// ----------------------------------------------------------------------------
constexpr int RQ0 = (MTOT * DM) / 4;
constexpr int RQ1 = RQ0 + WIN_SZ / 4;
constexpr int RQ2 = RQ1 + WX_SZ / 4;
constexpr int RQ3 = RQ2 + WDT_SZ / 4;
constexpr int RQ4 = RQ3 + WOUT_SZ / 4;

__global__ void round_all_kernel(
    const float* __restrict__ x,    __half* __restrict__ xrh,
    const float* __restrict__ Wi,   __half* __restrict__ wih,
    const float* __restrict__ Wx,   float* __restrict__ wx,
    const float* __restrict__ Wdt,  float* __restrict__ wdt,
    const float* __restrict__ Wo,   float* __restrict__ wo)
{
    int q = blockIdx.x * blockDim.x + threadIdx.x;
    if (q >= RQ4) return;
    if (q < RQ1) {
        const float* in; __half* out; int base;
        if (q < RQ0) { in = x;  out = xrh; base = 0;   }
        else         { in = Wi; out = wih; base = RQ0; }
        int i = (q - base) * 4;
        float4 v = *reinterpret_cast<const float4*>(in + i);
        __half2 h01 = __floats2half2_rn(v.x, v.y);
        __half2 h23 = __floats2half2_rn(v.z, v.w);
        *reinterpret_cast<__half2*>(out + i)     = h01;
        *reinterpret_cast<__half2*>(out + i + 2) = h23;
    } else {
        const float* in; float* out; int base;
        if      (q < RQ2) { in = Wx;  out = wx;  base = RQ1; }
        else if (q < RQ3) { in = Wdt; out = wdt; base = RQ2; }
        else              { in = Wo;  out = wo;  base = RQ3; }
        int i = (q - base) * 4;
        float4 v = *reinterpret_cast<const float4*>(in + i);
        v.x = tf32r(v.x); v.y = tf32r(v.y);
        v.z = tf32r(v.z); v.w = tf32r(v.w);
        *reinterpret_cast<float4*>(out + i) = v;
    }
}

// ============================================================================
// Shared GEMM tile constants
// ============================================================================
constexpr int TBM = 128, TBN = 128, TBK = 16;
constexpr int SKM = 136;
constexpr int SMK = 20;
constexpr int ASTG = 2560;
constexpr int BSTG = 2560;
constexpr int TSP  = 136;

// ============================================================================
// fp16 GEMM (in-proj only): A m-major half (lda), W half N x K, CTRANS out.
// Block 128x128x32(halves), 2-stage cp.async, warp 64x32, mma m16n8k16.
// smem [m][k-pairs] stride 20 words (40 halves) -> conflict-free frag reads.
// N % 128 == 0, K % 32 == 0.
// ============================================================================
constexpr int HSW = 20;   // words per row

__global__ void __launch_bounds__(256, 2) hgemm_kernel(
    const __half* __restrict__ A, int lda,
    const __half* __restrict__ W,
    float* __restrict__ C,          // N x MTOT (n-major)
    int N, int K)
{
    __shared__ uint32_t As[2][128 * HSW];   // 10 KB/stage
    __shared__ uint32_t Bs[2][128 * HSW];

    const int tid  = threadIdx.x;
    const int bm   = blockIdx.y * TBM;
    const int bn   = blockIdx.x * TBN;
    const int wid  = tid >> 5;
    const int lane = tid & 31;
    const int wm   = (wid & 1) * 64;
    const int wn   = (wid >> 1) * 32;
    const int gid  = lane >> 2;
    const int tig  = lane & 3;

    float acc[4][4][4];
    #pragma unroll
    for (int i = 0; i < 4; i++)
        #pragma unroll
        for (int j = 0; j < 4; j++)
            #pragma unroll
            for (int c = 0; c < 4; c++) acc[i][j][c] = 0.0f;

    auto issue_load = [&](int k0, int st) {
        #pragma unroll
        for (int itr = 0; itr < 2; itr++) {
            int s   = tid + itr * 256;        // 512 slots
            int row = s >> 2;
            int ko  = (s & 3) * 8;            // halves
            cpa16(&As[st][row * HSW + (s & 3) * 4],
                  A + (size_t)(bm + row) * lda + k0 + ko);
            cpa16(&Bs[st][row * HSW + (s & 3) * 4],
                  W + (size_t)(bn + row) * K + k0 + ko);
        }
        asm volatile("cp.async.commit_group;\n");
    };

    issue_load(0, 0);

    const int kt = K / 32;
    int st = 0;
    for (int it = 0; it < kt; it++) {
        asm volatile("cp.async.wait_group 0;\n");
        __syncthreads();
        if (it + 1 < kt) issue_load((it + 1) * 32, st ^ 1);

        #pragma unroll
        for (int kb = 0; kb < 2; kb++) {
            const int k8 = kb * 8;
            uint32_t afr[4][4], bfr[4][2];
            #pragma unroll
            for (int mi = 0; mi < 4; mi++) {
                int r = wm + mi * 16 + gid;
                afr[mi][0] = As[st][r * HSW + k8 + tig];
                afr[mi][1] = As[st][(r + 8) * HSW + k8 + tig];
                afr[mi][2] = As[st][r * HSW + k8 + tig + 4];
                afr[mi][3] = As[st][(r + 8) * HSW + k8 + tig + 4];
            }
            #pragma unroll
            for (int ni = 0; ni < 4; ni++) {
                int c = wn + ni * 8 + gid;
                bfr[ni][0] = Bs[st][c * HSW + k8 + tig];
                bfr[ni][1] = Bs[st][c * HSW + k8 + tig + 4];
            }
            #pragma unroll
            for (int mi = 0; mi < 4; mi++)
                #pragma unroll
                for (int ni = 0; ni < 4; ni++)
                    mma_f16(acc[mi][ni], afr[mi], bfr[ni]);
        }
        st ^= 1;
    }

    // CTRANS epilogue (n-major out), stages 32 n-cols per phase in As alias
    float (*Ts)[TSP] = reinterpret_cast<float (*)[TSP]>(&As[0][0]);
    #pragma unroll
    for (int p = 0; p < 4; p++) {
        __syncthreads();
        if ((wid >> 1) == p) {
            #pragma unroll
            for (int mi = 0; mi < 4; mi++)
                #pragma unroll
                for (int ni = 0; ni < 4; ni++)
                    #pragma unroll
                    for (int c = 0; c < 4; c++) {
                        int rr = wm + mi * 16 + gid + ((c >= 2) ? 8 : 0);
                        int cc = ni * 8 + tig * 2 + (c & 1);
                        Ts[cc][rr] = acc[mi][ni][c];
                    }
        }
        __syncthreads();
        int nn = tid >> 3;
        int mm = (tid & 7) * 16;
        size_t base = (size_t)(bn + p * 32 + nn) * MTOT + bm + mm;
        #pragma unroll
        for (int q = 0; q < 4; q++)
            *reinterpret_cast<float4*>(&C[base + q * 4]) =
                *reinterpret_cast<const float4*>(&Ts[nn][mm + q * 4]);
    }
}

// ============================================================================
// tf32 GEMM (x-proj / dt / out-proj). As in R13.
//   MODE: 0 none | 1 softplus(+bias) | 3 round cols < DTR
//         4 bias-add only (CTRANS) | 5 write fp16 to g_midh (no fp32 C)
// ============================================================================
template<bool ATRANS, bool CTRANS, int MODE>
__global__ void __launch_bounds__(256, 2) tgemm_kernel(
    const float* __restrict__ A, int lda,
    const float* __restrict__ W,
    const float* __restrict__ bias,
    float* __restrict__ C, int ldc,
    int N, int K)
{
    __shared__ float As[2][ASTG];
    __shared__ float Bs[2][BSTG];

    const int tid  = threadIdx.x;
    const int bm   = blockIdx.y * TBM;
    const int bn   = blockIdx.x * TBN;
    const int wid  = tid >> 5;
    const int lane = tid & 31;
    const int wm   = (wid & 1) * 64;
    const int wn   = (wid >> 1) * 32;
    const int gid  = lane >> 2;
    const int tig  = lane & 3;

    float acc[4][4][4];
    #pragma unroll
    for (int i = 0; i < 4; i++)
        #pragma unroll
        for (int j = 0; j < 4; j++)
            #pragma unroll
            for (int c = 0; c < 4; c++) acc[i][j][c] = 0.0f;

    auto issue_load = [&](int k0, int st) {
        #pragma unroll
        for (int itr = 0; itr < 2; itr++) {
            int s = tid + itr * 256;
            if (ATRANS) {
                int kk = s >> 5, mc = (s & 31) * 4;
                cpa16(&As[st][kk * SKM + mc],
                      A + (size_t)(k0 + kk) * MTOT + bm + mc);
            } else {
                int row = s >> 2, kc = (s & 3) * 4;
                cpa16(&As[st][row * SMK + kc],
                      A + (size_t)(bm + row) * lda + k0 + kc);
            }
            int n = s >> 2, kc = (s & 3) * 4;
            cpa16z(&Bs[st][n * SMK + kc],
                   W + (size_t)(bn + n) * K + k0 + kc,
                   (bn + n < N) ? 16 : 0);
        }
        asm volatile("cp.async.commit_group;\n");
    };

    issue_load(0, 0);

    const int kt = K / TBK;
    int st = 0;
    for (int it = 0; it < kt; it++) {
        asm volatile("cp.async.wait_group 0;\n");
        __syncthreads();
        if (it + 1 < kt) issue_load((it + 1) * TBK, st ^ 1);

        #pragma unroll
        for (int ks = 0; ks < 2; ks++) {
            const int kb = ks * 8;
            uint32_t afr[4][4], bfr[4][2];
            #pragma unroll
            for (int mi = 0; mi < 4; mi++) {
                int r = wm + mi * 16 + gid;
                if (ATRANS) {
                    afr[mi][0] = __float_as_uint(As[st][(kb + tig) * SKM + r]);
                    afr[mi][1] = __float_as_uint(As[st][(kb + tig) * SKM + r + 8]);
                    afr[mi][2] = __float_as_uint(As[st][(kb + tig + 4) * SKM + r]);
                    afr[mi][3] = __float_as_uint(As[st][(kb + tig + 4) * SKM + r + 8]);
                } else {
                    afr[mi][0] = __float_as_uint(As[st][r * SMK + kb + tig]);
                    afr[mi][1] = __float_as_uint(As[st][(r + 8) * SMK + kb + tig]);
                    afr[mi][2] = __float_as_uint(As[st][r * SMK + kb + tig + 4]);
                    afr[mi][3] = __float_as_uint(As[st][(r + 8) * SMK + kb + tig + 4]);
                }
            }
            #pragma unroll
            for (int ni = 0; ni < 4; ni++) {
                int c = wn + ni * 8 + gid;
                bfr[ni][0] = __float_as_uint(Bs[st][c * SMK + kb + tig]);
                bfr[ni][1] = __float_as_uint(Bs[st][c * SMK + kb + tig + 4]);
            }
            #pragma unroll
            for (int mi = 0; mi < 4; mi++)
                #pragma unroll
                for (int ni = 0; ni < 4; ni++)
                    mma_tf32(acc[mi][ni], afr[mi], bfr[ni]);
        }
        st ^= 1;
    }

    if constexpr (CTRANS) {
        float (*Ts)[TSP] = reinterpret_cast<float (*)[TSP]>(&As[0][0]);
        #pragma unroll
        for (int p = 0; p < 4; p++) {
            __syncthreads();
            if ((wid >> 1) == p) {
                #pragma unroll
                for (int mi = 0; mi < 4; mi++)
                    #pragma unroll
                    for (int ni = 0; ni < 4; ni++)
                        #pragma unroll
                        for (int c = 0; c < 4; c++) {
                            int rr = wm + mi * 16 + gid + ((c >= 2) ? 8 : 0);
                            int cc = ni * 8 + tig * 2 + (c & 1);
                            float v = acc[mi][ni][c];
                            if (MODE == 4)
                                v += bias[bn + p * 32 + cc];
                            Ts[cc][rr] = v;
                        }
            }
            __syncthreads();
            int nn = tid >> 3;
            int mm = (tid & 7) * 16;
            int grow = bn + p * 32 + nn;
            if (grow < N) {
                size_t base = (size_t)grow * MTOT + bm + mm;
                #pragma unroll
                for (int q = 0; q < 4; q++)
                    *reinterpret_cast<float4*>(&C[base + q * 4]) =
                        *reinterpret_cast<const float4*>(&Ts[nn][mm + q * 4]);
            }
        }
    } else {
        #pragma unroll
        for (int mi = 0; mi < 4; mi++) {
            int r = bm + wm + mi * 16 + gid;
            #pragma unroll
            for (int ni = 0; ni < 4; ni++) {
                int c = bn + wn + ni * 8 + tig * 2;
                if (c < N) {
                    float d0 = acc[mi][ni][0], d1 = acc[mi][ni][1];
                    float d2 = acc[mi][ni][2], d3 = acc[mi][ni][3];
                    if (MODE == 1) {
                        float b0 = bias[c], b1 = bias[c + 1];
                        d0 = softplusf(d0 + b0); d1 = softplusf(d1 + b1);
                        d2 = softplusf(d2 + b0); d3 = softplusf(d3 + b1);
                    }
                    if (MODE == 3 && c < DTR) {
                        d0 = tf32r(d0); d1 = tf32r(d1);
                        d2 = tf32r(d2); d3 = tf32r(d3);
                    }
                    if (MODE == 5) {
                        // fp16 inter-layer activation (feeds fp16 in-proj)
                        *reinterpret_cast<__half2*>(
                            &g_midh[(size_t)r * DM + c]) =
                            __floats2half2_rn(d0, d1);
                        *reinterpret_cast<__half2*>(
                            &g_midh[(size_t)(r + 8) * DM + c]) =
                            __floats2half2_rn(d2, d3);
                    } else {
                        C[(size_t)r * ldc + c]           = d0;
                        C[(size_t)r * ldc + c + 1]       = d1;
                        C[(size_t)(r + 8) * ldc + c]     = d2;
                        C[(size_t)(r + 8) * ldc + c + 1] = d3;
                    }
                }
            }
        }
    }
}

// ----------------------------------------------------------------------------
// Causal depthwise conv (k=4) + SiLU. Writes full (uT) + tf32-rounded (uTr).
// ----------------------------------------------------------------------------
__global__ void conv_silu_kernel(const float* __restrict__ xzT,
                                 const float* __restrict__ cw,
                                 const float* __restrict__ cb,
                                 float* __restrict__ uT,
                                 float* __restrict__ uTr)
{
    int i = blockIdx.x * blockDim.x + threadIdx.x;
    int d = i >> 13;
    int m = i & 8191;
    int t = m & 1023;
    const float* src = xzT + (size_t)d * MTOT + m;
    float w0 = cw[d * 4 + 0], w1 = cw[d * 4 + 1];
    float w2 = cw[d * 4 + 2], w3 = cw[d * 4 + 3];
    float acc = cb[d];
    if (t >= 3) acc = fmaf(src[-3], w0, acc);
    if (t >= 2) acc = fmaf(src[-2], w1, acc);
    if (t >= 1) acc = fmaf(src[-1], w2, acc);
    acc = fmaf(src[0], w3, acc);
    float s = siluf(acc);
    uT [(size_t)d * MTOT + m] = s;
    uTr[(size_t)d * MTOT + m] = tf32r(s);
}

// ----------------------------------------------------------------------------
// Selective scan v6 (unchanged from R13): 16-step chunks, cp.async double-
// buffered B/C + dt/u/z, softplus fused, butterfly+smem reduction.
// ----------------------------------------------------------------------------
constexpr int CH = 16;

__global__ void __launch_bounds__(128) ssm_scan_kernel(
    const float* __restrict__ proj,
    const float* __restrict__ dtT,
    const float* __restrict__ uT,
    const float* __restrict__ xzT,
    const float* __restrict__ A_log,
    const float* __restrict__ Dparam,
    float* __restrict__ yT)
{
    __shared__ float sBC [2][CH][128];
    __shared__ float sDU [2][4][8][CH];
    __shared__ float pbuf[4][2][CH][9];

    const unsigned FULL = 0xFFFFFFFFu;
    const float L2E = 1.4426950408889634f;
    const int tid  = threadIdx.x;
    const int wid  = tid >> 5;
    const int lane = tid & 31;
    const int b  = blockIdx.y;
    const int d0 = blockIdx.x * 8 + wid * 2;
    const int d1 = d0 + 1;

    float A00 = -__expf(A_log[(size_t)d0 * NS + lane])      * L2E;
    float A01 = -__expf(A_log[(size_t)d0 * NS + lane + 32]) * L2E;
    float A10 = -__expf(A_log[(size_t)d1 * NS + lane])      * L2E;
    float A11 = -__expf(A_log[(size_t)d1 * NS + lane + 32]) * L2E;
    float D0 = Dparam[d0], D1 = Dparam[d1];

    const int prow = lane >> 2;
    const int pseg = (lane & 3) * 4;
    const float* psrc =
        (prow == 0) ? dtT + (size_t)d0 * MTOT :
        (prow == 1) ? dtT + (size_t)d1 * MTOT :
        (prow == 2) ? uT  + (size_t)d0 * MTOT :
        (prow == 3) ? uT  + (size_t)d1 * MTOT :
        (prow == 4) ? xzT + (size_t)(DI + d0) * MTOT
                    : xzT + (size_t)(DI + d1) * MTOT;

    float h00 = 0.f, h01 = 0.f, h10 = 0.f, h11 = 0.f;

    auto issueAll = [&](int tc, int st) {
        size_t mb = (size_t)b * LL + tc;
        #pragma unroll
        for (int it = 0; it < 4; it++) {
            int s   = tid + it * 128;
            int row = s >> 5;
            int c4  = (s & 31) * 4;
            cpa16(&sBC[st][row][c4], proj + (mb + row) * PROJC + 48 + c4);
        }
        if (lane < 24)
            cpa16(&sDU[st][wid][prow][pseg], psrc + mb + pseg);
        asm volatile("cp.async.commit_group;\n");
    };

    issueAll(0, 0);

    const int jj = lane & 15;
    const int ch = lane >> 4;

    int st = 0;
    for (int tc = 0; tc < LL; tc += CH, st ^= 1) {
        const size_t mb = (size_t)b * LL + tc;

        if (tc + CH < LL) {
            issueAll(tc + CH, st ^ 1);
            asm volatile("cp.async.wait_group 1;\n");
        } else {
            asm volatile("cp.async.wait_group 0;\n");
        }
        __syncthreads();

        {
            float raw = sDU[st][wid][ch][jj];
            float uu  = sDU[st][wid][2 + ch][jj];
            float sp  = softplusf(raw);
            sDU[st][wid][ch][jj]     = sp;
            sDU[st][wid][6 + ch][jj] = sp * uu;
        }
        __syncwarp();

        #pragma unroll
        for (int j = 0; j < CH; j++) {
            float Bn0 = sBC[st][j][lane];
            float Bn1 = sBC[st][j][lane + 32];
            float Cn0 = sBC[st][j][64 + lane];
            float Cn1 = sBC[st][j][96 + lane];
            float dt0 = sDU[st][wid][0][j];
            float dt1 = sDU[st][wid][1][j];
            float du0 = sDU[st][wid][6][j];
            float du1 = sDU[st][wid][7][j];
            h00 = fmaf(ex2f(dt0 * A00), h00, du0 * Bn0);
            h01 = fmaf(ex2f(dt0 * A01), h01, du0 * Bn1);
            h10 = fmaf(ex2f(dt1 * A10), h10, du1 * Bn0);
            h11 = fmaf(ex2f(dt1 * A11), h11, du1 * Bn1);
            float y0 = fmaf(h00, Cn0, h01 * Cn1);
            float y1 = fmaf(h10, Cn0, h11 * Cn1);
            y0 += __shfl_xor_sync(FULL, y0, 16);
            y0 += __shfl_xor_sync(FULL, y0, 8);
            y1 += __shfl_xor_sync(FULL, y1, 16);
            y1 += __shfl_xor_sync(FULL, y1, 8);
            pbuf[wid][0][j][lane & 7] = y0;
            pbuf[wid][1][j][lane & 7] = y1;
        }
        __syncwarp();

        {
            float yf = 0.f;
            #pragma unroll
            for (int i = 0; i < 8; i++)
                yf += pbuf[wid][ch][jj][i];
            float uu = sDU[st][wid][2 + ch][jj];
            float zz = sDU[st][wid][4 + ch][jj];
            float Dv = ch ? D1 : D0;
            float out = (yf + uu * Dv) * siluf(zz);
            yT[(size_t)(d0 + ch) * MTOT + mb + jj] = tf32r(out);
        }
        __syncthreads();
    }
}

// ----------------------------------------------------------------------------
// kernel_launch
// ----------------------------------------------------------------------------
extern "C" void kernel_launch(void* const* d_in, const int* in_sizes, int n_in,
                              void* d_out, int out_size)
{
    const float* x     = (const float*)d_in[0];
    const float* W_in  = (const float*)d_in[1];
    const float* cw    = (const float*)d_in[2];
    const float* cb    = (const float*)d_in[3];
    const float* W_x   = (const float*)d_in[4];
    const float* W_dt  = (const float*)d_in[5];
    const float* b_dt  = (const float*)d_in[6];
    const float* A_log = (const float*)d_in[7];
    const float* Dp    = (const float*)d_in[8];
    const float* W_out = (const float*)d_in[9];

    float *xzT, *uT, *uTr, *proj, *dtT, *yT;
    float *wx, *wdt, *wout;
    __half *xrh, *winh, *midh;
    cudaGetSymbolAddress((void**)&xzT,  g_xzT);
    cudaGetSymbolAddress((void**)&uT,   g_uT);
    cudaGetSymbolAddress((void**)&uTr,  g_uTr);
    cudaGetSymbolAddress((void**)&proj, g_proj);
    cudaGetSymbolAddress((void**)&dtT,  g_dtT);
    cudaGetSymbolAddress((void**)&yT,   g_yT);
    cudaGetSymbolAddress((void**)&xrh,  g_xrh);
    cudaGetSymbolAddress((void**)&winh, g_winh);
    cudaGetSymbolAddress((void**)&midh, g_midh);
    cudaGetSymbolAddress((void**)&wx,   g_wx);
    cudaGetSymbolAddress((void**)&wdt,  g_wdt);
    cudaGetSymbolAddress((void**)&wout, g_wout);

    const dim3 tb256(256);
    const int MB = MTOT / TBM;   // 64

    // ---- precision prep: x,W_in -> fp16 ; W_x,W_dt,W_out -> tf32 ----
    round_all_kernel<<<(RQ4 + 255) / 256, tb256>>>(
        x, xrh, W_in, winh, W_x, wx, W_dt, wdt, W_out, wout);

    for (int l = 0; l < 2; l++) {
        const __half* xin = (l == 0) ? xrh : midh;
        float* xout = (float*)d_out;   // only used for l==1

        // 1. in-proj (fp16 tensor cores), n-major straight into xzT
        hgemm_kernel<<<dim3(XZC / TBN, MB), tb256>>>(
            xin, DM, winh + (size_t)l * XZC * DM, xzT, XZC, DM);

        // 2. conv + silu -> uT (full) + uTr (tf32-rounded)
        conv_silu_kernel<<<(DI * MTOT) / 256, tb256>>>(
            xzT, cw + (size_t)l * DI * 4, cb + (size_t)l * DI, uT, uTr);

        // 3. x-proj: proj[m,176] = u @ W_x^T ; rounds dt_r cols (<48) only
        tgemm_kernel<true, false, 3>
            <<<dim3((PROJC + TBN - 1) / TBN, MB), tb256>>>(
                uTr, 0, wx + (size_t)l * PROJC * DI, nullptr,
                proj, PROJC, PROJC, DI);

        // 4. dt raw (+bias) n-major straight into dtT (CTRANS, MODE 4)
        tgemm_kernel<false, true, 4>
            <<<dim3(DI / TBN, MB), tb256>>>(
                proj, PROJC, wdt + (size_t)l * DI * DTR,
                b_dt + (size_t)l * DI, dtT, 0, DI, DTR);

        // 5. selective scan (softplus fused) + skip + gate -> yT
        ssm_scan_kernel<<<dim3(DI / 8, BB), dim3(128)>>>(
            proj, dtT, uT, xzT,
            A_log + (size_t)l * DI * NS, Dp + (size_t)l * DI, yT);

        // 6. out-proj: l==0 -> fp16 midh (MODE 5); l==1 -> fp32 d_out
        if (l == 0)
            tgemm_kernel<true, false, 5>
                <<<dim3(DM / TBN, MB), tb256>>>(
                    yT, 0, wout + (size_t)l * DM * DI, nullptr,
                    yT /*unused*/, DM, DM, DI);
        else
            tgemm_kernel<true, false, 0>
                <<<dim3(DM / TBN, MB), tb256>>>(
                    yT, 0, wout + (size_t)l * DM * DI, nullptr,
                    xout, DM, DM, DI);
    }
}

// round 17
// speedup vs baseline: 1.4064x; 1.0570x over previous
#include <cuda_runtime.h>
#include <cuda_fp16.h>
#include <cstdint>

// ----------------------------------------------------------------------------
// Problem constants (fixed shapes)
// ----------------------------------------------------------------------------
constexpr int BB   = 8;
constexpr int LL   = 1024;
constexpr int DM   = 768;
constexpr int DI   = 1536;
constexpr int NS   = 64;
constexpr int DTR  = 48;
constexpr int MTOT = BB * LL;        // 8192
constexpr int XZC  = 2 * DI;         // 3072
constexpr int PROJC = DTR + 2 * NS;  // 176

// ----------------------------------------------------------------------------
// Scratch (device globals; no allocation allowed)
// ----------------------------------------------------------------------------
__device__ float    g_xzT [MTOT * XZC];      // (3072, m) in-proj out, d-major
__device__ float    g_uT  [MTOT * DI];       // (d, m) conv+silu, full fp32
__device__ uint32_t g_uhp [MTOT * DI / 2];   // (d/2, m) u as half2 pairs
__device__ float    g_proj[MTOT * PROJC];    // (m, 176) [dt_r(tf32) | B | C]
__device__ float    g_dtT [MTOT * DI];       // (d, m) RAW dt (+bias)
__device__ float    g_yT  [MTOT * DI];       // (d, m) scan out, tf32-rounded
__device__ __half   g_midh[MTOT * DM];       // inter-layer act (fp16)
__device__ __half   g_xrh [MTOT * DM];       // layer-0 input, fp16
__device__ __half   g_winh[2 * XZC * DM];    // W_in fp16
__device__ __half   g_wxh [2 * PROJC * DI];  // W_x fp16

constexpr int WIN_SZ  = 2 * XZC * DM;
constexpr int WX_SZ   = 2 * PROJC * DI;
constexpr int WDT_SZ  = 2 * DI * DTR;
constexpr int WOUT_SZ = 2 * DM * DI;
__device__ float g_wdt [WDT_SZ];             // tf32
__device__ float g_wout[WOUT_SZ];            // tf32

// ----------------------------------------------------------------------------
// Helpers
// ----------------------------------------------------------------------------
__device__ __forceinline__ float siluf(float x) {
    return x * (1.0f / (1.0f + __expf(-x)));
}
__device__ __forceinline__ float softplusf(float x) {
    return fmaxf(x, 0.0f) + log1pf(__expf(-fabsf(x)));
}
__device__ __forceinline__ float tf32r(float x) {
    uint32_t r;
    asm("cvt.rna.tf32.f32 %0, %1;" : "=r"(r) : "f"(x));
    return __uint_as_float(r);
}
__device__ __forceinline__ float ex2f(float x) {
    float r;
    asm("ex2.approx.f32 %0, %1;" : "=f"(r) : "f"(x));
    return r;
}
__device__ __forceinline__ void mma_tf32(float* d, const uint32_t* a,
                                         const uint32_t* b) {
    asm volatile(
        "mma.sync.aligned.m16n8k8.row.col.f32.tf32.tf32.f32 "
        "{%0,%1,%2,%3}, {%4,%5,%6,%7}, {%8,%9}, {%0,%1,%2,%3};\n"
        : "+f"(d[0]), "+f"(d[1]), "+f"(d[2]), "+f"(d[3])
        : "r"(a[0]), "r"(a[1]), "r"(a[2]), "r"(a[3]), "r"(b[0]), "r"(b[1]));
}
__device__ __forceinline__ void mma_f16(float* d, const uint32_t* a,
                                        const uint32_t* b) {
    asm volatile(
        "mma.sync.aligned.m16n8k16.row.col.f32.f16.f16.f32 "
        "{%0,%1,%2,%3}, {%4,%5,%6,%7}, {%8,%9}, {%0,%1,%2,%3};\n"
        : "+f"(d[0]), "+f"(d[1]), "+f"(d[2]), "+f"(d[3])
        : "r"(a[0]), "r"(a[1]), "r"(a[2]), "r"(a[3]), "r"(b[0]), "r"(b[1]));
}
__device__ __forceinline__ void cpa16(void* smem, const void* g) {
    uint32_t dst = (uint32_t)__cvta_generic_to_shared(smem);
    asm volatile("cp.async.ca.shared.global [%0], [%1], 16;\n"
                 :: "r"(dst), "l"(g));
}
__device__ __forceinline__ void cpa16z(void* smem, const void* g, int sz) {
    uint32_t dst = (uint32_t)__cvta_generic_to_shared(smem);
    asm volatile("cp.async.ca.shared.global [%0], [%1], 16, %2;\n"
                 :: "r"(dst), "l"(g), "r"(sz));
}

// ----------------------------------------------------------------------------
// Merged rounding: x,W_in,W_x -> fp16 ; W_dt,W_out -> tf32.
// ----------------------------------------------------------------------------
constexpr int RQ0 = (MTOT * DM) / 4;
constexpr int RQ1 = RQ0 + WIN_SZ / 4;
constexpr int RQ2 = RQ1 + WX_SZ / 4;
constexpr int RQ3 = RQ2 + WDT_SZ / 4;
constexpr int RQ4 = RQ3 + WOUT_SZ / 4;

__global__ void round_all_kernel(
    const float* __restrict__ x,    __half* __restrict__ xrh,
    const float* __restrict__ Wi,   __half* __restrict__ wih,
    const float* __restrict__ Wx,   __half* __restrict__ wxh,
    const float* __restrict__ Wdt,  float* __restrict__ wdt,
    const float* __restrict__ Wo,   float* __restrict__ wo)
{
    int q = blockIdx.x * blockDim.x + threadIdx.x;
    if (q >= RQ4) return;
    if (q < RQ2) {
        const float* in; __half* out; int base;
        if      (q < RQ0) { in = x;  out = xrh; base = 0;   }
        else if (q < RQ1) { in = Wi; out = wih; base = RQ0; }
        else              { in = Wx; out = wxh; base = RQ1; }
        int i = (q - base) * 4;
        float4 v = *reinterpret_cast<const float4*>(in + i);
        *reinterpret_cast<__half2*>(out + i)     = __floats2half2_rn(v.x, v.y);
        *reinterpret_cast<__half2*>(out + i + 2) = __floats2half2_rn(v.z, v.w);
    } else {
        const float* in; float* out; int base;
        if (q < RQ3) { in = Wdt; out = wdt; base = RQ2; }
        else         { in = Wo;  out = wo;  base = RQ3; }
        int i = (q - base) * 4;
        float4 v = *reinterpret_cast<const float4*>(in + i);
        v.x = tf32r(v.x); v.y = tf32r(v.y);
        v.z = tf32r(v.z); v.w = tf32r(v.w);
        *reinterpret_cast<float4*>(out + i) = v;
    }
}

// ============================================================================
// Shared GEMM tile constants
// ============================================================================
constexpr int TBM = 128, TBN = 128, TBK = 16;
constexpr int SKM = 136;
constexpr int SMK = 20;
constexpr int ASTG = 2560;
constexpr int BSTG = 2560;
constexpr int TSP  = 136;
constexpr int HSW  = 20;

// ============================================================================
// fp16 GEMM, A m-major (in-proj): CTRANS output to xzT. Proven in R14.
// ============================================================================
__global__ void __launch_bounds__(256, 2) hgemm_kernel(
    const __half* __restrict__ A, int lda,
    const __half* __restrict__ W,
    float* __restrict__ C,          // N x MTOT
    int N, int K)
{
    __shared__ uint32_t As[2][128 * HSW];
    __shared__ uint32_t Bs[2][128 * HSW];

    const int tid  = threadIdx.x;
    const int bm   = blockIdx.y * TBM;
    const int bn   = blockIdx.x * TBN;
    const int wid  = tid >> 5;
    const int lane = tid & 31;
    const int wm   = (wid & 1) * 64;
    const int wn   = (wid >> 1) * 32;
    const int gid  = lane >> 2;
    const int tig  = lane & 3;

    float acc[4][4][4];
    #pragma unroll
    for (int i = 0; i < 4; i++)
        #pragma unroll
        for (int j = 0; j < 4; j++)
            #pragma unroll
            for (int c = 0; c < 4; c++) acc[i][j][c] = 0.0f;

    auto issue_load = [&](int k0, int st) {
        #pragma unroll
        for (int itr = 0; itr < 2; itr++) {
            int s   = tid + itr * 256;
            int row = s >> 2;
            int ko  = (s & 3) * 8;
            cpa16(&As[st][row * HSW + (s & 3) * 4],
                  A + (size_t)(bm + row) * lda + k0 + ko);
            cpa16(&Bs[st][row * HSW + (s & 3) * 4],
                  W + (size_t)(bn + row) * K + k0 + ko);
        }
        asm volatile("cp.async.commit_group;\n");
    };

    issue_load(0, 0);

    const int kt = K / 32;
    int st = 0;
    for (int it = 0; it < kt; it++) {
        asm volatile("cp.async.wait_group 0;\n");
        __syncthreads();
        if (it + 1 < kt) issue_load((it + 1) * 32, st ^ 1);

        #pragma unroll
        for (int kb = 0; kb < 2; kb++) {
            const int k8 = kb * 8;
            uint32_t afr[4][4], bfr[4][2];
            #pragma unroll
            for (int mi = 0; mi < 4; mi++) {
                int r = wm + mi * 16 + gid;
                afr[mi][0] = As[st][r * HSW + k8 + tig];
                afr[mi][1] = As[st][(r + 8) * HSW + k8 + tig];
                afr[mi][2] = As[st][r * HSW + k8 + tig + 4];
                afr[mi][3] = As[st][(r + 8) * HSW + k8 + tig + 4];
            }
            #pragma unroll
            for (int ni = 0; ni < 4; ni++) {
                int c = wn + ni * 8 + gid;
                bfr[ni][0] = Bs[st][c * HSW + k8 + tig];
                bfr[ni][1] = Bs[st][c * HSW + k8 + tig + 4];
            }
            #pragma unroll
            for (int mi = 0; mi < 4; mi++)
                #pragma unroll
                for (int ni = 0; ni < 4; ni++)
                    mma_f16(acc[mi][ni], afr[mi], bfr[ni]);
        }
        st ^= 1;
    }

    float (*Ts)[TSP] = reinterpret_cast<float (*)[TSP]>(&As[0][0]);
    #pragma unroll
    for (int p = 0; p < 4; p++) {
        __syncthreads();
        if ((wid >> 1) == p) {
            #pragma unroll
            for (int mi = 0; mi < 4; mi++)
                #pragma unroll
                for (int ni = 0; ni < 4; ni++)
                    #pragma unroll
                    for (int c = 0; c < 4; c++) {
                        int rr = wm + mi * 16 + gid + ((c >= 2) ? 8 : 0);
                        int cc = ni * 8 + tig * 2 + (c & 1);
                        Ts[cc][rr] = acc[mi][ni][c];
                    }
        }
        __syncthreads();
        int nn = tid >> 3;
        int mm = (tid & 7) * 16;
        size_t base = (size_t)(bn + p * 32 + nn) * MTOT + bm + mm;
        #pragma unroll
        for (int q = 0; q < 4; q++)
            *reinterpret_cast<float4*>(&C[base + q * 4]) =
                *reinterpret_cast<const float4*>(&Ts[nn][mm + q * 4]);
    }
}

// ============================================================================
// fp16 GEMM, A in PAIRED d-major layout (x-proj ONLY this round):
//   Apair: uint32[K/2][MTOT], word = half2(A[m][2kp], A[m][2kp+1])
//   MODE: 3 = tf32-round cols < DTR
// ============================================================================
template<int MODE>
__global__ void __launch_bounds__(256, 2) hgemmT_kernel(
    const uint32_t* __restrict__ Apair,
    const __half* __restrict__ W,
    float* __restrict__ C, int ldc,
    int N, int K)
{
    __shared__ uint32_t As[2][16 * SKM];
    __shared__ uint32_t Bs[2][128 * HSW];

    const int tid  = threadIdx.x;
    const int bm   = blockIdx.y * TBM;
    const int bn   = blockIdx.x * TBN;
    const int wid  = tid >> 5;
    const int lane = tid & 31;
    const int wm   = (wid & 1) * 64;
    const int wn   = (wid >> 1) * 32;
    const int gid  = lane >> 2;
    const int tig  = lane & 3;

    float acc[4][4][4];
    #pragma unroll
    for (int i = 0; i < 4; i++)
        #pragma unroll
        for (int j = 0; j < 4; j++)
            #pragma unroll
            for (int c = 0; c < 4; c++) acc[i][j][c] = 0.0f;

    auto issue_load = [&](int k0, int st) {   // k0 halves, %32==0
        int kp0 = k0 >> 1;
        #pragma unroll
        for (int itr = 0; itr < 2; itr++) {
            int s = tid + itr * 256;
            int kk = s >> 5;
            int mc = (s & 31) * 4;
            cpa16(&As[st][kk * SKM + mc],
                  Apair + (size_t)(kp0 + kk) * MTOT + bm + mc);
            int n  = s >> 2;
            int kc = (s & 3) * 8;
            cpa16z(&Bs[st][n * HSW + (s & 3) * 4],
                   W + (size_t)(bn + n) * K + k0 + kc,
                   (bn + n < N) ? 16 : 0);
        }
        asm volatile("cp.async.commit_group;\n");
    };

    issue_load(0, 0);

    const int kt = K / 32;
    int st = 0;
    for (int it = 0; it < kt; it++) {
        asm volatile("cp.async.wait_group 0;\n");
        __syncthreads();
        if (it + 1 < kt) issue_load((it + 1) * 32, st ^ 1);

        #pragma unroll
        for (int kb = 0; kb < 2; kb++) {
            const int k8 = kb * 8;
            uint32_t afr[4][4], bfr[4][2];
            #pragma unroll
            for (int mi = 0; mi < 4; mi++) {
                int r = wm + mi * 16 + gid;
                afr[mi][0] = As[st][(k8 + tig) * SKM + r];
                afr[mi][1] = As[st][(k8 + tig) * SKM + r + 8];
                afr[mi][2] = As[st][(k8 + tig + 4) * SKM + r];
                afr[mi][3] = As[st][(k8 + tig + 4) * SKM + r + 8];
            }
            #pragma unroll
            for (int ni = 0; ni < 4; ni++) {
                int c = wn + ni * 8 + gid;
                bfr[ni][0] = Bs[st][c * HSW + k8 + tig];
                bfr[ni][1] = Bs[st][c * HSW + k8 + tig + 4];
            }
            #pragma unroll
            for (int mi = 0; mi < 4; mi++)
                #pragma unroll
                for (int ni = 0; ni < 4; ni++)
                    mma_f16(acc[mi][ni], afr[mi], bfr[ni]);
        }
        st ^= 1;
    }

    #pragma unroll
    for (int mi = 0; mi < 4; mi++) {
        int r = bm + wm + mi * 16 + gid;
        #pragma unroll
        for (int ni = 0; ni < 4; ni++) {
            int c = bn + wn + ni * 8 + tig * 2;
            if (c < N) {
                float d0 = acc[mi][ni][0], d1 = acc[mi][ni][1];
                float d2 = acc[mi][ni][2], d3 = acc[mi][ni][3];
                if (MODE == 3 && c < DTR) {
                    d0 = tf32r(d0); d1 = tf32r(d1);
                    d2 = tf32r(d2); d3 = tf32r(d3);
                }
                C[(size_t)r * ldc + c]           = d0;
                C[(size_t)r * ldc + c + 1]       = d1;
                C[(size_t)(r + 8) * ldc + c]     = d2;
                C[(size_t)(r + 8) * ldc + c + 1] = d3;
            }
        }
    }
}

// ============================================================================
// tf32 GEMM (dt / out-proj), exactly as R14.
//   MODE: 0 none | 4 bias-add (CTRANS) | 5 write fp16 to g_midh
// ============================================================================
template<bool ATRANS, bool CTRANS, int MODE>
__global__ void __launch_bounds__(256, 2) tgemm_kernel(
    const float* __restrict__ A, int lda,
    const float* __restrict__ W,
    const float* __restrict__ bias,
    float* __restrict__ C, int ldc,
    int N, int K)
{
    __shared__ float As[2][ASTG];
    __shared__ float Bs[2][BSTG];

    const int tid  = threadIdx.x;
    const int bm   = blockIdx.y * TBM;
    const int bn   = blockIdx.x * TBN;
    const int wid  = tid >> 5;
    const int lane = tid & 31;
    const int wm   = (wid & 1) * 64;
    const int wn   = (wid >> 1) * 32;
    const int gid  = lane >> 2;
    const int tig  = lane & 3;

    float acc[4][4][4];
    #pragma unroll
    for (int i = 0; i < 4; i++)
        #pragma unroll
        for (int j = 0; j < 4; j++)
            #pragma unroll
            for (int c = 0; c < 4; c++) acc[i][j][c] = 0.0f;

    auto issue_load = [&](int k0, int st) {
        #pragma unroll
        for (int itr = 0; itr < 2; itr++) {
            int s = tid + itr * 256;
            if (ATRANS) {
                int kk = s >> 5, mc = (s & 31) * 4;
                cpa16(&As[st][kk * SKM + mc],
                      A + (size_t)(k0 + kk) * MTOT + bm + mc);
            } else {
                int row = s >> 2, kc = (s & 3) * 4;
                cpa16(&As[st][row * SMK + kc],
                      A + (size_t)(bm + row) * lda + k0 + kc);
            }
            int n = s >> 2, kc = (s & 3) * 4;
            cpa16z(&Bs[st][n * SMK + kc],
                   W + (size_t)(bn + n) * K + k0 + kc,
                   (bn + n < N) ? 16 : 0);
        }
        asm volatile("cp.async.commit_group;\n");
    };

    issue_load(0, 0);

    const int kt = K / TBK;
    int st = 0;
    for (int it = 0; it < kt; it++) {
        asm volatile("cp.async.wait_group 0;\n");
        __syncthreads();
        if (it + 1 < kt) issue_load((it + 1) * TBK, st ^ 1);

        #pragma unroll
        for (int ks = 0; ks < 2; ks++) {
            const int kb = ks * 8;
            uint32_t afr[4][4], bfr[4][2];
            #pragma unroll
            for (int mi = 0; mi < 4; mi++) {
                int r = wm + mi * 16 + gid;
                if (ATRANS) {
                    afr[mi][0] = __float_as_uint(As[st][(kb + tig) * SKM + r]);
                    afr[mi][1] = __float_as_uint(As[st][(kb + tig) * SKM + r + 8]);
                    afr[mi][2] = __float_as_uint(As[st][(kb + tig + 4) * SKM + r]);
                    afr[mi][3] = __float_as_uint(As[st][(kb + tig + 4) * SKM + r + 8]);
                } else {
                    afr[mi][0] = __float_as_uint(As[st][r * SMK + kb + tig]);
                    afr[mi][1] = __float_as_uint(As[st][(r + 8) * SMK + kb + tig]);
                    afr[mi][2] = __float_as_uint(As[st][r * SMK + kb + tig + 4]);
                    afr[mi][3] = __float_as_uint(As[st][(r + 8) * SMK + kb + tig + 4]);
                }
            }
            #pragma unroll
            for (int ni = 0; ni < 4; ni++) {
                int c = wn + ni * 8 + gid;
                bfr[ni][0] = __float_as_uint(Bs[st][c * SMK + kb + tig]);
                bfr[ni][1] = __float_as_uint(Bs[st][c * SMK + kb + tig + 4]);
            }
            #pragma unroll
            for (int mi = 0; mi < 4; mi++)
                #pragma unroll
                for (int ni = 0; ni < 4; ni++)
                    mma_tf32(acc[mi][ni], afr[mi], bfr[ni]);
        }
        st ^= 1;
    }

    if constexpr (CTRANS) {
        float (*Ts)[TSP] = reinterpret_cast<float (*)[TSP]>(&As[0][0]);
        #pragma unroll
        for (int p = 0; p < 4; p++) {
            __syncthreads();
            if ((wid >> 1) == p) {
                #pragma unroll
                for (int mi = 0; mi < 4; mi++)
                    #pragma unroll
                    for (int ni = 0; ni < 4; ni++)
                        #pragma unroll
                        for (int c = 0; c < 4; c++) {
                            int rr = wm + mi * 16 + gid + ((c >= 2) ? 8 : 0);
                            int cc = ni * 8 + tig * 2 + (c & 1);
                            float v = acc[mi][ni][c];
                            if (MODE == 4)
                                v += bias[bn + p * 32 + cc];
                            Ts[cc][rr] = v;
                        }
            }
            __syncthreads();
            int nn = tid >> 3;
            int mm = (tid & 7) * 16;
            int grow = bn + p * 32 + nn;
            if (grow < N) {
                size_t base = (size_t)grow * MTOT + bm + mm;
                #pragma unroll
                for (int q = 0; q < 4; q++)
                    *reinterpret_cast<float4*>(&C[base + q * 4]) =
                        *reinterpret_cast<const float4*>(&Ts[nn][mm + q * 4]);
            }
        }
    } else {
        #pragma unroll
        for (int mi = 0; mi < 4; mi++) {
            int r = bm + wm + mi * 16 + gid;
            #pragma unroll
            for (int ni = 0; ni < 4; ni++) {
                int c = bn + wn + ni * 8 + tig * 2;
                if (c < N) {
                    float d0 = acc[mi][ni][0], d1 = acc[mi][ni][1];
                    float d2 = acc[mi][ni][2], d3 = acc[mi][ni][3];
                    if (MODE == 5) {
                        *reinterpret_cast<__half2*>(
                            &g_midh[(size_t)r * DM + c]) =
                            __floats2half2_rn(d0, d1);
                        *reinterpret_cast<__half2*>(
                            &g_midh[(size_t)(r + 8) * DM + c]) =
                            __floats2half2_rn(d2, d3);
                    } else {
                        C[(size_t)r * ldc + c]           = d0;
                        C[(size_t)r * ldc + c + 1]       = d1;
                        C[(size_t)(r + 8) * ldc + c]     = d2;
                        C[(size_t)(r + 8) * ldc + c + 1] = d3;
                    }
                }
            }
        }
    }
}

// ----------------------------------------------------------------------------
// Causal depthwise conv (k=4) + SiLU, one thread per (channel-pair, m).
// Writes full fp32 uT (scan) + packed half2 uhp (x-proj).
// ----------------------------------------------------------------------------
__global__ void conv_silu_kernel(const float* __restrict__ xzT,
                                 const float* __restrict__ cw,
                                 const float* __restrict__ cb,
                                 float* __restrict__ uT,
                                 uint32_t* __restrict__ uhp)
{
    int i = blockIdx.x * blockDim.x + threadIdx.x;
    int kp = i >> 13;
    int m  = i & 8191;
    int t  = m & 1023;
    int d0 = kp * 2, d1 = d0 + 1;
    const float* s0 = xzT + (size_t)d0 * MTOT + m;
    const float* s1 = xzT + (size_t)d1 * MTOT + m;
    float a0 = cb[d0], a1 = cb[d1];
    if (t >= 3) {
        a0 = fmaf(s0[-3], cw[d0 * 4 + 0], a0);
        a1 = fmaf(s1[-3], cw[d1 * 4 + 0], a1);
    }
    if (t >= 2) {
        a0 = fmaf(s0[-2], cw[d0 * 4 + 1], a0);
        a1 = fmaf(s1[-2], cw[d1 * 4 + 1], a1);
    }
    if (t >= 1) {
        a0 = fmaf(s0[-1], cw[d0 * 4 + 2], a0);
        a1 = fmaf(s1[-1], cw[d1 * 4 + 2], a1);
    }
    a0 = fmaf(s0[0], cw[d0 * 4 + 3], a0);
    a1 = fmaf(s1[0], cw[d1 * 4 + 3], a1);
    float v0 = siluf(a0), v1 = siluf(a1);
    uT[(size_t)d0 * MTOT + m] = v0;
    uT[(size_t)d1 * MTOT + m] = v1;
    __half2 h = __floats2half2_rn(v0, v1);
    uhp[(size_t)kp * MTOT + m] = *reinterpret_cast<uint32_t*>(&h);
}

// ----------------------------------------------------------------------------
// Selective scan v6 (R13/R14-proven): 16-step chunks, cp.async double-
// buffered B/C + dt/u/z, softplus fused, butterfly+smem reduction.
// Writes yT fp32 (tf32-rounded) for tf32 out-proj.
// ----------------------------------------------------------------------------
constexpr int CH = 16;

__global__ void __launch_bounds__(128) ssm_scan_kernel(
    const float* __restrict__ proj,
    const float* __restrict__ dtT,
    const float* __restrict__ uT,
    const float* __restrict__ xzT,
    const float* __restrict__ A_log,
    const float* __restrict__ Dparam,
    float* __restrict__ yT)
{
    __shared__ float sBC [2][CH][128];
    __shared__ float sDU [2][4][8][CH];
    __shared__ float pbuf[4][2][CH][9];

    const unsigned FULL = 0xFFFFFFFFu;
    const float L2E = 1.4426950408889634f;
    const int tid  = threadIdx.x;
    const int wid  = tid >> 5;
    const int lane = tid & 31;
    const int b  = blockIdx.y;
    const int d0 = blockIdx.x * 8 + wid * 2;
    const int d1 = d0 + 1;

    float A00 = -__expf(A_log[(size_t)d0 * NS + lane])      * L2E;
    float A01 = -__expf(A_log[(size_t)d0 * NS + lane + 32]) * L2E;
    float A10 = -__expf(A_log[(size_t)d1 * NS + lane])      * L2E;
    float A11 = -__expf(A_log[(size_t)d1 * NS + lane + 32]) * L2E;
    float D0 = Dparam[d0], D1 = Dparam[d1];

    const int prow = lane >> 2;
    const int pseg = (lane & 3) * 4;
    const float* psrc =
        (prow == 0) ? dtT + (size_t)d0 * MTOT :
        (prow == 1) ? dtT + (size_t)d1 * MTOT :
        (prow == 2) ? uT  + (size_t)d0 * MTOT :
        (prow == 3) ? uT  + (size_t)d1 * MTOT :
        (prow == 4) ? xzT + (size_t)(DI + d0) * MTOT
                    : xzT + (size_t)(DI + d1) * MTOT;

    float h00 = 0.f, h01 = 0.f, h10 = 0.f, h11 = 0.f;

    auto issueAll = [&](int tc, int st) {
        size_t mb = (size_t)b * LL + tc;
        #pragma unroll
        for (int it = 0; it < 4; it++) {
            int s   = tid + it * 128;
            int row = s >> 5;
            int c4  = (s & 31) * 4;
            cpa16(&sBC[st][row][c4], proj + (mb + row) * PROJC + 48 + c4);
        }
        if (lane < 24)
            cpa16(&sDU[st][wid][prow][pseg], psrc + mb + pseg);
        asm volatile("cp.async.commit_group;\n");
    };

    issueAll(0, 0);

    const int jj = lane & 15;
    const int ch = lane >> 4;

    int st = 0;
    for (int tc = 0; tc < LL; tc += CH, st ^= 1) {
        const size_t mb = (size_t)b * LL + tc;

        if (tc + CH < LL) {
            issueAll(tc + CH, st ^ 1);
            asm volatile("cp.async.wait_group 1;\n");
        } else {
            asm volatile("cp.async.wait_group 0;\n");
        }
        __syncthreads();

        {
            float raw = sDU[st][wid][ch][jj];
            float uu  = sDU[st][wid][2 + ch][jj];
            float sp  = softplusf(raw);
            sDU[st][wid][ch][jj]     = sp;
            sDU[st][wid][6 + ch][jj] = sp * uu;
        }
        __syncwarp();

        #pragma unroll
        for (int j = 0; j < CH; j++) {
            float Bn0 = sBC[st][j][lane];
            float Bn1 = sBC[st][j][lane + 32];
            float Cn0 = sBC[st][j][64 + lane];
            float Cn1 = sBC[st][j][96 + lane];
            float dt0 = sDU[st][wid][0][j];
            float dt1 = sDU[st][wid][1][j];
            float du0 = sDU[st][wid][6][j];
            float du1 = sDU[st][wid][7][j];
            h00 = fmaf(ex2f(dt0 * A00), h00, du0 * Bn0);
            h01 = fmaf(ex2f(dt0 * A01), h01, du0 * Bn1);
            h10 = fmaf(ex2f(dt1 * A10), h10, du1 * Bn0);
            h11 = fmaf(ex2f(dt1 * A11), h11, du1 * Bn1);
            float y0 = fmaf(h00, Cn0, h01 * Cn1);
            float y1 = fmaf(h10, Cn0, h11 * Cn1);
            y0 += __shfl_xor_sync(FULL, y0, 16);
            y0 += __shfl_xor_sync(FULL, y0, 8);
            y1 += __shfl_xor_sync(FULL, y1, 16);
            y1 += __shfl_xor_sync(FULL, y1, 8);
            pbuf[wid][0][j][lane & 7] = y0;
            pbuf[wid][1][j][lane & 7] = y1;
        }
        __syncwarp();

        {
            float yf = 0.f;
            #pragma unroll
            for (int i = 0; i < 8; i++)
                yf += pbuf[wid][ch][jj][i];
            float uu = sDU[st][wid][2 + ch][jj];
            float zz = sDU[st][wid][4 + ch][jj];
            float Dv = ch ? D1 : D0;
            float out = (yf + uu * Dv) * siluf(zz);
            yT[(size_t)(d0 + ch) * MTOT + mb + jj] = tf32r(out);
        }
        __syncthreads();
    }
}

// ----------------------------------------------------------------------------
// kernel_launch
// ----------------------------------------------------------------------------
extern "C" void kernel_launch(void* const* d_in, const int* in_sizes, int n_in,
                              void* d_out, int out_size)
{
    const float* x     = (const float*)d_in[0];
    const float* W_in  = (const float*)d_in[1];
    const float* cw    = (const float*)d_in[2];
    const float* cb    = (const float*)d_in[3];
    const float* W_x   = (const float*)d_in[4];
    const float* W_dt  = (const float*)d_in[5];
    const float* b_dt  = (const float*)d_in[6];
    const float* A_log = (const float*)d_in[7];
    const float* Dp    = (const float*)d_in[8];
    const float* W_out = (const float*)d_in[9];

    float *xzT, *uT, *proj, *dtT, *yT, *wdt, *wout;
    uint32_t *uhp;
    __half *xrh, *winh, *wxh, *midh;
    cudaGetSymbolAddress((void**)&xzT,  g_xzT);
    cudaGetSymbolAddress((void**)&uT,   g_uT);
    cudaGetSymbolAddress((void**)&uhp,  g_uhp);
    cudaGetSymbolAddress((void**)&proj, g_proj);
    cudaGetSymbolAddress((void**)&dtT,  g_dtT);
    cudaGetSymbolAddress((void**)&yT,   g_yT);
    cudaGetSymbolAddress((void**)&xrh,  g_xrh);
    cudaGetSymbolAddress((void**)&winh, g_winh);
    cudaGetSymbolAddress((void**)&wxh,  g_wxh);
    cudaGetSymbolAddress((void**)&wdt,  g_wdt);
    cudaGetSymbolAddress((void**)&wout, g_wout);
    cudaGetSymbolAddress((void**)&midh, g_midh);

    const dim3 tb256(256);
    const int MB = MTOT / TBM;   // 64

    round_all_kernel<<<(RQ4 + 255) / 256, tb256>>>(
        x, xrh, W_in, winh, W_x, wxh, W_dt, wdt, W_out, wout);

    for (int l = 0; l < 2; l++) {
        const __half* xin = (l == 0) ? xrh : midh;

        // 1. in-proj (fp16, m-major A), n-major into xzT
        hgemm_kernel<<<dim3(XZC / TBN, MB), tb256>>>(
            xin, DM, winh + (size_t)l * XZC * DM, xzT, XZC, DM);

        // 2. conv + silu -> uT (fp32) + uhp (paired fp16)
        conv_silu_kernel<<<(DI / 2 * MTOT) / 256, tb256>>>(
            xzT, cw + (size_t)l * DI * 4, cb + (size_t)l * DI, uT, uhp);

        // 3. x-proj (fp16 paired-A) -> proj ; round dt_r cols
        hgemmT_kernel<3><<<dim3(2, MB), tb256>>>(
            uhp, wxh + (size_t)l * PROJC * DI, proj, PROJC, PROJC, DI);

        // 4. dt raw (+bias) n-major into dtT (tf32 CTRANS, MODE 4)
        tgemm_kernel<false, true, 4>
            <<<dim3(DI / TBN, MB), tb256>>>(
                proj, PROJC, wdt + (size_t)l * DI * DTR,
                b_dt + (size_t)l * DI, dtT, 0, DI, DTR);

        // 5. selective scan -> yT (fp32, tf32-rounded)
        ssm_scan_kernel<<<dim3(DI / 8, BB), dim3(128)>>>(
            proj, dtT, uT, xzT,
            A_log + (size_t)l * DI * NS, Dp + (size_t)l * DI, yT);

        // 6. out-proj (tf32, ATRANS): l0 -> midh (MODE 5); l1 -> d_out
        if (l == 0)
            tgemm_kernel<true, false, 5>
                <<<dim3(DM / TBN, MB), tb256>>>(
                    yT, 0, wout + (size_t)l * DM * DI, nullptr,
                    yT /*unused*/, DM, DM, DI);
        else
            tgemm_kernel<true, false, 0>
                <<<dim3(DM / TBN, MB), tb256>>>(
                    yT, 0, wout + (size_t)l * DM * DI, nullptr,
                    (float*)d_out, DM, DM, DI);
    }
}